// round 1
// baseline (speedup 1.0000x reference)
#include <cuda_runtime.h>
#include <math.h>

// ---------------- problem constants ----------------
#define NN 4096
#define BB 4
#define EE 1024
#define HH 16
#define CC 64
#define DD 512
#define DH 32
#define LL 64
#define RR (NN*BB)   // 16384 rows

// ---------------- device scratch (no allocations allowed) ----------------
__device__ float g_qlin[RR*DD];
__device__ float g_klin[RR*DD];
__device__ float g_vlin[RR*DD];
__device__ float g_qloc[RR*DD];
__device__ float g_kloc[RR*DD];
__device__ float g_vloc[RR*DD];
__device__ float g_olin[RR*DD];
__device__ float g_oloc[RR*DD];
__device__ float g_ln  [RR*DD];
__device__ float g_grn [RR*DD];
__device__ float g_kv    [BB*HH*LL*DH*DH];
__device__ float g_kvprev[BB*HH*LL*DH*DH];

// ---------------- helpers ----------------
__device__ __forceinline__ float gelu_tanh(float x) {
    // jax.nn.gelu default (approximate=True)
    float x3 = x*x*x;
    return 0.5f*x*(1.0f + tanhf(0.7978845608028654f*(x + 0.044715f*x3)));
}

// ---------------- GEMM: C[M,Ncols] = A[M,K] @ W[Ncols,K]^T (+bias, epilogue) ----
// mode 0: C = acc + bias
// mode 1: C = gelu(acc + bias)
// mode 2: C = 0.5f * (C_old + acc + bias)
__global__ __launch_bounds__(256, 2)
void gemm_nt_kernel(const float* __restrict__ A,
                    const float* __restrict__ W,
                    const float* __restrict__ bias,
                    float* __restrict__ C,
                    int M, int Ncols, int K, int mode)
{
    const int BK = 16;
    __shared__ float As[BK][128];
    __shared__ float Bs[BK][128];

    int tid  = threadIdx.x;          // 0..255
    int tcol = tid & 15;             // 0..15
    int trow = tid >> 4;             // 0..15
    int rowBase = blockIdx.y * 128;
    int colBase = blockIdx.x * 128;

    int lr = tid >> 2;               // 0..63 (row within half-tile)
    int lc = (tid & 3) * 4;          // k-offset {0,4,8,12}

    float acc[8][8];
    #pragma unroll
    for (int i = 0; i < 8; i++)
        #pragma unroll
        for (int j = 0; j < 8; j++) acc[i][j] = 0.f;

    for (int k0 = 0; k0 < K; k0 += BK) {
        #pragma unroll
        for (int h = 0; h < 2; h++) {
            int r = lr + h*64;
            float4 va = *reinterpret_cast<const float4*>(
                &A[(size_t)(rowBase + r)*K + k0 + lc]);
            As[lc+0][r] = va.x; As[lc+1][r] = va.y;
            As[lc+2][r] = va.z; As[lc+3][r] = va.w;
            float4 vb = *reinterpret_cast<const float4*>(
                &W[(size_t)(colBase + r)*K + k0 + lc]);
            Bs[lc+0][r] = vb.x; Bs[lc+1][r] = vb.y;
            Bs[lc+2][r] = vb.z; Bs[lc+3][r] = vb.w;
        }
        __syncthreads();
        #pragma unroll
        for (int kk = 0; kk < BK; kk++) {
            float4 a0 = *reinterpret_cast<const float4*>(&As[kk][trow*8]);
            float4 a1 = *reinterpret_cast<const float4*>(&As[kk][trow*8+4]);
            float4 b0 = *reinterpret_cast<const float4*>(&Bs[kk][tcol*8]);
            float4 b1 = *reinterpret_cast<const float4*>(&Bs[kk][tcol*8+4]);
            float af[8] = {a0.x,a0.y,a0.z,a0.w,a1.x,a1.y,a1.z,a1.w};
            float bf[8] = {b0.x,b0.y,b0.z,b0.w,b1.x,b1.y,b1.z,b1.w};
            #pragma unroll
            for (int i = 0; i < 8; i++)
                #pragma unroll
                for (int j = 0; j < 8; j++)
                    acc[i][j] += af[i]*bf[j];
        }
        __syncthreads();
    }

    #pragma unroll
    for (int i = 0; i < 8; i++) {
        int r = rowBase + trow*8 + i;
        #pragma unroll
        for (int j = 0; j < 8; j++) {
            int c = colBase + tcol*8 + j;
            float v = acc[i][j] + bias[c];
            size_t off = (size_t)r*Ncols + c;
            if (mode == 1)      v = gelu_tanh(v);
            else if (mode == 2) v = 0.5f*(C[off] + v);
            C[off] = v;
        }
    }
}

// ---------------- local branch: o = (relu(ql kl^T) * tril) @ vl ----------------
__global__ __launch_bounds__(256)
void attn_local_kernel()
{
    __shared__ float qs[64][33];
    __shared__ float ks[64][33];
    __shared__ float vs[64][33];
    __shared__ float S [64][64];

    int z = blockIdx.x;                 // (b,h,l)
    int l = z & 63, h = (z >> 6) & 15, b = z >> 10;
    int tid = threadIdx.x;

    for (int idx = tid; idx < 64*32; idx += 256) {
        int c = idx >> 5, dh = idx & 31;
        size_t off = ((size_t)((l*64 + c)*BB + b))*DD + h*32 + dh;
        qs[c][dh] = g_qloc[off];
        ks[c][dh] = g_kloc[off];
        vs[c][dh] = g_vloc[off];
    }
    __syncthreads();

    for (int idx = tid; idx < 64*64; idx += 256) {
        int c = idx >> 6, j = idx & 63;
        float s = 0.f;
        if (j <= c) {
            #pragma unroll
            for (int d = 0; d < 32; d++) s += qs[c][d]*ks[j][d];
            s = fmaxf(s, 0.f);
        }
        S[c][j] = s;
    }
    __syncthreads();

    for (int idx = tid; idx < 64*32; idx += 256) {
        int c = idx >> 5, dh = idx & 31;
        float o = 0.f;
        #pragma unroll
        for (int j = 0; j < 64; j++) o += S[c][j]*vs[j][dh];
        size_t off = ((size_t)((l*64 + c)*BB + b))*DD + h*32 + dh;
        g_oloc[off] = o;
    }
}

// ---------------- per-chunk kv state: kv[d][e] = sum_c k[c][d] v[c][e] ----------
__global__ __launch_bounds__(256)
void attn_kv_kernel()
{
    __shared__ float ks[64][33];
    __shared__ float vs[64][33];

    int z = blockIdx.x;
    int l = z & 63, h = (z >> 6) & 15, b = z >> 10;
    int tid = threadIdx.x;

    for (int idx = tid; idx < 64*32; idx += 256) {
        int c = idx >> 5, dh = idx & 31;
        size_t off = ((size_t)((l*64 + c)*BB + b))*DD + h*32 + dh;
        ks[c][dh] = g_klin[off];
        vs[c][dh] = g_vlin[off];
    }
    __syncthreads();

    for (int idx = tid; idx < 32*32; idx += 256) {
        int d = idx >> 5, e = idx & 31;
        float s = 0.f;
        #pragma unroll
        for (int c = 0; c < 64; c++) s += ks[c][d]*vs[c][e];
        g_kv[(size_t)z*1024 + idx] = s;
    }
}

// ---------------- exclusive cumsum over chunks (the only sequential dep) -------
__global__ __launch_bounds__(256)
void kv_cumsum_kernel()
{
    int bh = blockIdx.x;                    // 0..63 = (b,h)
    const float* src = g_kv     + (size_t)bh*LL*1024;
    float*       dst = g_kvprev + (size_t)bh*LL*1024;
    for (int j = threadIdx.x; j < 1024; j += 256) {
        float acc = 0.f;
        #pragma unroll 4
        for (int l = 0; l < LL; l++) {
            dst[l*1024 + j] = acc;
            acc += src[l*1024 + j];
        }
    }
}

// ------------- linear branch: o = (q k^T * tril) @ v + q @ kv_prev -------------
__global__ __launch_bounds__(256)
void attn_lin_kernel()
{
    __shared__ float qs [64][33];
    __shared__ float ks [64][33];
    __shared__ float vs [64][33];
    __shared__ float kvp[32][33];
    __shared__ float S  [64][64];

    int z = blockIdx.x;
    int l = z & 63, h = (z >> 6) & 15, b = z >> 10;
    int tid = threadIdx.x;

    for (int idx = tid; idx < 64*32; idx += 256) {
        int c = idx >> 5, dh = idx & 31;
        size_t off = ((size_t)((l*64 + c)*BB + b))*DD + h*32 + dh;
        qs[c][dh] = g_qlin[off];
        ks[c][dh] = g_klin[off];
        vs[c][dh] = g_vlin[off];
    }
    for (int idx = tid; idx < 32*32; idx += 256) {
        kvp[idx >> 5][idx & 31] = g_kvprev[(size_t)z*1024 + idx];
    }
    __syncthreads();

    for (int idx = tid; idx < 64*64; idx += 256) {
        int c = idx >> 6, j = idx & 63;
        float s = 0.f;
        if (j <= c) {
            #pragma unroll
            for (int d = 0; d < 32; d++) s += qs[c][d]*ks[j][d];
        }
        S[c][j] = s;
    }
    __syncthreads();

    for (int idx = tid; idx < 64*32; idx += 256) {
        int c = idx >> 5, dh = idx & 31;
        float o = 0.f;
        #pragma unroll
        for (int j = 0; j < 64; j++) o += S[c][j]*vs[j][dh];
        #pragma unroll
        for (int d = 0; d < 32; d++) o += qs[c][d]*kvp[d][dh];
        size_t off = ((size_t)((l*64 + c)*BB + b))*DD + h*32 + dh;
        g_olin[off] = o;
    }
}

// ---------------- norms: LayerNorm(o_lin), gated RMSNorm(o_loc) ----------------
__device__ __forceinline__ float block_sum256(float v, float* sbuf) {
    int tid = threadIdx.x;
    #pragma unroll
    for (int o = 16; o > 0; o >>= 1) v += __shfl_xor_sync(0xffffffffu, v, o);
    __syncthreads();
    if ((tid & 31) == 0) sbuf[tid >> 5] = v;
    __syncthreads();
    float t = sbuf[0];
    #pragma unroll
    for (int w = 1; w < 8; w++) t += sbuf[w];
    return t;
}

__global__ __launch_bounds__(256)
void norm_kernel(const float* __restrict__ ln_g, const float* __restrict__ ln_b,
                 const float* __restrict__ gsc,  const float* __restrict__ ggt)
{
    __shared__ float sbuf[8];
    int r = blockIdx.x, tid = threadIdx.x;

    // ---- LayerNorm over D=512 (two elems/thread), two-pass for stability ----
    const float* xl = g_olin + (size_t)r*DD;
    float a0 = xl[tid], a1 = xl[tid + 256];
    float mu = block_sum256(a0 + a1, sbuf) * (1.0f/512.0f);
    float d0 = a0 - mu, d1 = a1 - mu;
    float var = block_sum256(d0*d0 + d1*d1, sbuf) * (1.0f/512.0f);
    float rs = rsqrtf(var + 1e-5f);
    g_ln[(size_t)r*DD + tid      ] = d0*rs*ln_g[tid      ] + ln_b[tid      ];
    g_ln[(size_t)r*DD + tid + 256] = d1*rs*ln_g[tid + 256] + ln_b[tid + 256];

    // ---- gated RMSNorm ----
    const float* xo = g_oloc + (size_t)r*DD;
    float b0 = xo[tid], b1 = xo[tid + 256];
    float ms = block_sum256(b0*b0 + b1*b1, sbuf) * (1.0f/512.0f);
    float inv = rsqrtf(ms + 1e-8f);
    float s0 = 1.0f/(1.0f + expf(-ggt[tid      ]*b0));
    float s1 = 1.0f/(1.0f + expf(-ggt[tid + 256]*b1));
    g_grn[(size_t)r*DD + tid      ] = b0*inv*gsc[tid      ]*s0;
    g_grn[(size_t)r*DD + tid + 256] = b1*inv*gsc[tid + 256]*s1;
}

// ---------------- launch ----------------
extern "C" void kernel_launch(void* const* d_in, const int* in_sizes, int n_in,
                              void* d_out, int out_size)
{
    const float* query   = (const float*)d_in[0];
    const float* wq_lin  = (const float*)d_in[1];
    const float* bq_lin  = (const float*)d_in[2];
    const float* wk_lin  = (const float*)d_in[3];
    const float* bk_lin  = (const float*)d_in[4];
    const float* wv_lin  = (const float*)d_in[5];
    const float* bv_lin  = (const float*)d_in[6];
    const float* wo_lin  = (const float*)d_in[7];
    const float* bo_lin  = (const float*)d_in[8];
    const float* wq_loc  = (const float*)d_in[9];
    const float* bq_loc  = (const float*)d_in[10];
    const float* wk_loc  = (const float*)d_in[11];
    const float* bk_loc  = (const float*)d_in[12];
    const float* wv_loc  = (const float*)d_in[13];
    const float* bv_loc  = (const float*)d_in[14];
    const float* wo_loc  = (const float*)d_in[15];
    const float* bo_loc  = (const float*)d_in[16];
    const float* ln_g    = (const float*)d_in[17];
    const float* ln_b    = (const float*)d_in[18];
    const float* grn_s   = (const float*)d_in[19];
    const float* grn_g   = (const float*)d_in[20];
    float* out = (float*)d_out;

    float *p_qlin, *p_klin, *p_vlin, *p_qloc, *p_kloc, *p_vloc, *p_ln, *p_grn;
    cudaGetSymbolAddress((void**)&p_qlin, g_qlin);
    cudaGetSymbolAddress((void**)&p_klin, g_klin);
    cudaGetSymbolAddress((void**)&p_vlin, g_vlin);
    cudaGetSymbolAddress((void**)&p_qloc, g_qloc);
    cudaGetSymbolAddress((void**)&p_kloc, g_kloc);
    cudaGetSymbolAddress((void**)&p_vloc, g_vloc);
    cudaGetSymbolAddress((void**)&p_ln,   g_ln);
    cudaGetSymbolAddress((void**)&p_grn,  g_grn);

    dim3 blk(256);
    dim3 gproj(DD/128, RR/128);   // (4,128)
    dim3 gout (EE/128, RR/128);   // (8,128)

    // input projections (gelu on q_lin/k_lin)
    gemm_nt_kernel<<<gproj, blk>>>(query, wq_lin, bq_lin, p_qlin, RR, DD, EE, 1);
    gemm_nt_kernel<<<gproj, blk>>>(query, wk_lin, bk_lin, p_klin, RR, DD, EE, 1);
    gemm_nt_kernel<<<gproj, blk>>>(query, wv_lin, bv_lin, p_vlin, RR, DD, EE, 0);
    gemm_nt_kernel<<<gproj, blk>>>(query, wq_loc, bq_loc, p_qloc, RR, DD, EE, 0);
    gemm_nt_kernel<<<gproj, blk>>>(query, wk_loc, bk_loc, p_kloc, RR, DD, EE, 0);
    gemm_nt_kernel<<<gproj, blk>>>(query, wv_loc, bv_loc, p_vloc, RR, DD, EE, 0);

    // attention
    attn_local_kernel<<<BB*HH*LL, blk>>>();
    attn_kv_kernel   <<<BB*HH*LL, blk>>>();
    kv_cumsum_kernel <<<BB*HH,    blk>>>();
    attn_lin_kernel  <<<BB*HH*LL, blk>>>();

    // norms
    norm_kernel<<<RR, blk>>>(ln_g, ln_b, grn_s, grn_g);

    // output projections; second pass accumulates and averages
    gemm_nt_kernel<<<gout, blk>>>(p_ln,  wo_lin, bo_lin, out, RR, EE, DD, 0);
    gemm_nt_kernel<<<gout, blk>>>(p_grn, wo_loc, bo_loc, out, RR, EE, DD, 2);
}

// round 3
// speedup vs baseline: 2.0123x; 2.0123x over previous
#include <cuda_runtime.h>
#include <cuda_bf16.h>
#include <stdint.h>
#include <math.h>

// ---------------- problem constants ----------------
#define NN 4096
#define BB 4
#define EE 1024
#define HH 16
#define DD 512
#define DH 32
#define LL 64
#define RR (NN*BB)   // 16384 rows

// ---------------- gemm geometry ----------------
#define BM 128
#define BN 256
#define BK 32                      // bf16 elems per k-step (64 bytes per row)
#define KSTEPS 96                  // both gemms: K' = 3072
#define STAGE_BYTES ((BM+BN)*64)   // 24576
#define NSTAGES 3
#define SMEM_GEMM (NSTAGES*STAGE_BYTES)  // 73728

// ---------------- device scratch ----------------
__device__ __nv_bfloat16 g_a1[(size_t)RR*2048];      // [query_hi | query_lo]
__device__ __nv_bfloat16 g_w1[(size_t)3072*2048];    // 6 proj weights; cols [hi|lo]
__device__ __nv_bfloat16 g_a2[(size_t)RR*2048];      // [ln_hi | ln_lo | grn_hi | grn_lo]
__device__ __nv_bfloat16 g_w2[(size_t)1024*2048];    // [wol_hi | wol_lo | woc_hi | woc_lo]
__device__ float g_bias1[3072];
__device__ float g_bias2[1024];
__device__ float g_proj[(size_t)6*RR*DD];            // q_lin,k_lin,v_lin,q_loc,k_loc,v_loc
__device__ float g_olin[(size_t)RR*DD];
__device__ float g_oloc[(size_t)RR*DD];
__device__ float g_kv    [(size_t)BB*HH*LL*DH*DH];
__device__ float g_kvprev[(size_t)BB*HH*LL*DH*DH];

// ---------------- asm helpers (all base sm_80-era; no 'a' features) ----------
__device__ __forceinline__ uint32_t smem_u32(const void* p) {
    uint32_t a;
    asm("{ .reg .u64 t; cvta.to.shared.u64 t, %1; cvt.u32.u64 %0, t; }" : "=r"(a) : "l"(p));
    return a;
}
__device__ __forceinline__ void cpasync16(uint32_t s, const void* g) {
    asm volatile("cp.async.cg.shared.global [%0], [%1], 16;" :: "r"(s), "l"(g));
}
#define CP_COMMIT() asm volatile("cp.async.commit_group;" ::: "memory")
#define CP_WAIT1()  asm volatile("cp.async.wait_group 1;"  ::: "memory")

__device__ __forceinline__ void ldsm4(uint32_t* r, uint32_t addr) {
    asm volatile("ldmatrix.sync.aligned.m8n8.x4.shared.b16 {%0,%1,%2,%3}, [%4];"
        : "=r"(r[0]), "=r"(r[1]), "=r"(r[2]), "=r"(r[3]) : "r"(addr));
}
__device__ __forceinline__ void mma_bf16(float* c, const uint32_t* a,
                                         uint32_t b0, uint32_t b1) {
    asm volatile(
        "mma.sync.aligned.m16n8k16.row.col.f32.bf16.bf16.f32 "
        "{%0,%1,%2,%3}, {%4,%5,%6,%7}, {%8,%9}, {%0,%1,%2,%3};"
        : "+f"(c[0]), "+f"(c[1]), "+f"(c[2]), "+f"(c[3])
        : "r"(a[0]), "r"(a[1]), "r"(a[2]), "r"(a[3]), "r"(b0), "r"(b1));
}

__device__ __forceinline__ float gelu_tanh(float x) {
    float x3 = x*x*x;
    return 0.5f*x*(1.0f + tanhf(0.7978845608028654f*(x + 0.044715f*x3)));
}
__device__ __forceinline__ void split_bf16(float x, __nv_bfloat16& hi, __nv_bfloat16& lo) {
    hi = __float2bfloat16(x);
    lo = __float2bfloat16(x - __bfloat162float(hi));
}

// swizzled byte offset inside a [rows][32 bf16] tile (64B rows)
__device__ __forceinline__ uint32_t swz(int row, int kq) {
    return (uint32_t)(row*64 + ((kq ^ ((row>>1)&3)) << 4));
}

// (aoff,boff) in bf16 elements along the 2048-wide concatenated K for k-step ks
__device__ __forceinline__ void seg_off(int gemmid, int ks, int& aoff, int& boff) {
    if (gemmid == 0) {
        int seg = ks >> 5, ko = (ks & 31)*32;
        aoff = ko + (seg == 2 ? 1024 : 0);
        boff = ko + (seg == 1 ? 1024 : 0);
    } else {
        int seg = ks >> 4, ko = (ks & 15)*32;
        int sa, sb;
        switch (seg) {
            case 0:  sa = 0;    sb = 0;    break;
            case 1:  sa = 0;    sb = 512;  break;
            case 2:  sa = 512;  sb = 0;    break;
            case 3:  sa = 1024; sb = 1024; break;
            case 4:  sa = 1024; sb = 1536; break;
            default: sa = 1536; sb = 1024; break;
        }
        aoff = sa + ko; boff = sb + ko;
    }
}

// =======================================================================
//   bf16 mma.sync GEMM: C[M,N] = A[M,K'] @ B[N,K']^T (3-term bf16 split)
//   gemmid 0: N=3072 -> g_proj (+bias, gelu on first 2 projections)
//   gemmid 1: N=1024 -> out = 0.5*acc + bias2
// =======================================================================
__global__ __launch_bounds__(256, 1)
void gemm_tc(int gemmid, float* __restrict__ outp)
{
    extern __shared__ char smem[];
    const uint32_t sb = smem_u32(smem);
    const int tid = threadIdx.x;
    const int mbase = blockIdx.y * BM;
    const int nbase = blockIdx.x * BN;
    const __nv_bfloat16* __restrict__ Ap = gemmid ? g_a2 : g_a1;
    const __nv_bfloat16* __restrict__ Bp = gemmid ? g_w2 : g_w1;

    float acc[2][16][4];
    #pragma unroll
    for (int i = 0; i < 2; i++)
        #pragma unroll
        for (int j = 0; j < 16; j++)
            #pragma unroll
            for (int q = 0; q < 4; q++) acc[i][j][q] = 0.f;

    // ---- stage loader: A 128x4 chunks (512 tasks) + B 256x4 (1024 tasks) ----
    auto load_stage = [&](uint32_t sst, int aoff, int boff) {
        #pragma unroll
        for (int j = 0; j < 2; j++) {
            int task = tid + 256*j, row = task >> 2, ch = task & 3;
            cpasync16(sst + swz(row, ch),
                      Ap + (size_t)(mbase + row)*2048 + aoff + ch*8);
        }
        #pragma unroll
        for (int j = 0; j < 4; j++) {
            int task = tid + 256*j, row = task >> 2, ch = task & 3;
            cpasync16(sst + (uint32_t)(BM*64) + swz(row, ch),
                      Bp + (size_t)(nbase + row)*2048 + boff + ch*8);
        }
    };

    {   // prologue: stages 0,1
        int ao, bo;
        seg_off(gemmid, 0, ao, bo); load_stage(sb, ao, bo); CP_COMMIT();
        seg_off(gemmid, 1, ao, bo); load_stage(sb + STAGE_BYTES, ao, bo); CP_COMMIT();
    }

    const int lane = tid & 31, wid = tid >> 5;
    const int m0 = (wid & 3) * 32;       // 4 warps along M
    const int n0 = (wid >> 2) * 128;     // 2 warps along N

    for (int ks = 0; ks < KSTEPS; ks++) {
        CP_WAIT1();
        __syncthreads();
        if (ks + 2 < KSTEPS) {
            int ao, bo; seg_off(gemmid, ks + 2, ao, bo);
            load_stage(sb + (uint32_t)(((ks + 2) % NSTAGES) * STAGE_BYTES), ao, bo);
        }
        CP_COMMIT();

        uint32_t sA = sb + (uint32_t)((ks % NSTAGES) * STAGE_BYTES);
        uint32_t sB = sA + (uint32_t)(BM*64);
        #pragma unroll
        for (int kt = 0; kt < 2; kt++) {
            uint32_t aF[2][4];
            int kq = kt*2 + (lane >> 4);
            #pragma unroll
            for (int mt = 0; mt < 2; mt++) {
                int row = m0 + mt*16 + (lane & 15);
                ldsm4(aF[mt], sA + swz(row, kq));
            }
            #pragma unroll
            for (int p = 0; p < 8; p++) {
                uint32_t bF[4];
                int n = n0 + p*16 + (lane & 15);
                ldsm4(bF, sB + swz(n, kq));
                // bF: r0=(nt=2p,klo) r1=(2p+1,klo) r2=(2p,khi) r3=(2p+1,khi)
                #pragma unroll
                for (int mt = 0; mt < 2; mt++) {
                    mma_bf16(acc[mt][2*p],   aF[mt], bF[0], bF[2]);
                    mma_bf16(acc[mt][2*p+1], aF[mt], bF[1], bF[3]);
                }
            }
        }
    }

    // ---- epilogue: registers -> global with bias / gelu / 0.5-avg ----
    const int r_lo  = mbase + m0 + (lane >> 2);
    const int cbase = nbase + n0 + (lane & 3)*2;
    #pragma unroll
    for (int mt = 0; mt < 2; mt++) {
        #pragma unroll
        for (int nt = 0; nt < 16; nt++) {
            int col = cbase + nt*8;
            int row0 = r_lo + mt*16;
            float v0 = acc[mt][nt][0], v1 = acc[mt][nt][1];
            float v2 = acc[mt][nt][2], v3 = acc[mt][nt][3];
            if (gemmid == 0) {
                float b0 = g_bias1[col], b1 = g_bias1[col+1];
                v0 += b0; v1 += b1; v2 += b0; v3 += b1;
                int proj = col >> 9, lc = col & 511;
                if (proj < 2) {
                    v0 = gelu_tanh(v0); v1 = gelu_tanh(v1);
                    v2 = gelu_tanh(v2); v3 = gelu_tanh(v3);
                }
                float* base = g_proj + (size_t)proj * ((size_t)RR*DD);
                *reinterpret_cast<float2*>(base + (size_t)row0*DD + lc)
                    = make_float2(v0, v1);
                *reinterpret_cast<float2*>(base + (size_t)(row0+8)*DD + lc)
                    = make_float2(v2, v3);
            } else {
                float b0 = g_bias2[col], b1 = g_bias2[col+1];
                *reinterpret_cast<float2*>(outp + (size_t)row0*1024 + col)
                    = make_float2(0.5f*v0 + b0, 0.5f*v1 + b1);
                *reinterpret_cast<float2*>(outp + (size_t)(row0+8)*1024 + col)
                    = make_float2(0.5f*v2 + b0, 0.5f*v3 + b1);
            }
        }
    }
}

// =======================================================================
//   conversion kernels (fp32 -> bf16 hi/lo splits)
// =======================================================================
__global__ void conv_a1(const float* __restrict__ query)
{
    size_t i = (size_t)blockIdx.x * 256 + threadIdx.x;   // 16384*1024
    int r = (int)(i >> 10), c = (int)(i & 1023);
    __nv_bfloat16 hi, lo;
    split_bf16(query[i], hi, lo);
    g_a1[(size_t)r*2048 + c]        = hi;
    g_a1[(size_t)r*2048 + 1024 + c] = lo;
}

__global__ void conv_w1(const float* __restrict__ w0, const float* __restrict__ w1,
                        const float* __restrict__ w2, const float* __restrict__ w3,
                        const float* __restrict__ w4, const float* __restrict__ w5)
{
    size_t i = (size_t)blockIdx.x * 256 + threadIdx.x;   // 3072*1024
    int n = (int)(i >> 10), k = (int)(i & 1023);
    int proj = n >> 9, rloc = n & 511;
    const float* src;
    switch (proj) {
        case 0: src = w0; break; case 1: src = w1; break; case 2: src = w2; break;
        case 3: src = w3; break; case 4: src = w4; break; default: src = w5; break;
    }
    __nv_bfloat16 hi, lo;
    split_bf16(src[(size_t)rloc*1024 + k], hi, lo);
    g_w1[(size_t)n*2048 + k]        = hi;
    g_w1[(size_t)n*2048 + 1024 + k] = lo;
}

__global__ void conv_w2(const float* __restrict__ wo_lin, const float* __restrict__ wo_loc)
{
    size_t i = (size_t)blockIdx.x * 256 + threadIdx.x;   // 1024*512
    int n = (int)(i >> 9), k = (int)(i & 511);
    __nv_bfloat16 hi, lo;
    split_bf16(wo_lin[(size_t)n*512 + k], hi, lo);
    g_w2[(size_t)n*2048 + k]       = hi;
    g_w2[(size_t)n*2048 + 512 + k] = lo;
    split_bf16(wo_loc[(size_t)n*512 + k], hi, lo);
    g_w2[(size_t)n*2048 + 1024 + k] = hi;
    g_w2[(size_t)n*2048 + 1536 + k] = lo;
}

__global__ void conv_bias(const float* __restrict__ b0, const float* __restrict__ b1,
                          const float* __restrict__ b2, const float* __restrict__ b3,
                          const float* __restrict__ b4, const float* __restrict__ b5,
                          const float* __restrict__ bo_lin, const float* __restrict__ bo_loc)
{
    int c = blockIdx.x * 256 + threadIdx.x;   // 3072
    int proj = c >> 9, lc = c & 511;
    const float* src;
    switch (proj) {
        case 0: src = b0; break; case 1: src = b1; break; case 2: src = b2; break;
        case 3: src = b3; break; case 4: src = b4; break; default: src = b5; break;
    }
    g_bias1[c] = src[lc];
    if (c < 1024) g_bias2[c] = 0.5f * (bo_lin[c] + bo_loc[c]);
}

// =======================================================================
//   attention kernels (fp32, chunk-local, smem resident)
// =======================================================================
__global__ __launch_bounds__(256)
void attn_local_kernel()
{
    __shared__ float qs[64][33];
    __shared__ float ks[64][33];
    __shared__ float vs[64][33];
    __shared__ float S [64][64];

    int z = blockIdx.x;
    int l = z & 63, h = (z >> 6) & 15, b = z >> 10;
    int tid = threadIdx.x;
    const float* Q = g_proj + (size_t)3*RR*DD;
    const float* K = g_proj + (size_t)4*RR*DD;
    const float* V = g_proj + (size_t)5*RR*DD;

    for (int idx = tid; idx < 64*32; idx += 256) {
        int c = idx >> 5, dh = idx & 31;
        size_t off = ((size_t)((l*64 + c)*BB + b))*DD + h*32 + dh;
        qs[c][dh] = Q[off]; ks[c][dh] = K[off]; vs[c][dh] = V[off];
    }
    __syncthreads();

    for (int idx = tid; idx < 64*64; idx += 256) {
        int c = idx >> 6, j = idx & 63;
        float s = 0.f;
        if (j <= c) {
            #pragma unroll
            for (int d = 0; d < 32; d++) s += qs[c][d]*ks[j][d];
            s = fmaxf(s, 0.f);
        }
        S[c][j] = s;
    }
    __syncthreads();

    for (int idx = tid; idx < 64*32; idx += 256) {
        int c = idx >> 5, dh = idx & 31;
        float o = 0.f;
        #pragma unroll
        for (int j = 0; j < 64; j++) o += S[c][j]*vs[j][dh];
        size_t off = ((size_t)((l*64 + c)*BB + b))*DD + h*32 + dh;
        g_oloc[off] = o;
    }
}

__global__ __launch_bounds__(256)
void attn_kv_kernel()
{
    __shared__ float ks[64][33];
    __shared__ float vs[64][33];

    int z = blockIdx.x;
    int l = z & 63, h = (z >> 6) & 15, b = z >> 10;
    int tid = threadIdx.x;
    const float* K = g_proj + (size_t)1*RR*DD;
    const float* V = g_proj + (size_t)2*RR*DD;

    for (int idx = tid; idx < 64*32; idx += 256) {
        int c = idx >> 5, dh = idx & 31;
        size_t off = ((size_t)((l*64 + c)*BB + b))*DD + h*32 + dh;
        ks[c][dh] = K[off]; vs[c][dh] = V[off];
    }
    __syncthreads();

    for (int idx = tid; idx < 32*32; idx += 256) {
        int d = idx >> 5, e = idx & 31;
        float s = 0.f;
        #pragma unroll
        for (int c = 0; c < 64; c++) s += ks[c][d]*vs[c][e];
        g_kv[(size_t)z*1024 + idx] = s;
    }
}

__global__ __launch_bounds__(256)
void kv_cumsum_kernel()
{
    int bh = blockIdx.x;
    const float* src = g_kv     + (size_t)bh*LL*1024;
    float*       dst = g_kvprev + (size_t)bh*LL*1024;
    for (int j = threadIdx.x; j < 1024; j += 256) {
        float acc = 0.f;
        #pragma unroll 4
        for (int l = 0; l < LL; l++) {
            dst[l*1024 + j] = acc;
            acc += src[l*1024 + j];
        }
    }
}

__global__ __launch_bounds__(256)
void attn_lin_kernel()
{
    __shared__ float qs [64][33];
    __shared__ float ks [64][33];
    __shared__ float vs [64][33];
    __shared__ float kvp[32][33];
    __shared__ float S  [64][64];

    int z = blockIdx.x;
    int l = z & 63, h = (z >> 6) & 15, b = z >> 10;
    int tid = threadIdx.x;
    const float* Q = g_proj;
    const float* K = g_proj + (size_t)1*RR*DD;
    const float* V = g_proj + (size_t)2*RR*DD;

    for (int idx = tid; idx < 64*32; idx += 256) {
        int c = idx >> 5, dh = idx & 31;
        size_t off = ((size_t)((l*64 + c)*BB + b))*DD + h*32 + dh;
        qs[c][dh] = Q[off]; ks[c][dh] = K[off]; vs[c][dh] = V[off];
    }
    for (int idx = tid; idx < 32*32; idx += 256)
        kvp[idx >> 5][idx & 31] = g_kvprev[(size_t)z*1024 + idx];
    __syncthreads();

    for (int idx = tid; idx < 64*64; idx += 256) {
        int c = idx >> 6, j = idx & 63;
        float s = 0.f;
        if (j <= c) {
            #pragma unroll
            for (int d = 0; d < 32; d++) s += qs[c][d]*ks[j][d];
        }
        S[c][j] = s;
    }
    __syncthreads();

    for (int idx = tid; idx < 64*32; idx += 256) {
        int c = idx >> 5, dh = idx & 31;
        float o = 0.f;
        #pragma unroll
        for (int j = 0; j < 64; j++) o += S[c][j]*vs[j][dh];
        #pragma unroll
        for (int d = 0; d < 32; d++) o += qs[c][d]*kvp[d][dh];
        size_t off = ((size_t)((l*64 + c)*BB + b))*DD + h*32 + dh;
        g_olin[off] = o;
    }
}

// ---------------- norms -> bf16 hi/lo splits into g_a2 ----------------
__device__ __forceinline__ float block_sum256(float v, float* sbuf) {
    int tid = threadIdx.x;
    #pragma unroll
    for (int o = 16; o > 0; o >>= 1) v += __shfl_xor_sync(0xffffffffu, v, o);
    __syncthreads();
    if ((tid & 31) == 0) sbuf[tid >> 5] = v;
    __syncthreads();
    float t = sbuf[0];
    #pragma unroll
    for (int w = 1; w < 8; w++) t += sbuf[w];
    return t;
}

__global__ __launch_bounds__(256)
void norm_kernel(const float* __restrict__ ln_g, const float* __restrict__ ln_b,
                 const float* __restrict__ gsc,  const float* __restrict__ ggt)
{
    __shared__ float sbuf[8];
    int r = blockIdx.x, tid = threadIdx.x;
    __nv_bfloat16* a2 = g_a2 + (size_t)r*2048;

    // LayerNorm over D=512
    const float* xl = g_olin + (size_t)r*DD;
    float a0 = xl[tid], a1 = xl[tid + 256];
    float mu = block_sum256(a0 + a1, sbuf) * (1.0f/512.0f);
    float d0 = a0 - mu, d1 = a1 - mu;
    float var = block_sum256(d0*d0 + d1*d1, sbuf) * (1.0f/512.0f);
    float rs = rsqrtf(var + 1e-5f);
    float y0 = d0*rs*ln_g[tid      ] + ln_b[tid      ];
    float y1 = d1*rs*ln_g[tid + 256] + ln_b[tid + 256];
    __nv_bfloat16 hi, lo;
    split_bf16(y0, hi, lo); a2[tid      ] = hi; a2[512 + tid      ] = lo;
    split_bf16(y1, hi, lo); a2[tid + 256] = hi; a2[512 + tid + 256] = lo;

    // gated RMSNorm
    const float* xo = g_oloc + (size_t)r*DD;
    float b0 = xo[tid], b1 = xo[tid + 256];
    float ms = block_sum256(b0*b0 + b1*b1, sbuf) * (1.0f/512.0f);
    float inv = rsqrtf(ms + 1e-8f);
    float s0 = 1.0f/(1.0f + expf(-ggt[tid      ]*b0));
    float s1 = 1.0f/(1.0f + expf(-ggt[tid + 256]*b1));
    float z0 = b0*inv*gsc[tid      ]*s0;
    float z1 = b1*inv*gsc[tid + 256]*s1;
    split_bf16(z0, hi, lo); a2[1024 + tid      ] = hi; a2[1536 + tid      ] = lo;
    split_bf16(z1, hi, lo); a2[1024 + tid + 256] = hi; a2[1536 + tid + 256] = lo;
}

// =======================================================================
//   launch
// =======================================================================
extern "C" void kernel_launch(void* const* d_in, const int* in_sizes, int n_in,
                              void* d_out, int out_size)
{
    const float* query   = (const float*)d_in[0];
    const float* wq_lin  = (const float*)d_in[1];
    const float* bq_lin  = (const float*)d_in[2];
    const float* wk_lin  = (const float*)d_in[3];
    const float* bk_lin  = (const float*)d_in[4];
    const float* wv_lin  = (const float*)d_in[5];
    const float* bv_lin  = (const float*)d_in[6];
    const float* wo_lin  = (const float*)d_in[7];
    const float* bo_lin  = (const float*)d_in[8];
    const float* wq_loc  = (const float*)d_in[9];
    const float* bq_loc  = (const float*)d_in[10];
    const float* wk_loc  = (const float*)d_in[11];
    const float* bk_loc  = (const float*)d_in[12];
    const float* wv_loc  = (const float*)d_in[13];
    const float* bv_loc  = (const float*)d_in[14];
    const float* wo_loc  = (const float*)d_in[15];
    const float* bo_loc  = (const float*)d_in[16];
    const float* ln_g    = (const float*)d_in[17];
    const float* ln_b    = (const float*)d_in[18];
    const float* grn_s   = (const float*)d_in[19];
    const float* grn_g   = (const float*)d_in[20];
    float* out = (float*)d_out;

    cudaFuncSetAttribute(gemm_tc, cudaFuncAttributeMaxDynamicSharedMemorySize, SMEM_GEMM);

    // conversions
    conv_a1  <<<(RR*1024)/256, 256>>>(query);
    conv_w1  <<<(3072*1024)/256, 256>>>(wq_lin, wk_lin, wv_lin, wq_loc, wk_loc, wv_loc);
    conv_w2  <<<(1024*512)/256, 256>>>(wo_lin, wo_loc);
    conv_bias<<<3072/256, 256>>>(bq_lin, bk_lin, bv_lin, bq_loc, bk_loc, bv_loc, bo_lin, bo_loc);

    // fused input projections (6-in-1), bf16 tensor cores
    gemm_tc<<<dim3(3072/BN, RR/BM), 256, SMEM_GEMM>>>(0, nullptr);

    // attention
    attn_local_kernel<<<BB*HH*LL, 256>>>();
    attn_kv_kernel   <<<BB*HH*LL, 256>>>();
    kv_cumsum_kernel <<<BB*HH,    256>>>();
    attn_lin_kernel  <<<BB*HH*LL, 256>>>();

    // norms (emit bf16 hi/lo operands for the output GEMM)
    norm_kernel<<<RR, 256>>>(ln_g, ln_b, grn_s, grn_g);

    // fused output projections (2-in-1), writes d_out
    gemm_tc<<<dim3(1024/BN, RR/BM), 256, SMEM_GEMM>>>(1, out);
}

// round 4
// speedup vs baseline: 2.0671x; 1.0272x over previous
#include <cuda_runtime.h>
#include <cuda_bf16.h>
#include <stdint.h>
#include <math.h>

// ---------------- problem constants ----------------
#define NN 4096
#define BB 4
#define EE 1024
#define HH 16
#define DD 512
#define DH 32
#define LL 64
#define RR (NN*BB)   // 16384 rows

// ---------------- gemm geometry ----------------
#define BM 128
#define BN 256
#define BK 32                      // bf16 elems per k-step (64 bytes per row)
#define KSTEPS 96                  // both gemms: K' = 3072
#define STAGE_BYTES ((BM+BN)*64)   // 24576
#define NSTAGES 4
#define SMEM_GEMM (NSTAGES*STAGE_BYTES)  // 98304

// ---------------- device scratch ----------------
__device__ __nv_bfloat16 g_a1[(size_t)RR*2048];      // [query_hi | query_lo]
__device__ __nv_bfloat16 g_w1[(size_t)3072*2048];    // 6 proj weights; cols [hi|lo]
__device__ __nv_bfloat16 g_a2[(size_t)RR*2048];      // [ln_hi | ln_lo | grn_hi | grn_lo]
__device__ __nv_bfloat16 g_w2[(size_t)1024*2048];    // [wol_hi | wol_lo | woc_hi | woc_lo]
__device__ float g_bias1[3072];
__device__ float g_bias2[1024];
__device__ float g_proj[(size_t)6*RR*DD];            // q_lin,k_lin,v_lin,q_loc,k_loc,v_loc
__device__ float g_olin[(size_t)RR*DD];
__device__ float g_oloc[(size_t)RR*DD];
__device__ float g_kv    [(size_t)BB*HH*LL*DH*DH];
__device__ float g_kvprev[(size_t)BB*HH*LL*DH*DH];

// ---------------- asm helpers (base sm_80-era; no 'a' features) ----------
__device__ __forceinline__ uint32_t smem_u32(const void* p) {
    uint32_t a;
    asm("{ .reg .u64 t; cvta.to.shared.u64 t, %1; cvt.u32.u64 %0, t; }" : "=r"(a) : "l"(p));
    return a;
}
__device__ __forceinline__ void cpasync16(uint32_t s, const void* g) {
    asm volatile("cp.async.cg.shared.global [%0], [%1], 16;" :: "r"(s), "l"(g));
}
#define CP_COMMIT() asm volatile("cp.async.commit_group;" ::: "memory")
#define CP_WAIT2()  asm volatile("cp.async.wait_group 2;"  ::: "memory")

__device__ __forceinline__ void ldsm4(uint32_t* r, uint32_t addr) {
    asm volatile("ldmatrix.sync.aligned.m8n8.x4.shared.b16 {%0,%1,%2,%3}, [%4];"
        : "=r"(r[0]), "=r"(r[1]), "=r"(r[2]), "=r"(r[3]) : "r"(addr));
}
__device__ __forceinline__ void mma_bf16(float* c, const uint32_t* a,
                                         uint32_t b0, uint32_t b1) {
    asm volatile(
        "mma.sync.aligned.m16n8k16.row.col.f32.bf16.bf16.f32 "
        "{%0,%1,%2,%3}, {%4,%5,%6,%7}, {%8,%9}, {%0,%1,%2,%3};"
        : "+f"(c[0]), "+f"(c[1]), "+f"(c[2]), "+f"(c[3])
        : "r"(a[0]), "r"(a[1]), "r"(a[2]), "r"(a[3]), "r"(b0), "r"(b1));
}

__device__ __forceinline__ float gelu_tanh(float x) {
    float x3 = x*x*x;
    return 0.5f*x*(1.0f + tanhf(0.7978845608028654f*(x + 0.044715f*x3)));
}
__device__ __forceinline__ void split_bf16(float x, __nv_bfloat16& hi, __nv_bfloat16& lo) {
    hi = __float2bfloat16(x);
    lo = __float2bfloat16(x - __bfloat162float(hi));
}

// swizzled byte offset inside a [rows][32 bf16] tile (64B rows)
__device__ __forceinline__ uint32_t swz(int row, int kq) {
    return (uint32_t)(row*64 + ((kq ^ ((row>>1)&3)) << 4));
}

// (aoff,boff) in bf16 elements along the 2048-wide concatenated K for k-step ks
__device__ __forceinline__ void seg_off(int gemmid, int ks, int& aoff, int& boff) {
    if (gemmid == 0) {
        int seg = ks >> 5, ko = (ks & 31)*32;
        aoff = ko + (seg == 2 ? 1024 : 0);
        boff = ko + (seg == 1 ? 1024 : 0);
    } else {
        int seg = ks >> 4, ko = (ks & 15)*32;
        int sa, sb;
        switch (seg) {
            case 0:  sa = 0;    sb = 0;    break;
            case 1:  sa = 0;    sb = 512;  break;
            case 2:  sa = 512;  sb = 0;    break;
            case 3:  sa = 1024; sb = 1024; break;
            case 4:  sa = 1024; sb = 1536; break;
            default: sa = 1536; sb = 1024; break;
        }
        aoff = sa + ko; boff = sb + ko;
    }
}

// =======================================================================
//   bf16 mma.sync GEMM: C[M,N] = A[M,K'] @ B[N,K']^T (3-term bf16 split)
//   warp tile 64x64 (warp grid 2x4), 4-stage cp.async pipeline
//   gemmid 0: N=3072 -> g_proj (+bias, gelu on first 2 projections)
//   gemmid 1: N=1024 -> out = 0.5*acc + bias2
// =======================================================================
__global__ __launch_bounds__(256, 1)
void gemm_tc(int gemmid, float* __restrict__ outp)
{
    extern __shared__ char smem[];
    const uint32_t sb = smem_u32(smem);
    const int tid = threadIdx.x;
    const int mbase = blockIdx.y * BM;
    const int nbase = blockIdx.x * BN;
    const __nv_bfloat16* __restrict__ Ap = gemmid ? g_a2 : g_a1;
    const __nv_bfloat16* __restrict__ Bp = gemmid ? g_w2 : g_w1;

    float acc[4][8][4];
    #pragma unroll
    for (int i = 0; i < 4; i++)
        #pragma unroll
        for (int j = 0; j < 8; j++)
            #pragma unroll
            for (int q = 0; q < 4; q++) acc[i][j][q] = 0.f;

    // ---- stage loader: A 128 rows x 4 chunks + B 256 rows x 4 chunks ----
    auto load_stage = [&](uint32_t sst, int aoff, int boff) {
        #pragma unroll
        for (int j = 0; j < 2; j++) {
            int task = tid + 256*j, row = task >> 2, ch = task & 3;
            cpasync16(sst + swz(row, ch),
                      Ap + (size_t)(mbase + row)*2048 + aoff + ch*8);
        }
        #pragma unroll
        for (int j = 0; j < 4; j++) {
            int task = tid + 256*j, row = task >> 2, ch = task & 3;
            cpasync16(sst + (uint32_t)(BM*64) + swz(row, ch),
                      Bp + (size_t)(nbase + row)*2048 + boff + ch*8);
        }
    };

    {   // prologue: stages 0,1,2
        int ao, bo;
        seg_off(gemmid, 0, ao, bo); load_stage(sb, ao, bo); CP_COMMIT();
        seg_off(gemmid, 1, ao, bo); load_stage(sb + STAGE_BYTES, ao, bo); CP_COMMIT();
        seg_off(gemmid, 2, ao, bo); load_stage(sb + 2*STAGE_BYTES, ao, bo); CP_COMMIT();
    }

    const int lane = tid & 31, wid = tid >> 5;
    const int m0 = (wid & 1) * 64;       // 2 warps along M
    const int n0 = (wid >> 1) * 64;      // 4 warps along N

    for (int ks = 0; ks < KSTEPS; ks++) {
        CP_WAIT2();
        __syncthreads();
        if (ks + 3 < KSTEPS) {
            int ao, bo; seg_off(gemmid, ks + 3, ao, bo);
            load_stage(sb + (uint32_t)(((ks + 3) % NSTAGES) * STAGE_BYTES), ao, bo);
        }
        CP_COMMIT();

        uint32_t sA = sb + (uint32_t)((ks % NSTAGES) * STAGE_BYTES);
        uint32_t sB = sA + (uint32_t)(BM*64);
        #pragma unroll
        for (int kt = 0; kt < 2; kt++) {
            int kq = kt*2 + (lane >> 4);
            uint32_t aF[4][4];
            #pragma unroll
            for (int mt = 0; mt < 4; mt++)
                ldsm4(aF[mt], sA + swz(m0 + mt*16 + (lane & 15), kq));
            #pragma unroll
            for (int p = 0; p < 4; p++) {
                uint32_t bF[4];
                ldsm4(bF, sB + swz(n0 + p*16 + (lane & 15), kq));
                // bF: r0=(n-group 2p, klo) r1=(2p+1, klo) r2=(2p, khi) r3=(2p+1, khi)
                #pragma unroll
                for (int mt = 0; mt < 4; mt++) {
                    mma_bf16(acc[mt][2*p],   aF[mt], bF[0], bF[2]);
                    mma_bf16(acc[mt][2*p+1], aF[mt], bF[1], bF[3]);
                }
            }
        }
    }

    // ---- epilogue: registers -> global with bias / gelu / 0.5-avg ----
    const int r_lo  = mbase + m0 + (lane >> 2);
    const int cbase = nbase + n0 + (lane & 3)*2;
    #pragma unroll
    for (int mt = 0; mt < 4; mt++) {
        #pragma unroll
        for (int nt = 0; nt < 8; nt++) {
            int col = cbase + nt*8;
            int row0 = r_lo + mt*16;
            float v0 = acc[mt][nt][0], v1 = acc[mt][nt][1];
            float v2 = acc[mt][nt][2], v3 = acc[mt][nt][3];
            if (gemmid == 0) {
                float b0 = g_bias1[col], b1 = g_bias1[col+1];
                v0 += b0; v1 += b1; v2 += b0; v3 += b1;
                int proj = col >> 9, lc = col & 511;
                if (proj < 2) {
                    v0 = gelu_tanh(v0); v1 = gelu_tanh(v1);
                    v2 = gelu_tanh(v2); v3 = gelu_tanh(v3);
                }
                float* base = g_proj + (size_t)proj * ((size_t)RR*DD);
                *reinterpret_cast<float2*>(base + (size_t)row0*DD + lc)
                    = make_float2(v0, v1);
                *reinterpret_cast<float2*>(base + (size_t)(row0+8)*DD + lc)
                    = make_float2(v2, v3);
            } else {
                float b0 = g_bias2[col], b1 = g_bias2[col+1];
                *reinterpret_cast<float2*>(outp + (size_t)row0*1024 + col)
                    = make_float2(0.5f*v0 + b0, 0.5f*v1 + b1);
                *reinterpret_cast<float2*>(outp + (size_t)(row0+8)*1024 + col)
                    = make_float2(0.5f*v2 + b0, 0.5f*v3 + b1);
            }
        }
    }
}

// =======================================================================
//   conversion kernels (fp32 -> bf16 hi/lo splits)
// =======================================================================
__global__ void conv_a1(const float* __restrict__ query)
{
    size_t i = (size_t)blockIdx.x * 256 + threadIdx.x;   // 16384*1024
    int r = (int)(i >> 10), c = (int)(i & 1023);
    __nv_bfloat16 hi, lo;
    split_bf16(query[i], hi, lo);
    g_a1[(size_t)r*2048 + c]        = hi;
    g_a1[(size_t)r*2048 + 1024 + c] = lo;
}

__global__ void conv_w1(const float* __restrict__ w0, const float* __restrict__ w1,
                        const float* __restrict__ w2, const float* __restrict__ w3,
                        const float* __restrict__ w4, const float* __restrict__ w5)
{
    size_t i = (size_t)blockIdx.x * 256 + threadIdx.x;   // 3072*1024
    int n = (int)(i >> 10), k = (int)(i & 1023);
    int proj = n >> 9, rloc = n & 511;
    const float* src;
    switch (proj) {
        case 0: src = w0; break; case 1: src = w1; break; case 2: src = w2; break;
        case 3: src = w3; break; case 4: src = w4; break; default: src = w5; break;
    }
    __nv_bfloat16 hi, lo;
    split_bf16(src[(size_t)rloc*1024 + k], hi, lo);
    g_w1[(size_t)n*2048 + k]        = hi;
    g_w1[(size_t)n*2048 + 1024 + k] = lo;
}

__global__ void conv_w2(const float* __restrict__ wo_lin, const float* __restrict__ wo_loc)
{
    size_t i = (size_t)blockIdx.x * 256 + threadIdx.x;   // 1024*512
    int n = (int)(i >> 9), k = (int)(i & 511);
    __nv_bfloat16 hi, lo;
    split_bf16(wo_lin[(size_t)n*512 + k], hi, lo);
    g_w2[(size_t)n*2048 + k]       = hi;
    g_w2[(size_t)n*2048 + 512 + k] = lo;
    split_bf16(wo_loc[(size_t)n*512 + k], hi, lo);
    g_w2[(size_t)n*2048 + 1024 + k] = hi;
    g_w2[(size_t)n*2048 + 1536 + k] = lo;
}

__global__ void conv_bias(const float* __restrict__ b0, const float* __restrict__ b1,
                          const float* __restrict__ b2, const float* __restrict__ b3,
                          const float* __restrict__ b4, const float* __restrict__ b5,
                          const float* __restrict__ bo_lin, const float* __restrict__ bo_loc)
{
    int c = blockIdx.x * 256 + threadIdx.x;   // 3072
    int proj = c >> 9, lc = c & 511;
    const float* src;
    switch (proj) {
        case 0: src = b0; break; case 1: src = b1; break; case 2: src = b2; break;
        case 3: src = b3; break; case 4: src = b4; break; default: src = b5; break;
    }
    g_bias1[c] = src[lc];
    if (c < 1024) g_bias2[c] = 0.5f * (bo_lin[c] + bo_loc[c]);
}

// =======================================================================
//   attention kernels (fp32, chunk-local, smem resident)
// =======================================================================
__global__ __launch_bounds__(256)
void attn_local_kernel()
{
    __shared__ float qs[64][33];
    __shared__ float ks[64][33];
    __shared__ float vs[64][33];
    __shared__ float S [64][64];

    int z = blockIdx.x;
    int l = z & 63, h = (z >> 6) & 15, b = z >> 10;
    int tid = threadIdx.x;
    const float* Q = g_proj + (size_t)3*RR*DD;
    const float* K = g_proj + (size_t)4*RR*DD;
    const float* V = g_proj + (size_t)5*RR*DD;

    for (int idx = tid; idx < 64*32; idx += 256) {
        int c = idx >> 5, dh = idx & 31;
        size_t off = ((size_t)((l*64 + c)*BB + b))*DD + h*32 + dh;
        qs[c][dh] = Q[off]; ks[c][dh] = K[off]; vs[c][dh] = V[off];
    }
    __syncthreads();

    for (int idx = tid; idx < 64*64; idx += 256) {
        int c = idx >> 6, j = idx & 63;
        float s = 0.f;
        if (j <= c) {
            #pragma unroll
            for (int d = 0; d < 32; d++) s += qs[c][d]*ks[j][d];
            s = fmaxf(s, 0.f);
        }
        S[c][j] = s;
    }
    __syncthreads();

    for (int idx = tid; idx < 64*32; idx += 256) {
        int c = idx >> 5, dh = idx & 31;
        float o = 0.f;
        #pragma unroll
        for (int j = 0; j < 64; j++) o += S[c][j]*vs[j][dh];
        size_t off = ((size_t)((l*64 + c)*BB + b))*DD + h*32 + dh;
        g_oloc[off] = o;
    }
}

__global__ __launch_bounds__(256)
void attn_kv_kernel()
{
    __shared__ float ks[64][33];
    __shared__ float vs[64][33];

    int z = blockIdx.x;
    int l = z & 63, h = (z >> 6) & 15, b = z >> 10;
    int tid = threadIdx.x;
    const float* K = g_proj + (size_t)1*RR*DD;
    const float* V = g_proj + (size_t)2*RR*DD;

    for (int idx = tid; idx < 64*32; idx += 256) {
        int c = idx >> 5, dh = idx & 31;
        size_t off = ((size_t)((l*64 + c)*BB + b))*DD + h*32 + dh;
        ks[c][dh] = K[off]; vs[c][dh] = V[off];
    }
    __syncthreads();

    for (int idx = tid; idx < 32*32; idx += 256) {
        int d = idx >> 5, e = idx & 31;
        float s = 0.f;
        #pragma unroll
        for (int c = 0; c < 64; c++) s += ks[c][d]*vs[c][e];
        g_kv[(size_t)z*1024 + idx] = s;
    }
}

__global__ __launch_bounds__(256)
void kv_cumsum_kernel()
{
    int bh = blockIdx.x;
    const float* src = g_kv     + (size_t)bh*LL*1024;
    float*       dst = g_kvprev + (size_t)bh*LL*1024;
    for (int j = threadIdx.x; j < 1024; j += 256) {
        float acc = 0.f;
        #pragma unroll 4
        for (int l = 0; l < LL; l++) {
            dst[l*1024 + j] = acc;
            acc += src[l*1024 + j];
        }
    }
}

__global__ __launch_bounds__(256)
void attn_lin_kernel()
{
    __shared__ float qs [64][33];
    __shared__ float ks [64][33];
    __shared__ float vs [64][33];
    __shared__ float kvp[32][33];
    __shared__ float S  [64][64];

    int z = blockIdx.x;
    int l = z & 63, h = (z >> 6) & 15, b = z >> 10;
    int tid = threadIdx.x;
    const float* Q = g_proj;
    const float* K = g_proj + (size_t)1*RR*DD;
    const float* V = g_proj + (size_t)2*RR*DD;

    for (int idx = tid; idx < 64*32; idx += 256) {
        int c = idx >> 5, dh = idx & 31;
        size_t off = ((size_t)((l*64 + c)*BB + b))*DD + h*32 + dh;
        qs[c][dh] = Q[off]; ks[c][dh] = K[off]; vs[c][dh] = V[off];
    }
    for (int idx = tid; idx < 32*32; idx += 256)
        kvp[idx >> 5][idx & 31] = g_kvprev[(size_t)z*1024 + idx];
    __syncthreads();

    for (int idx = tid; idx < 64*64; idx += 256) {
        int c = idx >> 6, j = idx & 63;
        float s = 0.f;
        if (j <= c) {
            #pragma unroll
            for (int d = 0; d < 32; d++) s += qs[c][d]*ks[j][d];
        }
        S[c][j] = s;
    }
    __syncthreads();

    for (int idx = tid; idx < 64*32; idx += 256) {
        int c = idx >> 5, dh = idx & 31;
        float o = 0.f;
        #pragma unroll
        for (int j = 0; j < 64; j++) o += S[c][j]*vs[j][dh];
        #pragma unroll
        for (int d = 0; d < 32; d++) o += qs[c][d]*kvp[d][dh];
        size_t off = ((size_t)((l*64 + c)*BB + b))*DD + h*32 + dh;
        g_olin[off] = o;
    }
}

// ---------------- norms -> bf16 hi/lo splits into g_a2 ----------------
__device__ __forceinline__ float block_sum256(float v, float* sbuf) {
    int tid = threadIdx.x;
    #pragma unroll
    for (int o = 16; o > 0; o >>= 1) v += __shfl_xor_sync(0xffffffffu, v, o);
    __syncthreads();
    if ((tid & 31) == 0) sbuf[tid >> 5] = v;
    __syncthreads();
    float t = sbuf[0];
    #pragma unroll
    for (int w = 1; w < 8; w++) t += sbuf[w];
    return t;
}

__global__ __launch_bounds__(256)
void norm_kernel(const float* __restrict__ ln_g, const float* __restrict__ ln_b,
                 const float* __restrict__ gsc,  const float* __restrict__ ggt)
{
    __shared__ float sbuf[8];
    int r = blockIdx.x, tid = threadIdx.x;
    __nv_bfloat16* a2 = g_a2 + (size_t)r*2048;

    // LayerNorm over D=512
    const float* xl = g_olin + (size_t)r*DD;
    float a0 = xl[tid], a1 = xl[tid + 256];
    float mu = block_sum256(a0 + a1, sbuf) * (1.0f/512.0f);
    float d0 = a0 - mu, d1 = a1 - mu;
    float var = block_sum256(d0*d0 + d1*d1, sbuf) * (1.0f/512.0f);
    float rs = rsqrtf(var + 1e-5f);
    float y0 = d0*rs*ln_g[tid      ] + ln_b[tid      ];
    float y1 = d1*rs*ln_g[tid + 256] + ln_b[tid + 256];
    __nv_bfloat16 hi, lo;
    split_bf16(y0, hi, lo); a2[tid      ] = hi; a2[512 + tid      ] = lo;
    split_bf16(y1, hi, lo); a2[tid + 256] = hi; a2[512 + tid + 256] = lo;

    // gated RMSNorm
    const float* xo = g_oloc + (size_t)r*DD;
    float b0 = xo[tid], b1 = xo[tid + 256];
    float ms = block_sum256(b0*b0 + b1*b1, sbuf) * (1.0f/512.0f);
    float inv = rsqrtf(ms + 1e-8f);
    float s0 = 1.0f/(1.0f + expf(-ggt[tid      ]*b0));
    float s1 = 1.0f/(1.0f + expf(-ggt[tid + 256]*b1));
    float z0 = b0*inv*gsc[tid      ]*s0;
    float z1 = b1*inv*gsc[tid + 256]*s1;
    split_bf16(z0, hi, lo); a2[1024 + tid      ] = hi; a2[1536 + tid      ] = lo;
    split_bf16(z1, hi, lo); a2[1024 + tid + 256] = hi; a2[1536 + tid + 256] = lo;
}

// =======================================================================
//   launch  (gemm0 placed at launch idx 3 so ncu's skip lands on it)
// =======================================================================
extern "C" void kernel_launch(void* const* d_in, const int* in_sizes, int n_in,
                              void* d_out, int out_size)
{
    const float* query   = (const float*)d_in[0];
    const float* wq_lin  = (const float*)d_in[1];
    const float* bq_lin  = (const float*)d_in[2];
    const float* wk_lin  = (const float*)d_in[3];
    const float* bk_lin  = (const float*)d_in[4];
    const float* wv_lin  = (const float*)d_in[5];
    const float* bv_lin  = (const float*)d_in[6];
    const float* wo_lin  = (const float*)d_in[7];
    const float* bo_lin  = (const float*)d_in[8];
    const float* wq_loc  = (const float*)d_in[9];
    const float* bq_loc  = (const float*)d_in[10];
    const float* wk_loc  = (const float*)d_in[11];
    const float* bk_loc  = (const float*)d_in[12];
    const float* wv_loc  = (const float*)d_in[13];
    const float* bv_loc  = (const float*)d_in[14];
    const float* wo_loc  = (const float*)d_in[15];
    const float* bo_loc  = (const float*)d_in[16];
    const float* ln_g    = (const float*)d_in[17];
    const float* ln_b    = (const float*)d_in[18];
    const float* grn_s   = (const float*)d_in[19];
    const float* grn_g   = (const float*)d_in[20];
    float* out = (float*)d_out;

    cudaFuncSetAttribute(gemm_tc, cudaFuncAttributeMaxDynamicSharedMemorySize, SMEM_GEMM);

    // conversions needed by gemm0 first
    conv_bias<<<3072/256, 256>>>(bq_lin, bk_lin, bv_lin, bq_loc, bk_loc, bv_loc, bo_lin, bo_loc);
    conv_a1  <<<(RR*1024)/256, 256>>>(query);
    conv_w1  <<<(3072*1024)/256, 256>>>(wq_lin, wk_lin, wv_lin, wq_loc, wk_loc, wv_loc);

    // fused input projections (6-in-1), bf16 tensor cores   [launch idx 3]
    gemm_tc<<<dim3(3072/BN, RR/BM), 256, SMEM_GEMM>>>(0, nullptr);

    conv_w2  <<<(1024*512)/256, 256>>>(wo_lin, wo_loc);

    // attention                                              [idx 5..8]
    attn_local_kernel<<<BB*HH*LL, 256>>>();
    attn_kv_kernel   <<<BB*HH*LL, 256>>>();
    kv_cumsum_kernel <<<BB*HH,    256>>>();
    attn_lin_kernel  <<<BB*HH*LL, 256>>>();

    // norms (emit bf16 hi/lo operands for the output GEMM)
    norm_kernel<<<RR, 256>>>(ln_g, ln_b, grn_s, grn_g);

    // fused output projections (2-in-1), writes d_out
    gemm_tc<<<dim3(1024/BN, RR/BM), 256, SMEM_GEMM>>>(1, out);
}

// round 5
// speedup vs baseline: 2.1677x; 1.0487x over previous
#include <cuda_runtime.h>
#include <cuda_bf16.h>
#include <stdint.h>
#include <math.h>

// ---------------- problem constants ----------------
#define NN 4096
#define BB 4
#define EE 1024
#define HH 16
#define DD 512
#define DH 32
#define LL 64
#define RR (NN*BB)   // 16384 rows

// ---------------- gemm geometry ----------------
#define BM 128
#define BN 256
#define BK 32                      // bf16 elems per k-step (64 bytes per row)
#define KSTEPS 96                  // both gemms: K' = 3072
#define STAGE_BYTES ((BM+BN)*64)   // 24576
#define NSTAGES 4
#define SMEM_GEMM (NSTAGES*STAGE_BYTES)  // 98304

// ---------------- device scratch ----------------
__device__ __nv_bfloat16 g_a1[(size_t)RR*2048];      // [query_hi | query_lo]
__device__ __nv_bfloat16 g_w1[(size_t)3072*2048];    // 6 proj weights; cols [hi|lo]
__device__ __nv_bfloat16 g_a2[(size_t)RR*2048];      // [ln_hi | ln_lo | grn_hi | grn_lo]
__device__ __nv_bfloat16 g_w2[(size_t)1024*2048];    // [wol_hi | wol_lo | woc_hi | woc_lo]
__device__ float g_bias1[3072];
__device__ float g_bias2[1024];
__device__ float g_proj[(size_t)6*RR*DD];            // q_lin,k_lin,v_lin,q_loc,k_loc,v_loc
__device__ float g_olin[(size_t)RR*DD];
__device__ float g_oloc[(size_t)RR*DD];
__device__ float g_kv    [(size_t)BB*HH*LL*DH*DH];
__device__ float g_kvprev[(size_t)BB*HH*LL*DH*DH];

// ---------------- asm helpers (base sm_80-era; no 'a' features) ----------
__device__ __forceinline__ uint32_t smem_u32(const void* p) {
    uint32_t a;
    asm("{ .reg .u64 t; cvta.to.shared.u64 t, %1; cvt.u32.u64 %0, t; }" : "=r"(a) : "l"(p));
    return a;
}
__device__ __forceinline__ void cpasync16(uint32_t s, const void* g) {
    asm volatile("cp.async.cg.shared.global [%0], [%1], 16;" :: "r"(s), "l"(g));
}
#define CP_COMMIT() asm volatile("cp.async.commit_group;" ::: "memory")
#define CP_WAIT2()  asm volatile("cp.async.wait_group 2;"  ::: "memory")

__device__ __forceinline__ void ldsm4(uint32_t* r, uint32_t addr) {
    asm volatile("ldmatrix.sync.aligned.m8n8.x4.shared.b16 {%0,%1,%2,%3}, [%4];"
        : "=r"(r[0]), "=r"(r[1]), "=r"(r[2]), "=r"(r[3]) : "r"(addr));
}
__device__ __forceinline__ void mma_bf16(float* c, const uint32_t* a,
                                         uint32_t b0, uint32_t b1) {
    asm volatile(
        "mma.sync.aligned.m16n8k16.row.col.f32.bf16.bf16.f32 "
        "{%0,%1,%2,%3}, {%4,%5,%6,%7}, {%8,%9}, {%0,%1,%2,%3};"
        : "+f"(c[0]), "+f"(c[1]), "+f"(c[2]), "+f"(c[3])
        : "r"(a[0]), "r"(a[1]), "r"(a[2]), "r"(a[3]), "r"(b0), "r"(b1));
}

__device__ __forceinline__ float gelu_tanh(float x) {
    float x3 = x*x*x;
    return 0.5f*x*(1.0f + tanhf(0.7978845608028654f*(x + 0.044715f*x3)));
}
__device__ __forceinline__ void split_bf16(float x, __nv_bfloat16& hi, __nv_bfloat16& lo) {
    hi = __float2bfloat16(x);
    lo = __float2bfloat16(x - __bfloat162float(hi));
}

// swizzled byte offset inside a [rows][32 bf16] tile (64B rows)
__device__ __forceinline__ uint32_t swz(int row, int kq) {
    return (uint32_t)(row*64 + ((kq ^ ((row>>1)&3)) << 4));
}

// (aoff,boff) in bf16 elements along the 2048-wide concatenated K for k-step ks
__device__ __forceinline__ void seg_off(int gemmid, int ks, int& aoff, int& boff) {
    if (gemmid == 0) {
        int seg = ks >> 5, ko = (ks & 31)*32;
        aoff = ko + (seg == 2 ? 1024 : 0);
        boff = ko + (seg == 1 ? 1024 : 0);
    } else {
        int seg = ks >> 4, ko = (ks & 15)*32;
        int sa, sb;
        switch (seg) {
            case 0:  sa = 0;    sb = 0;    break;
            case 1:  sa = 0;    sb = 512;  break;
            case 2:  sa = 512;  sb = 0;    break;
            case 3:  sa = 1024; sb = 1024; break;
            case 4:  sa = 1024; sb = 1536; break;
            default: sa = 1536; sb = 1024; break;
        }
        aoff = sa + ko; boff = sb + ko;
    }
}

// =======================================================================
//   bf16 mma.sync GEMM: C[M,N] = A[M,K'] @ B[N,K']^T (3-term bf16 split)
//   512 threads, warp grid 4x4, warp tile 32x64, 4-stage cp.async pipeline
//   gemmid 0: N=3072 -> g_proj (+bias, gelu on first 2 projections)
//   gemmid 1: N=1024 -> out = 0.5*acc + bias2
// =======================================================================
__global__ __launch_bounds__(512, 1)
void gemm_tc(int gemmid, float* __restrict__ outp)
{
    extern __shared__ char smem[];
    const uint32_t sb = smem_u32(smem);
    const int tid = threadIdx.x;
    const int mbase = blockIdx.y * BM;
    const int nbase = blockIdx.x * BN;
    const __nv_bfloat16* __restrict__ Ap = gemmid ? g_a2 : g_a1;
    const __nv_bfloat16* __restrict__ Bp = gemmid ? g_w2 : g_w1;

    float acc[2][8][4];
    #pragma unroll
    for (int i = 0; i < 2; i++)
        #pragma unroll
        for (int j = 0; j < 8; j++)
            #pragma unroll
            for (int q = 0; q < 4; q++) acc[i][j][q] = 0.f;

    // ---- stage loader: A 128 rows x 4 chunks (512 tasks = 1/thread),
    //                    B 256 rows x 4 chunks (1024 tasks = 2/thread) ----
    const int ld_row = tid >> 2, ld_ch = tid & 3;
    const uint32_t ld_swzA = swz(ld_row, ld_ch);
    const int ld_rowB0 = tid >> 2, ld_rowB1 = (tid + 512) >> 2;
    const uint32_t ld_swzB0 = (uint32_t)(BM*64) + swz(ld_rowB0, ld_ch);
    const uint32_t ld_swzB1 = (uint32_t)(BM*64) + swz(ld_rowB1, ld_ch);

    auto load_stage = [&](uint32_t sst, int aoff, int boff) {
        cpasync16(sst + ld_swzA,
                  Ap + (size_t)(mbase + ld_row)*2048 + aoff + ld_ch*8);
        cpasync16(sst + ld_swzB0,
                  Bp + (size_t)(nbase + ld_rowB0)*2048 + boff + ld_ch*8);
        cpasync16(sst + ld_swzB1,
                  Bp + (size_t)(nbase + ld_rowB1)*2048 + boff + ld_ch*8);
    };

    {   // prologue: stages 0,1,2
        int ao, bo;
        seg_off(gemmid, 0, ao, bo); load_stage(sb, ao, bo); CP_COMMIT();
        seg_off(gemmid, 1, ao, bo); load_stage(sb + STAGE_BYTES, ao, bo); CP_COMMIT();
        seg_off(gemmid, 2, ao, bo); load_stage(sb + 2*STAGE_BYTES, ao, bo); CP_COMMIT();
    }

    const int lane = tid & 31, wid = tid >> 5;
    const int m0 = (wid & 3) * 32;       // 4 warps along M (32 rows each)
    const int n0 = (wid >> 2) * 64;      // 4 warps along N (64 cols each)

    // precomputed swizzle bases: addr = base ^ (kq<<4)
    uint32_t aBase[2], bBase[4];
    #pragma unroll
    for (int mt = 0; mt < 2; mt++) {
        int row = m0 + mt*16 + (lane & 15);
        aBase[mt] = (uint32_t)(row*64) ^ (((uint32_t)(row>>1)&3) << 4);
    }
    #pragma unroll
    for (int p = 0; p < 4; p++) {
        int row = n0 + p*16 + (lane & 15);
        bBase[p] = (uint32_t)(BM*64 + row*64) ^ (((uint32_t)(row>>1)&3) << 4);
    }
    const uint32_t kqSel = (uint32_t)(lane >> 4) << 4;   // 0 or 16

    for (int ks = 0; ks < KSTEPS; ks++) {
        CP_WAIT2();
        __syncthreads();
        if (ks + 3 < KSTEPS) {
            int ao, bo; seg_off(gemmid, ks + 3, ao, bo);
            load_stage(sb + (uint32_t)(((ks + 3) % NSTAGES) * STAGE_BYTES), ao, bo);
        }
        CP_COMMIT();

        uint32_t sS = sb + (uint32_t)((ks % NSTAGES) * STAGE_BYTES);
        #pragma unroll
        for (int kt = 0; kt < 2; kt++) {
            uint32_t kx = ((uint32_t)(kt*2) << 4) ^ kqSel;  // (kt*2 + lane>>4)<<4
            uint32_t aF[2][4];
            ldsm4(aF[0], sS + (aBase[0] ^ kx));
            ldsm4(aF[1], sS + (aBase[1] ^ kx));
            #pragma unroll
            for (int p = 0; p < 4; p++) {
                uint32_t bF[4];
                ldsm4(bF, sS + (bBase[p] ^ kx));
                // bF: r0=(n-group 2p, klo) r1=(2p+1, klo) r2=(2p, khi) r3=(2p+1, khi)
                #pragma unroll
                for (int mt = 0; mt < 2; mt++) {
                    mma_bf16(acc[mt][2*p],   aF[mt], bF[0], bF[2]);
                    mma_bf16(acc[mt][2*p+1], aF[mt], bF[1], bF[3]);
                }
            }
        }
    }

    // ---- epilogue: registers -> global with bias / gelu / 0.5-avg ----
    const int r_lo  = mbase + m0 + (lane >> 2);
    const int cbase = nbase + n0 + (lane & 3)*2;
    #pragma unroll
    for (int mt = 0; mt < 2; mt++) {
        #pragma unroll
        for (int nt = 0; nt < 8; nt++) {
            int col = cbase + nt*8;
            int row0 = r_lo + mt*16;
            float v0 = acc[mt][nt][0], v1 = acc[mt][nt][1];
            float v2 = acc[mt][nt][2], v3 = acc[mt][nt][3];
            if (gemmid == 0) {
                float b0 = g_bias1[col], b1 = g_bias1[col+1];
                v0 += b0; v1 += b1; v2 += b0; v3 += b1;
                int proj = col >> 9, lc = col & 511;
                if (proj < 2) {
                    v0 = gelu_tanh(v0); v1 = gelu_tanh(v1);
                    v2 = gelu_tanh(v2); v3 = gelu_tanh(v3);
                }
                float* base = g_proj + (size_t)proj * ((size_t)RR*DD);
                *reinterpret_cast<float2*>(base + (size_t)row0*DD + lc)
                    = make_float2(v0, v1);
                *reinterpret_cast<float2*>(base + (size_t)(row0+8)*DD + lc)
                    = make_float2(v2, v3);
            } else {
                float b0 = g_bias2[col], b1 = g_bias2[col+1];
                *reinterpret_cast<float2*>(outp + (size_t)row0*1024 + col)
                    = make_float2(0.5f*v0 + b0, 0.5f*v1 + b1);
                *reinterpret_cast<float2*>(outp + (size_t)(row0+8)*1024 + col)
                    = make_float2(0.5f*v2 + b0, 0.5f*v3 + b1);
            }
        }
    }
}

// =======================================================================
//   conversion kernels (fp32 -> bf16 hi/lo splits)
// =======================================================================
__global__ void conv_a1(const float* __restrict__ query)
{
    size_t i = (size_t)blockIdx.x * 256 + threadIdx.x;   // 16384*1024
    int r = (int)(i >> 10), c = (int)(i & 1023);
    __nv_bfloat16 hi, lo;
    split_bf16(query[i], hi, lo);
    g_a1[(size_t)r*2048 + c]        = hi;
    g_a1[(size_t)r*2048 + 1024 + c] = lo;
}

__global__ void conv_w1(const float* __restrict__ w0, const float* __restrict__ w1,
                        const float* __restrict__ w2, const float* __restrict__ w3,
                        const float* __restrict__ w4, const float* __restrict__ w5)
{
    size_t i = (size_t)blockIdx.x * 256 + threadIdx.x;   // 3072*1024
    int n = (int)(i >> 10), k = (int)(i & 1023);
    int proj = n >> 9, rloc = n & 511;
    const float* src;
    switch (proj) {
        case 0: src = w0; break; case 1: src = w1; break; case 2: src = w2; break;
        case 3: src = w3; break; case 4: src = w4; break; default: src = w5; break;
    }
    __nv_bfloat16 hi, lo;
    split_bf16(src[(size_t)rloc*1024 + k], hi, lo);
    g_w1[(size_t)n*2048 + k]        = hi;
    g_w1[(size_t)n*2048 + 1024 + k] = lo;
}

__global__ void conv_w2(const float* __restrict__ wo_lin, const float* __restrict__ wo_loc)
{
    size_t i = (size_t)blockIdx.x * 256 + threadIdx.x;   // 1024*512
    int n = (int)(i >> 9), k = (int)(i & 511);
    __nv_bfloat16 hi, lo;
    split_bf16(wo_lin[(size_t)n*512 + k], hi, lo);
    g_w2[(size_t)n*2048 + k]       = hi;
    g_w2[(size_t)n*2048 + 512 + k] = lo;
    split_bf16(wo_loc[(size_t)n*512 + k], hi, lo);
    g_w2[(size_t)n*2048 + 1024 + k] = hi;
    g_w2[(size_t)n*2048 + 1536 + k] = lo;
}

__global__ void conv_bias(const float* __restrict__ b0, const float* __restrict__ b1,
                          const float* __restrict__ b2, const float* __restrict__ b3,
                          const float* __restrict__ b4, const float* __restrict__ b5,
                          const float* __restrict__ bo_lin, const float* __restrict__ bo_loc)
{
    int c = blockIdx.x * 256 + threadIdx.x;   // 3072
    int proj = c >> 9, lc = c & 511;
    const float* src;
    switch (proj) {
        case 0: src = b0; break; case 1: src = b1; break; case 2: src = b2; break;
        case 3: src = b3; break; case 4: src = b4; break; default: src = b5; break;
    }
    g_bias1[c] = src[lc];
    if (c < 1024) g_bias2[c] = 0.5f * (bo_lin[c] + bo_loc[c]);
}

// =======================================================================
//   attention kernels (fp32, chunk-local, smem resident)
// =======================================================================
__global__ __launch_bounds__(256)
void attn_local_kernel()
{
    __shared__ float qs[64][33];
    __shared__ float ks[64][33];
    __shared__ float vs[64][33];
    __shared__ float S [64][64];

    int z = blockIdx.x;
    int l = z & 63, h = (z >> 6) & 15, b = z >> 10;
    int tid = threadIdx.x;
    const float* Q = g_proj + (size_t)3*RR*DD;
    const float* K = g_proj + (size_t)4*RR*DD;
    const float* V = g_proj + (size_t)5*RR*DD;

    for (int idx = tid; idx < 64*32; idx += 256) {
        int c = idx >> 5, dh = idx & 31;
        size_t off = ((size_t)((l*64 + c)*BB + b))*DD + h*32 + dh;
        qs[c][dh] = Q[off]; ks[c][dh] = K[off]; vs[c][dh] = V[off];
    }
    __syncthreads();

    for (int idx = tid; idx < 64*64; idx += 256) {
        int c = idx >> 6, j = idx & 63;
        float s = 0.f;
        if (j <= c) {
            #pragma unroll
            for (int d = 0; d < 32; d++) s += qs[c][d]*ks[j][d];
            s = fmaxf(s, 0.f);
        }
        S[c][j] = s;
    }
    __syncthreads();

    for (int idx = tid; idx < 64*32; idx += 256) {
        int c = idx >> 5, dh = idx & 31;
        float o = 0.f;
        #pragma unroll
        for (int j = 0; j < 64; j++) o += S[c][j]*vs[j][dh];
        size_t off = ((size_t)((l*64 + c)*BB + b))*DD + h*32 + dh;
        g_oloc[off] = o;
    }
}

__global__ __launch_bounds__(256)
void attn_kv_kernel()
{
    __shared__ float ks[64][33];
    __shared__ float vs[64][33];

    int z = blockIdx.x;
    int l = z & 63, h = (z >> 6) & 15, b = z >> 10;
    int tid = threadIdx.x;
    const float* K = g_proj + (size_t)1*RR*DD;
    const float* V = g_proj + (size_t)2*RR*DD;

    for (int idx = tid; idx < 64*32; idx += 256) {
        int c = idx >> 5, dh = idx & 31;
        size_t off = ((size_t)((l*64 + c)*BB + b))*DD + h*32 + dh;
        ks[c][dh] = K[off]; vs[c][dh] = V[off];
    }
    __syncthreads();

    for (int idx = tid; idx < 32*32; idx += 256) {
        int d = idx >> 5, e = idx & 31;
        float s = 0.f;
        #pragma unroll
        for (int c = 0; c < 64; c++) s += ks[c][d]*vs[c][e];
        g_kv[(size_t)z*1024 + idx] = s;
    }
}

__global__ __launch_bounds__(256)
void kv_cumsum_kernel()
{
    int bh = blockIdx.x;
    const float* src = g_kv     + (size_t)bh*LL*1024;
    float*       dst = g_kvprev + (size_t)bh*LL*1024;
    for (int j = threadIdx.x; j < 1024; j += 256) {
        float acc = 0.f;
        #pragma unroll 4
        for (int l = 0; l < LL; l++) {
            dst[l*1024 + j] = acc;
            acc += src[l*1024 + j];
        }
    }
}

__global__ __launch_bounds__(256)
void attn_lin_kernel()
{
    __shared__ float qs [64][33];
    __shared__ float ks [64][33];
    __shared__ float vs [64][33];
    __shared__ float kvp[32][33];
    __shared__ float S  [64][64];

    int z = blockIdx.x;
    int l = z & 63, h = (z >> 6) & 15, b = z >> 10;
    int tid = threadIdx.x;
    const float* Q = g_proj;
    const float* K = g_proj + (size_t)1*RR*DD;
    const float* V = g_proj + (size_t)2*RR*DD;

    for (int idx = tid; idx < 64*32; idx += 256) {
        int c = idx >> 5, dh = idx & 31;
        size_t off = ((size_t)((l*64 + c)*BB + b))*DD + h*32 + dh;
        qs[c][dh] = Q[off]; ks[c][dh] = K[off]; vs[c][dh] = V[off];
    }
    for (int idx = tid; idx < 32*32; idx += 256)
        kvp[idx >> 5][idx & 31] = g_kvprev[(size_t)z*1024 + idx];
    __syncthreads();

    for (int idx = tid; idx < 64*64; idx += 256) {
        int c = idx >> 6, j = idx & 63;
        float s = 0.f;
        if (j <= c) {
            #pragma unroll
            for (int d = 0; d < 32; d++) s += qs[c][d]*ks[j][d];
        }
        S[c][j] = s;
    }
    __syncthreads();

    for (int idx = tid; idx < 64*32; idx += 256) {
        int c = idx >> 5, dh = idx & 31;
        float o = 0.f;
        #pragma unroll
        for (int j = 0; j < 64; j++) o += S[c][j]*vs[j][dh];
        #pragma unroll
        for (int d = 0; d < 32; d++) o += qs[c][d]*kvp[d][dh];
        size_t off = ((size_t)((l*64 + c)*BB + b))*DD + h*32 + dh;
        g_olin[off] = o;
    }
}

// ---------------- norms -> bf16 hi/lo splits into g_a2 ----------------
__device__ __forceinline__ float block_sum256(float v, float* sbuf) {
    int tid = threadIdx.x;
    #pragma unroll
    for (int o = 16; o > 0; o >>= 1) v += __shfl_xor_sync(0xffffffffu, v, o);
    __syncthreads();
    if ((tid & 31) == 0) sbuf[tid >> 5] = v;
    __syncthreads();
    float t = sbuf[0];
    #pragma unroll
    for (int w = 1; w < 8; w++) t += sbuf[w];
    return t;
}

__global__ __launch_bounds__(256)
void norm_kernel(const float* __restrict__ ln_g, const float* __restrict__ ln_b,
                 const float* __restrict__ gsc,  const float* __restrict__ ggt)
{
    __shared__ float sbuf[8];
    int r = blockIdx.x, tid = threadIdx.x;
    __nv_bfloat16* a2 = g_a2 + (size_t)r*2048;

    // LayerNorm over D=512
    const float* xl = g_olin + (size_t)r*DD;
    float a0 = xl[tid], a1 = xl[tid + 256];
    float mu = block_sum256(a0 + a1, sbuf) * (1.0f/512.0f);
    float d0 = a0 - mu, d1 = a1 - mu;
    float var = block_sum256(d0*d0 + d1*d1, sbuf) * (1.0f/512.0f);
    float rs = rsqrtf(var + 1e-5f);
    float y0 = d0*rs*ln_g[tid      ] + ln_b[tid      ];
    float y1 = d1*rs*ln_g[tid + 256] + ln_b[tid + 256];
    __nv_bfloat16 hi, lo;
    split_bf16(y0, hi, lo); a2[tid      ] = hi; a2[512 + tid      ] = lo;
    split_bf16(y1, hi, lo); a2[tid + 256] = hi; a2[512 + tid + 256] = lo;

    // gated RMSNorm
    const float* xo = g_oloc + (size_t)r*DD;
    float b0 = xo[tid], b1 = xo[tid + 256];
    float ms = block_sum256(b0*b0 + b1*b1, sbuf) * (1.0f/512.0f);
    float inv = rsqrtf(ms + 1e-8f);
    float s0 = 1.0f/(1.0f + expf(-ggt[tid      ]*b0));
    float s1 = 1.0f/(1.0f + expf(-ggt[tid + 256]*b1));
    float z0 = b0*inv*gsc[tid      ]*s0;
    float z1 = b1*inv*gsc[tid + 256]*s1;
    split_bf16(z0, hi, lo); a2[1024 + tid      ] = hi; a2[1536 + tid      ] = lo;
    split_bf16(z1, hi, lo); a2[1024 + tid + 256] = hi; a2[1536 + tid + 256] = lo;
}

// =======================================================================
//   launch  (gemm0 at launch idx 3 so ncu's skip lands on it)
// =======================================================================
extern "C" void kernel_launch(void* const* d_in, const int* in_sizes, int n_in,
                              void* d_out, int out_size)
{
    const float* query   = (const float*)d_in[0];
    const float* wq_lin  = (const float*)d_in[1];
    const float* bq_lin  = (const float*)d_in[2];
    const float* wk_lin  = (const float*)d_in[3];
    const float* bk_lin  = (const float*)d_in[4];
    const float* wv_lin  = (const float*)d_in[5];
    const float* bv_lin  = (const float*)d_in[6];
    const float* wo_lin  = (const float*)d_in[7];
    const float* bo_lin  = (const float*)d_in[8];
    const float* wq_loc  = (const float*)d_in[9];
    const float* bq_loc  = (const float*)d_in[10];
    const float* wk_loc  = (const float*)d_in[11];
    const float* bk_loc  = (const float*)d_in[12];
    const float* wv_loc  = (const float*)d_in[13];
    const float* bv_loc  = (const float*)d_in[14];
    const float* wo_loc  = (const float*)d_in[15];
    const float* bo_loc  = (const float*)d_in[16];
    const float* ln_g    = (const float*)d_in[17];
    const float* ln_b    = (const float*)d_in[18];
    const float* grn_s   = (const float*)d_in[19];
    const float* grn_g   = (const float*)d_in[20];
    float* out = (float*)d_out;

    cudaFuncSetAttribute(gemm_tc, cudaFuncAttributeMaxDynamicSharedMemorySize, SMEM_GEMM);

    // conversions needed by gemm0 first
    conv_bias<<<3072/256, 256>>>(bq_lin, bk_lin, bv_lin, bq_loc, bk_loc, bv_loc, bo_lin, bo_loc);
    conv_a1  <<<(RR*1024)/256, 256>>>(query);
    conv_w1  <<<(3072*1024)/256, 256>>>(wq_lin, wk_lin, wv_lin, wq_loc, wk_loc, wv_loc);

    // fused input projections (6-in-1), bf16 tensor cores   [launch idx 3]
    gemm_tc<<<dim3(3072/BN, RR/BM), 512, SMEM_GEMM>>>(0, nullptr);

    conv_w2  <<<(1024*512)/256, 256>>>(wo_lin, wo_loc);

    // attention
    attn_local_kernel<<<BB*HH*LL, 256>>>();
    attn_kv_kernel   <<<BB*HH*LL, 256>>>();
    kv_cumsum_kernel <<<BB*HH,    256>>>();
    attn_lin_kernel  <<<BB*HH*LL, 256>>>();

    // norms (emit bf16 hi/lo operands for the output GEMM)
    norm_kernel<<<RR, 256>>>(ln_g, ln_b, grn_s, grn_g);

    // fused output projections (2-in-1), writes d_out
    gemm_tc<<<dim3(1024/BN, RR/BM), 512, SMEM_GEMM>>>(1, out);
}

// round 6
// speedup vs baseline: 2.3577x; 1.0877x over previous
#include <cuda_runtime.h>
#include <cuda_bf16.h>
#include <stdint.h>
#include <math.h>

// ---------------- problem constants ----------------
#define NN 4096
#define BB 4
#define EE 1024
#define HH 16
#define DD 512
#define DH 32
#define LL 64
#define RR (NN*BB)   // 16384 rows

// ---------------- gemm geometry ----------------
#define BM 128
#define BN 256
#define BK 64                       // bf16 elems per k-step (128 bytes per row)
#define KSTEPS 48                   // both gemms: K' = 3072
#define STAGE_BYTES ((BM+BN)*128)   // 49152
#define NSTAGES 3
#define SMEM_GEMM (NSTAGES*STAGE_BYTES)  // 147456

// ---------------- device scratch ----------------
__device__ __nv_bfloat16 g_a1[(size_t)RR*2048];      // [query_hi | query_lo]
__device__ __nv_bfloat16 g_w1[(size_t)3072*2048];    // 6 proj weights; cols [hi|lo]
__device__ __nv_bfloat16 g_a2[(size_t)RR*2048];      // [ln_hi | ln_lo | grn_hi | grn_lo]
__device__ __nv_bfloat16 g_w2[(size_t)1024*2048];    // [wol_hi | wol_lo | woc_hi | woc_lo]
__device__ float g_bias1[3072];
__device__ float g_bias2[1024];
__device__ float g_proj[(size_t)6*RR*DD];            // q_lin,k_lin,v_lin,q_loc,k_loc,v_loc
__device__ float g_olin[(size_t)RR*DD];
__device__ float g_oloc[(size_t)RR*DD];
__device__ float g_kv    [(size_t)BB*HH*LL*DH*DH];
__device__ float g_kvprev[(size_t)BB*HH*LL*DH*DH];

// ---------------- asm helpers (base sm_80-era; no 'a' features) ----------
__device__ __forceinline__ uint32_t smem_u32(const void* p) {
    uint32_t a;
    asm("{ .reg .u64 t; cvta.to.shared.u64 t, %1; cvt.u32.u64 %0, t; }" : "=r"(a) : "l"(p));
    return a;
}
__device__ __forceinline__ void cpasync16(uint32_t s, const void* g) {
    asm volatile("cp.async.cg.shared.global [%0], [%1], 16;" :: "r"(s), "l"(g));
}
#define CP_COMMIT() asm volatile("cp.async.commit_group;" ::: "memory")
#define CP_WAIT1()  asm volatile("cp.async.wait_group 1;"  ::: "memory")

__device__ __forceinline__ void ldsm4(uint32_t* r, uint32_t addr) {
    asm volatile("ldmatrix.sync.aligned.m8n8.x4.shared.b16 {%0,%1,%2,%3}, [%4];"
        : "=r"(r[0]), "=r"(r[1]), "=r"(r[2]), "=r"(r[3]) : "r"(addr));
}
__device__ __forceinline__ void mma_bf16(float* c, const uint32_t* a,
                                         uint32_t b0, uint32_t b1) {
    asm volatile(
        "mma.sync.aligned.m16n8k16.row.col.f32.bf16.bf16.f32 "
        "{%0,%1,%2,%3}, {%4,%5,%6,%7}, {%8,%9}, {%0,%1,%2,%3};"
        : "+f"(c[0]), "+f"(c[1]), "+f"(c[2]), "+f"(c[3])
        : "r"(a[0]), "r"(a[1]), "r"(a[2]), "r"(a[3]), "r"(b0), "r"(b1));
}

__device__ __forceinline__ float gelu_tanh(float x) {
    float x3 = x*x*x;
    return 0.5f*x*(1.0f + tanhf(0.7978845608028654f*(x + 0.044715f*x3)));
}
__device__ __forceinline__ void split_bf16(float x, __nv_bfloat16& hi, __nv_bfloat16& lo) {
    hi = __float2bfloat16(x);
    lo = __float2bfloat16(x - __bfloat162float(hi));
}

// SW128 swizzle base for a [rows][64 bf16] tile (128B rows):
// addr = base(row) ^ (chunk16B << 4)
__device__ __forceinline__ uint32_t swz128(int row) {
    return (uint32_t)(row*128) ^ (((uint32_t)row & 7u) << 4);
}

// (aoff,boff) in bf16 elements along the 2048-wide concatenated K for k-step ks
__device__ __forceinline__ void seg_off(int gemmid, int ks, int& aoff, int& boff) {
    if (gemmid == 0) {
        int seg = ks >> 4, ko = (ks & 15)*64;
        aoff = ko + (seg == 2 ? 1024 : 0);
        boff = ko + (seg == 1 ? 1024 : 0);
    } else {
        int seg = ks >> 3, ko = (ks & 7)*64;
        int sa, sb;
        switch (seg) {
            case 0:  sa = 0;    sb = 0;    break;
            case 1:  sa = 0;    sb = 512;  break;
            case 2:  sa = 512;  sb = 0;    break;
            case 3:  sa = 1024; sb = 1024; break;
            case 4:  sa = 1024; sb = 1536; break;
            default: sa = 1536; sb = 1024; break;
        }
        aoff = sa + ko; boff = sb + ko;
    }
}

// =======================================================================
//   bf16 mma.sync GEMM: C[M,N] = A[M,K'] @ B[N,K']^T (3-term bf16 split)
//   512 threads, warp grid 4x4, warp tile 32x64, BK=64, 3-stage cp.async
//   gemmid 0: N=3072 -> g_proj (+bias, gelu on first 2 projections)
//   gemmid 1: N=1024 -> out = 0.5*acc + bias2
// =======================================================================
__global__ __launch_bounds__(512, 1)
void gemm_tc(int gemmid, float* __restrict__ outp)
{
    extern __shared__ char smem[];
    const uint32_t sb = smem_u32(smem);
    const int tid = threadIdx.x;
    const int mbase = blockIdx.y * BM;
    const int nbase = blockIdx.x * BN;
    const __nv_bfloat16* __restrict__ Ap = gemmid ? g_a2 : g_a1;
    const __nv_bfloat16* __restrict__ Bp = gemmid ? g_w2 : g_w1;

    float acc[2][8][4];
    #pragma unroll
    for (int i = 0; i < 2; i++)
        #pragma unroll
        for (int j = 0; j < 8; j++)
            #pragma unroll
            for (int q = 0; q < 4; q++) acc[i][j][q] = 0.f;

    // ---- stage loader: A 128 rows x 8 chunks (1024 tasks = 2/thread),
    //                    B 256 rows x 8 chunks (2048 tasks = 4/thread) ----
    const int ldA_row0 = tid >> 3,        ldA_row1 = (tid + 512) >> 3;
    const int ldB_row0 = tid >> 3,        ldB_row1 = (tid + 512) >> 3;
    const int ldB_row2 = (tid + 1024) >> 3, ldB_row3 = (tid + 1536) >> 3;
    const int ld_ch = tid & 7;
    const uint32_t chx = (uint32_t)ld_ch << 4;
    const uint32_t sA0 = swz128(ldA_row0) ^ chx;
    const uint32_t sA1 = swz128(ldA_row1) ^ chx;
    const uint32_t sB0 = (uint32_t)(BM*128) + (swz128(ldB_row0) ^ chx);
    const uint32_t sB1 = (uint32_t)(BM*128) + (swz128(ldB_row1) ^ chx);
    const uint32_t sB2 = (uint32_t)(BM*128) + (swz128(ldB_row2) ^ chx);
    const uint32_t sB3 = (uint32_t)(BM*128) + (swz128(ldB_row3) ^ chx);

    auto load_stage = [&](uint32_t sst, int aoff, int boff) {
        cpasync16(sst + sA0, Ap + (size_t)(mbase + ldA_row0)*2048 + aoff + ld_ch*8);
        cpasync16(sst + sA1, Ap + (size_t)(mbase + ldA_row1)*2048 + aoff + ld_ch*8);
        cpasync16(sst + sB0, Bp + (size_t)(nbase + ldB_row0)*2048 + boff + ld_ch*8);
        cpasync16(sst + sB1, Bp + (size_t)(nbase + ldB_row1)*2048 + boff + ld_ch*8);
        cpasync16(sst + sB2, Bp + (size_t)(nbase + ldB_row2)*2048 + boff + ld_ch*8);
        cpasync16(sst + sB3, Bp + (size_t)(nbase + ldB_row3)*2048 + boff + ld_ch*8);
    };

    {   // prologue: stages 0,1
        int ao, bo;
        seg_off(gemmid, 0, ao, bo); load_stage(sb, ao, bo); CP_COMMIT();
        seg_off(gemmid, 1, ao, bo); load_stage(sb + STAGE_BYTES, ao, bo); CP_COMMIT();
    }

    const int lane = tid & 31, wid = tid >> 5;
    const int m0 = (wid & 3) * 32;       // 4 warps along M (32 rows each)
    const int n0 = (wid >> 2) * 64;      // 4 warps along N (64 cols each)

    // ldsm bases: addr = sS + (base ^ (kchunk<<4)); kchunk = 2*kt + (lane>>4)
    uint32_t aBase[2], bBase[4];
    #pragma unroll
    for (int mt = 0; mt < 2; mt++)
        aBase[mt] = swz128(m0 + mt*16 + (lane & 15));
    #pragma unroll
    for (int p = 0; p < 4; p++)
        bBase[p] = (uint32_t)(BM*128) + swz128(n0 + p*16 + (lane & 15));
    const uint32_t kqSel = (uint32_t)(lane >> 4) << 4;   // 0 or 16

    for (int ks = 0; ks < KSTEPS; ks++) {
        CP_WAIT1();
        __syncthreads();
        if (ks + 2 < KSTEPS) {
            int ao, bo; seg_off(gemmid, ks + 2, ao, bo);
            load_stage(sb + (uint32_t)(((ks + 2) % NSTAGES) * STAGE_BYTES), ao, bo);
        }
        CP_COMMIT();

        uint32_t sS = sb + (uint32_t)((ks % NSTAGES) * STAGE_BYTES);
        #pragma unroll
        for (int kt = 0; kt < 4; kt++) {
            uint32_t kx = ((uint32_t)(kt*2) << 4) ^ kqSel;
            uint32_t aF[2][4];
            ldsm4(aF[0], sS + (aBase[0] ^ kx));
            ldsm4(aF[1], sS + (aBase[1] ^ kx));
            #pragma unroll
            for (int p = 0; p < 4; p++) {
                uint32_t bF[4];
                ldsm4(bF, sS + (bBase[p] ^ kx));
                // bF: r0=(n-group 2p, klo) r1=(2p+1, klo) r2=(2p, khi) r3=(2p+1, khi)
                #pragma unroll
                for (int mt = 0; mt < 2; mt++) {
                    mma_bf16(acc[mt][2*p],   aF[mt], bF[0], bF[2]);
                    mma_bf16(acc[mt][2*p+1], aF[mt], bF[1], bF[3]);
                }
            }
        }
    }

    // ---- epilogue: registers -> global with bias / gelu / 0.5-avg ----
    const int r_lo  = mbase + m0 + (lane >> 2);
    const int cbase = nbase + n0 + (lane & 3)*2;
    #pragma unroll
    for (int mt = 0; mt < 2; mt++) {
        #pragma unroll
        for (int nt = 0; nt < 8; nt++) {
            int col = cbase + nt*8;
            int row0 = r_lo + mt*16;
            float v0 = acc[mt][nt][0], v1 = acc[mt][nt][1];
            float v2 = acc[mt][nt][2], v3 = acc[mt][nt][3];
            if (gemmid == 0) {
                float b0 = g_bias1[col], b1 = g_bias1[col+1];
                v0 += b0; v1 += b1; v2 += b0; v3 += b1;
                int proj = col >> 9, lc = col & 511;
                if (proj < 2) {
                    v0 = gelu_tanh(v0); v1 = gelu_tanh(v1);
                    v2 = gelu_tanh(v2); v3 = gelu_tanh(v3);
                }
                float* base = g_proj + (size_t)proj * ((size_t)RR*DD);
                *reinterpret_cast<float2*>(base + (size_t)row0*DD + lc)
                    = make_float2(v0, v1);
                *reinterpret_cast<float2*>(base + (size_t)(row0+8)*DD + lc)
                    = make_float2(v2, v3);
            } else {
                float b0 = g_bias2[col], b1 = g_bias2[col+1];
                *reinterpret_cast<float2*>(outp + (size_t)row0*1024 + col)
                    = make_float2(0.5f*v0 + b0, 0.5f*v1 + b1);
                *reinterpret_cast<float2*>(outp + (size_t)(row0+8)*1024 + col)
                    = make_float2(0.5f*v2 + b0, 0.5f*v3 + b1);
            }
        }
    }
}

// =======================================================================
//   conversion kernels (fp32 -> bf16 hi/lo splits)
// =======================================================================
__global__ void conv_a1(const float* __restrict__ query)
{
    size_t i = (size_t)blockIdx.x * 256 + threadIdx.x;   // 16384*1024
    int r = (int)(i >> 10), c = (int)(i & 1023);
    __nv_bfloat16 hi, lo;
    split_bf16(query[i], hi, lo);
    g_a1[(size_t)r*2048 + c]        = hi;
    g_a1[(size_t)r*2048 + 1024 + c] = lo;
}

__global__ void conv_w1(const float* __restrict__ w0, const float* __restrict__ w1,
                        const float* __restrict__ w2, const float* __restrict__ w3,
                        const float* __restrict__ w4, const float* __restrict__ w5)
{
    size_t i = (size_t)blockIdx.x * 256 + threadIdx.x;   // 3072*1024
    int n = (int)(i >> 10), k = (int)(i & 1023);
    int proj = n >> 9, rloc = n & 511;
    const float* src;
    switch (proj) {
        case 0: src = w0; break; case 1: src = w1; break; case 2: src = w2; break;
        case 3: src = w3; break; case 4: src = w4; break; default: src = w5; break;
    }
    __nv_bfloat16 hi, lo;
    split_bf16(src[(size_t)rloc*1024 + k], hi, lo);
    g_w1[(size_t)n*2048 + k]        = hi;
    g_w1[(size_t)n*2048 + 1024 + k] = lo;
}

__global__ void conv_w2(const float* __restrict__ wo_lin, const float* __restrict__ wo_loc)
{
    size_t i = (size_t)blockIdx.x * 256 + threadIdx.x;   // 1024*512
    int n = (int)(i >> 9), k = (int)(i & 511);
    __nv_bfloat16 hi, lo;
    split_bf16(wo_lin[(size_t)n*512 + k], hi, lo);
    g_w2[(size_t)n*2048 + k]       = hi;
    g_w2[(size_t)n*2048 + 512 + k] = lo;
    split_bf16(wo_loc[(size_t)n*512 + k], hi, lo);
    g_w2[(size_t)n*2048 + 1024 + k] = hi;
    g_w2[(size_t)n*2048 + 1536 + k] = lo;
}

__global__ void conv_bias(const float* __restrict__ b0, const float* __restrict__ b1,
                          const float* __restrict__ b2, const float* __restrict__ b3,
                          const float* __restrict__ b4, const float* __restrict__ b5,
                          const float* __restrict__ bo_lin, const float* __restrict__ bo_loc)
{
    int c = blockIdx.x * 256 + threadIdx.x;   // 3072
    int proj = c >> 9, lc = c & 511;
    const float* src;
    switch (proj) {
        case 0: src = b0; break; case 1: src = b1; break; case 2: src = b2; break;
        case 3: src = b3; break; case 4: src = b4; break; default: src = b5; break;
    }
    g_bias1[c] = src[lc];
    if (c < 1024) g_bias2[c] = 0.5f * (bo_lin[c] + bo_loc[c]);
}

// =======================================================================
//   attention kernels (fp32, chunk-local, smem resident)
// =======================================================================
__global__ __launch_bounds__(256)
void attn_local_kernel()
{
    __shared__ float qs[64][33];
    __shared__ float ks[64][33];
    __shared__ float vs[64][33];
    __shared__ float S [64][64];

    int z = blockIdx.x;
    int l = z & 63, h = (z >> 6) & 15, b = z >> 10;
    int tid = threadIdx.x;
    const float* Q = g_proj + (size_t)3*RR*DD;
    const float* K = g_proj + (size_t)4*RR*DD;
    const float* V = g_proj + (size_t)5*RR*DD;

    for (int idx = tid; idx < 64*32; idx += 256) {
        int c = idx >> 5, dh = idx & 31;
        size_t off = ((size_t)((l*64 + c)*BB + b))*DD + h*32 + dh;
        qs[c][dh] = Q[off]; ks[c][dh] = K[off]; vs[c][dh] = V[off];
    }
    __syncthreads();

    for (int idx = tid; idx < 64*64; idx += 256) {
        int c = idx >> 6, j = idx & 63;
        float s = 0.f;
        if (j <= c) {
            #pragma unroll
            for (int d = 0; d < 32; d++) s += qs[c][d]*ks[j][d];
            s = fmaxf(s, 0.f);
        }
        S[c][j] = s;
    }
    __syncthreads();

    for (int idx = tid; idx < 64*32; idx += 256) {
        int c = idx >> 5, dh = idx & 31;
        float o = 0.f;
        #pragma unroll
        for (int j = 0; j < 64; j++) o += S[c][j]*vs[j][dh];
        size_t off = ((size_t)((l*64 + c)*BB + b))*DD + h*32 + dh;
        g_oloc[off] = o;
    }
}

__global__ __launch_bounds__(256)
void attn_kv_kernel()
{
    __shared__ float ks[64][33];
    __shared__ float vs[64][33];

    int z = blockIdx.x;
    int l = z & 63, h = (z >> 6) & 15, b = z >> 10;
    int tid = threadIdx.x;
    const float* K = g_proj + (size_t)1*RR*DD;
    const float* V = g_proj + (size_t)2*RR*DD;

    for (int idx = tid; idx < 64*32; idx += 256) {
        int c = idx >> 5, dh = idx & 31;
        size_t off = ((size_t)((l*64 + c)*BB + b))*DD + h*32 + dh;
        ks[c][dh] = K[off]; vs[c][dh] = V[off];
    }
    __syncthreads();

    for (int idx = tid; idx < 32*32; idx += 256) {
        int d = idx >> 5, e = idx & 31;
        float s = 0.f;
        #pragma unroll
        for (int c = 0; c < 64; c++) s += ks[c][d]*vs[c][e];
        g_kv[(size_t)z*1024 + idx] = s;
    }
}

__global__ __launch_bounds__(256)
void kv_cumsum_kernel()
{
    int bh = blockIdx.x;
    const float* src = g_kv     + (size_t)bh*LL*1024;
    float*       dst = g_kvprev + (size_t)bh*LL*1024;
    for (int j = threadIdx.x; j < 1024; j += 256) {
        float acc = 0.f;
        #pragma unroll 4
        for (int l = 0; l < LL; l++) {
            dst[l*1024 + j] = acc;
            acc += src[l*1024 + j];
        }
    }
}

__global__ __launch_bounds__(256)
void attn_lin_kernel()
{
    __shared__ float qs [64][33];
    __shared__ float ks [64][33];
    __shared__ float vs [64][33];
    __shared__ float kvp[32][33];
    __shared__ float S  [64][64];

    int z = blockIdx.x;
    int l = z & 63, h = (z >> 6) & 15, b = z >> 10;
    int tid = threadIdx.x;
    const float* Q = g_proj;
    const float* K = g_proj + (size_t)1*RR*DD;
    const float* V = g_proj + (size_t)2*RR*DD;

    for (int idx = tid; idx < 64*32; idx += 256) {
        int c = idx >> 5, dh = idx & 31;
        size_t off = ((size_t)((l*64 + c)*BB + b))*DD + h*32 + dh;
        qs[c][dh] = Q[off]; ks[c][dh] = K[off]; vs[c][dh] = V[off];
    }
    for (int idx = tid; idx < 32*32; idx += 256)
        kvp[idx >> 5][idx & 31] = g_kvprev[(size_t)z*1024 + idx];
    __syncthreads();

    for (int idx = tid; idx < 64*64; idx += 256) {
        int c = idx >> 6, j = idx & 63;
        float s = 0.f;
        if (j <= c) {
            #pragma unroll
            for (int d = 0; d < 32; d++) s += qs[c][d]*ks[j][d];
        }
        S[c][j] = s;
    }
    __syncthreads();

    for (int idx = tid; idx < 64*32; idx += 256) {
        int c = idx >> 5, dh = idx & 31;
        float o = 0.f;
        #pragma unroll
        for (int j = 0; j < 64; j++) o += S[c][j]*vs[j][dh];
        #pragma unroll
        for (int d = 0; d < 32; d++) o += qs[c][d]*kvp[d][dh];
        size_t off = ((size_t)((l*64 + c)*BB + b))*DD + h*32 + dh;
        g_olin[off] = o;
    }
}

// ---------------- norms -> bf16 hi/lo splits into g_a2 ----------------
__device__ __forceinline__ float block_sum256(float v, float* sbuf) {
    int tid = threadIdx.x;
    #pragma unroll
    for (int o = 16; o > 0; o >>= 1) v += __shfl_xor_sync(0xffffffffu, v, o);
    __syncthreads();
    if ((tid & 31) == 0) sbuf[tid >> 5] = v;
    __syncthreads();
    float t = sbuf[0];
    #pragma unroll
    for (int w = 1; w < 8; w++) t += sbuf[w];
    return t;
}

__global__ __launch_bounds__(256)
void norm_kernel(const float* __restrict__ ln_g, const float* __restrict__ ln_b,
                 const float* __restrict__ gsc,  const float* __restrict__ ggt)
{
    __shared__ float sbuf[8];
    int r = blockIdx.x, tid = threadIdx.x;
    __nv_bfloat16* a2 = g_a2 + (size_t)r*2048;

    // LayerNorm over D=512
    const float* xl = g_olin + (size_t)r*DD;
    float a0 = xl[tid], a1 = xl[tid + 256];
    float mu = block_sum256(a0 + a1, sbuf) * (1.0f/512.0f);
    float d0 = a0 - mu, d1 = a1 - mu;
    float var = block_sum256(d0*d0 + d1*d1, sbuf) * (1.0f/512.0f);
    float rs = rsqrtf(var + 1e-5f);
    float y0 = d0*rs*ln_g[tid      ] + ln_b[tid      ];
    float y1 = d1*rs*ln_g[tid + 256] + ln_b[tid + 256];
    __nv_bfloat16 hi, lo;
    split_bf16(y0, hi, lo); a2[tid      ] = hi; a2[512 + tid      ] = lo;
    split_bf16(y1, hi, lo); a2[tid + 256] = hi; a2[512 + tid + 256] = lo;

    // gated RMSNorm
    const float* xo = g_oloc + (size_t)r*DD;
    float b0 = xo[tid], b1 = xo[tid + 256];
    float ms = block_sum256(b0*b0 + b1*b1, sbuf) * (1.0f/512.0f);
    float inv = rsqrtf(ms + 1e-8f);
    float s0 = 1.0f/(1.0f + expf(-ggt[tid      ]*b0));
    float s1 = 1.0f/(1.0f + expf(-ggt[tid + 256]*b1));
    float z0 = b0*inv*gsc[tid      ]*s0;
    float z1 = b1*inv*gsc[tid + 256]*s1;
    split_bf16(z0, hi, lo); a2[1024 + tid      ] = hi; a2[1536 + tid      ] = lo;
    split_bf16(z1, hi, lo); a2[1024 + tid + 256] = hi; a2[1536 + tid + 256] = lo;
}

// =======================================================================
//   launch  (gemm0 at launch idx 3 so ncu's skip lands on it)
// =======================================================================
extern "C" void kernel_launch(void* const* d_in, const int* in_sizes, int n_in,
                              void* d_out, int out_size)
{
    const float* query   = (const float*)d_in[0];
    const float* wq_lin  = (const float*)d_in[1];
    const float* bq_lin  = (const float*)d_in[2];
    const float* wk_lin  = (const float*)d_in[3];
    const float* bk_lin  = (const float*)d_in[4];
    const float* wv_lin  = (const float*)d_in[5];
    const float* bv_lin  = (const float*)d_in[6];
    const float* wo_lin  = (const float*)d_in[7];
    const float* bo_lin  = (const float*)d_in[8];
    const float* wq_loc  = (const float*)d_in[9];
    const float* bq_loc  = (const float*)d_in[10];
    const float* wk_loc  = (const float*)d_in[11];
    const float* bk_loc  = (const float*)d_in[12];
    const float* wv_loc  = (const float*)d_in[13];
    const float* bv_loc  = (const float*)d_in[14];
    const float* wo_loc  = (const float*)d_in[15];
    const float* bo_loc  = (const float*)d_in[16];
    const float* ln_g    = (const float*)d_in[17];
    const float* ln_b    = (const float*)d_in[18];
    const float* grn_s   = (const float*)d_in[19];
    const float* grn_g   = (const float*)d_in[20];
    float* out = (float*)d_out;

    cudaFuncSetAttribute(gemm_tc, cudaFuncAttributeMaxDynamicSharedMemorySize, SMEM_GEMM);

    // conversions needed by gemm0 first
    conv_bias<<<3072/256, 256>>>(bq_lin, bk_lin, bv_lin, bq_loc, bk_loc, bv_loc, bo_lin, bo_loc);
    conv_a1  <<<(RR*1024)/256, 256>>>(query);
    conv_w1  <<<(3072*1024)/256, 256>>>(wq_lin, wk_lin, wv_lin, wq_loc, wk_loc, wv_loc);

    // fused input projections (6-in-1), bf16 tensor cores   [launch idx 3]
    gemm_tc<<<dim3(3072/BN, RR/BM), 512, SMEM_GEMM>>>(0, nullptr);

    conv_w2  <<<(1024*512)/256, 256>>>(wo_lin, wo_loc);

    // attention
    attn_local_kernel<<<BB*HH*LL, 256>>>();
    attn_kv_kernel   <<<BB*HH*LL, 256>>>();
    kv_cumsum_kernel <<<BB*HH,    256>>>();
    attn_lin_kernel  <<<BB*HH*LL, 256>>>();

    // norms (emit bf16 hi/lo operands for the output GEMM)
    norm_kernel<<<RR, 256>>>(ln_g, ln_b, grn_s, grn_g);

    // fused output projections (2-in-1), writes d_out
    gemm_tc<<<dim3(1024/BN, RR/BM), 512, SMEM_GEMM>>>(1, out);
}

// round 7
// speedup vs baseline: 2.6070x; 1.1058x over previous
#include <cuda_runtime.h>
#include <cuda_bf16.h>
#include <stdint.h>
#include <math.h>

// ---------------- problem constants ----------------
#define NN 4096
#define BB 4
#define EE 1024
#define HH 16
#define DD 512
#define DH 32
#define LL 64
#define RR (NN*BB)   // 16384 rows

// ---------------- gemm geometry ----------------
#define BM 128
#define BN 256
#define BK 64                       // bf16 elems per k-step (128 bytes per row)
#define KSTEPS 48                   // both gemms: K' = 3072
#define STAGE_BYTES ((BM+BN)*128)   // 49152
#define NSTAGES 3
#define SMEM_GEMM (NSTAGES*STAGE_BYTES)  // 147456

// ---------------- device scratch ----------------
__device__ __nv_bfloat16 g_a1[(size_t)RR*2048];      // [query_hi | query_lo]
__device__ __nv_bfloat16 g_w1[(size_t)3072*2048];    // 6 proj weights; cols [hi|lo]
__device__ __nv_bfloat16 g_a2[(size_t)RR*2048];      // [ln_hi | ln_lo | grn_hi | grn_lo]
__device__ __nv_bfloat16 g_w2[(size_t)1024*2048];    // [wol_hi | wol_lo | woc_hi | woc_lo]
__device__ float g_bias1[3072];
__device__ float g_bias2[1024];
__device__ float g_proj[(size_t)6*RR*DD];            // q_lin,k_lin,v_lin,q_loc,k_loc,v_loc
__device__ float g_olin[(size_t)RR*DD];
__device__ float g_oloc[(size_t)RR*DD];
__device__ float g_kv    [(size_t)BB*HH*LL*DH*DH];
__device__ float g_kvprev[(size_t)BB*HH*LL*DH*DH];

// ---------------- asm helpers (base sm_80-era; no 'a' features) ----------
__device__ __forceinline__ uint32_t smem_u32(const void* p) {
    uint32_t a;
    asm("{ .reg .u64 t; cvta.to.shared.u64 t, %1; cvt.u32.u64 %0, t; }" : "=r"(a) : "l"(p));
    return a;
}
__device__ __forceinline__ void cpasync16(uint32_t s, const void* g) {
    asm volatile("cp.async.cg.shared.global [%0], [%1], 16;" :: "r"(s), "l"(g));
}
#define CP_COMMIT() asm volatile("cp.async.commit_group;" ::: "memory")
#define CP_WAIT1()  asm volatile("cp.async.wait_group 1;"  ::: "memory")

__device__ __forceinline__ void ldsm4(uint32_t* r, uint32_t addr) {
    asm volatile("ldmatrix.sync.aligned.m8n8.x4.shared.b16 {%0,%1,%2,%3}, [%4];"
        : "=r"(r[0]), "=r"(r[1]), "=r"(r[2]), "=r"(r[3]) : "r"(addr));
}
__device__ __forceinline__ void mma_bf16(float* c, const uint32_t* a,
                                         uint32_t b0, uint32_t b1) {
    asm volatile(
        "mma.sync.aligned.m16n8k16.row.col.f32.bf16.bf16.f32 "
        "{%0,%1,%2,%3}, {%4,%5,%6,%7}, {%8,%9}, {%0,%1,%2,%3};"
        : "+f"(c[0]), "+f"(c[1]), "+f"(c[2]), "+f"(c[3])
        : "r"(a[0]), "r"(a[1]), "r"(a[2]), "r"(a[3]), "r"(b0), "r"(b1));
}

__device__ __forceinline__ float gelu_tanh(float x) {
    float x3 = x*x*x;
    return 0.5f*x*(1.0f + tanhf(0.7978845608028654f*(x + 0.044715f*x3)));
}
__device__ __forceinline__ void split_bf16(float x, __nv_bfloat16& hi, __nv_bfloat16& lo) {
    hi = __float2bfloat16(x);
    lo = __float2bfloat16(x - __bfloat162float(hi));
}

// SW128 swizzle base for a [rows][64 bf16] tile (128B rows)
__device__ __forceinline__ uint32_t swz128(int row) {
    return (uint32_t)(row*128) ^ (((uint32_t)row & 7u) << 4);
}

// (aoff,boff) in bf16 elements along the 2048-wide concatenated K for k-step ks
__device__ __forceinline__ void seg_off(int gemmid, int ks, int& aoff, int& boff) {
    if (gemmid == 0) {
        int seg = ks >> 4, ko = (ks & 15)*64;
        aoff = ko + (seg == 2 ? 1024 : 0);
        boff = ko + (seg == 1 ? 1024 : 0);
    } else {
        int seg = ks >> 3, ko = (ks & 7)*64;
        int sa, sb;
        switch (seg) {
            case 0:  sa = 0;    sb = 0;    break;
            case 1:  sa = 0;    sb = 512;  break;
            case 2:  sa = 512;  sb = 0;    break;
            case 3:  sa = 1024; sb = 1024; break;
            case 4:  sa = 1024; sb = 1536; break;
            default: sa = 1536; sb = 1024; break;
        }
        aoff = sa + ko; boff = sb + ko;
    }
}

// =======================================================================
//   bf16 mma.sync GEMM (unchanged from R6)
// =======================================================================
__global__ __launch_bounds__(512, 1)
void gemm_tc(int gemmid, float* __restrict__ outp)
{
    extern __shared__ char smem[];
    const uint32_t sb = smem_u32(smem);
    const int tid = threadIdx.x;
    const int mbase = blockIdx.y * BM;
    const int nbase = blockIdx.x * BN;
    const __nv_bfloat16* __restrict__ Ap = gemmid ? g_a2 : g_a1;
    const __nv_bfloat16* __restrict__ Bp = gemmid ? g_w2 : g_w1;

    float acc[2][8][4];
    #pragma unroll
    for (int i = 0; i < 2; i++)
        #pragma unroll
        for (int j = 0; j < 8; j++)
            #pragma unroll
            for (int q = 0; q < 4; q++) acc[i][j][q] = 0.f;

    const int ldA_row0 = tid >> 3,          ldA_row1 = (tid + 512) >> 3;
    const int ldB_row0 = tid >> 3,          ldB_row1 = (tid + 512) >> 3;
    const int ldB_row2 = (tid + 1024) >> 3, ldB_row3 = (tid + 1536) >> 3;
    const int ld_ch = tid & 7;
    const uint32_t chx = (uint32_t)ld_ch << 4;
    const uint32_t sA0 = swz128(ldA_row0) ^ chx;
    const uint32_t sA1 = swz128(ldA_row1) ^ chx;
    const uint32_t sB0 = (uint32_t)(BM*128) + (swz128(ldB_row0) ^ chx);
    const uint32_t sB1 = (uint32_t)(BM*128) + (swz128(ldB_row1) ^ chx);
    const uint32_t sB2 = (uint32_t)(BM*128) + (swz128(ldB_row2) ^ chx);
    const uint32_t sB3 = (uint32_t)(BM*128) + (swz128(ldB_row3) ^ chx);

    auto load_stage = [&](uint32_t sst, int aoff, int boff) {
        cpasync16(sst + sA0, Ap + (size_t)(mbase + ldA_row0)*2048 + aoff + ld_ch*8);
        cpasync16(sst + sA1, Ap + (size_t)(mbase + ldA_row1)*2048 + aoff + ld_ch*8);
        cpasync16(sst + sB0, Bp + (size_t)(nbase + ldB_row0)*2048 + boff + ld_ch*8);
        cpasync16(sst + sB1, Bp + (size_t)(nbase + ldB_row1)*2048 + boff + ld_ch*8);
        cpasync16(sst + sB2, Bp + (size_t)(nbase + ldB_row2)*2048 + boff + ld_ch*8);
        cpasync16(sst + sB3, Bp + (size_t)(nbase + ldB_row3)*2048 + boff + ld_ch*8);
    };

    {
        int ao, bo;
        seg_off(gemmid, 0, ao, bo); load_stage(sb, ao, bo); CP_COMMIT();
        seg_off(gemmid, 1, ao, bo); load_stage(sb + STAGE_BYTES, ao, bo); CP_COMMIT();
    }

    const int lane = tid & 31, wid = tid >> 5;
    const int m0 = (wid & 3) * 32;
    const int n0 = (wid >> 2) * 64;

    uint32_t aBase[2], bBase[4];
    #pragma unroll
    for (int mt = 0; mt < 2; mt++)
        aBase[mt] = swz128(m0 + mt*16 + (lane & 15));
    #pragma unroll
    for (int p = 0; p < 4; p++)
        bBase[p] = (uint32_t)(BM*128) + swz128(n0 + p*16 + (lane & 15));
    const uint32_t kqSel = (uint32_t)(lane >> 4) << 4;

    for (int ks = 0; ks < KSTEPS; ks++) {
        CP_WAIT1();
        __syncthreads();
        if (ks + 2 < KSTEPS) {
            int ao, bo; seg_off(gemmid, ks + 2, ao, bo);
            load_stage(sb + (uint32_t)(((ks + 2) % NSTAGES) * STAGE_BYTES), ao, bo);
        }
        CP_COMMIT();

        uint32_t sS = sb + (uint32_t)((ks % NSTAGES) * STAGE_BYTES);
        #pragma unroll
        for (int kt = 0; kt < 4; kt++) {
            uint32_t kx = ((uint32_t)(kt*2) << 4) ^ kqSel;
            uint32_t aF[2][4];
            ldsm4(aF[0], sS + (aBase[0] ^ kx));
            ldsm4(aF[1], sS + (aBase[1] ^ kx));
            #pragma unroll
            for (int p = 0; p < 4; p++) {
                uint32_t bF[4];
                ldsm4(bF, sS + (bBase[p] ^ kx));
                #pragma unroll
                for (int mt = 0; mt < 2; mt++) {
                    mma_bf16(acc[mt][2*p],   aF[mt], bF[0], bF[2]);
                    mma_bf16(acc[mt][2*p+1], aF[mt], bF[1], bF[3]);
                }
            }
        }
    }

    const int r_lo  = mbase + m0 + (lane >> 2);
    const int cbase = nbase + n0 + (lane & 3)*2;
    #pragma unroll
    for (int mt = 0; mt < 2; mt++) {
        #pragma unroll
        for (int nt = 0; nt < 8; nt++) {
            int col = cbase + nt*8;
            int row0 = r_lo + mt*16;
            float v0 = acc[mt][nt][0], v1 = acc[mt][nt][1];
            float v2 = acc[mt][nt][2], v3 = acc[mt][nt][3];
            if (gemmid == 0) {
                float b0 = g_bias1[col], b1 = g_bias1[col+1];
                v0 += b0; v1 += b1; v2 += b0; v3 += b1;
                int proj = col >> 9, lc = col & 511;
                if (proj < 2) {
                    v0 = gelu_tanh(v0); v1 = gelu_tanh(v1);
                    v2 = gelu_tanh(v2); v3 = gelu_tanh(v3);
                }
                float* base = g_proj + (size_t)proj * ((size_t)RR*DD);
                *reinterpret_cast<float2*>(base + (size_t)row0*DD + lc)
                    = make_float2(v0, v1);
                *reinterpret_cast<float2*>(base + (size_t)(row0+8)*DD + lc)
                    = make_float2(v2, v3);
            } else {
                float b0 = g_bias2[col], b1 = g_bias2[col+1];
                *reinterpret_cast<float2*>(outp + (size_t)row0*1024 + col)
                    = make_float2(0.5f*v0 + b0, 0.5f*v1 + b1);
                *reinterpret_cast<float2*>(outp + (size_t)(row0+8)*1024 + col)
                    = make_float2(0.5f*v2 + b0, 0.5f*v3 + b1);
            }
        }
    }
}

// =======================================================================
//   conversion kernels (fp32 -> bf16 hi/lo splits)
// =======================================================================
__global__ void conv_a1(const float* __restrict__ query)
{
    size_t i = (size_t)blockIdx.x * 256 + threadIdx.x;
    int r = (int)(i >> 10), c = (int)(i & 1023);
    __nv_bfloat16 hi, lo;
    split_bf16(query[i], hi, lo);
    g_a1[(size_t)r*2048 + c]        = hi;
    g_a1[(size_t)r*2048 + 1024 + c] = lo;
}

__global__ void conv_w1(const float* __restrict__ w0, const float* __restrict__ w1,
                        const float* __restrict__ w2, const float* __restrict__ w3,
                        const float* __restrict__ w4, const float* __restrict__ w5)
{
    size_t i = (size_t)blockIdx.x * 256 + threadIdx.x;
    int n = (int)(i >> 10), k = (int)(i & 1023);
    int proj = n >> 9, rloc = n & 511;
    const float* src;
    switch (proj) {
        case 0: src = w0; break; case 1: src = w1; break; case 2: src = w2; break;
        case 3: src = w3; break; case 4: src = w4; break; default: src = w5; break;
    }
    __nv_bfloat16 hi, lo;
    split_bf16(src[(size_t)rloc*1024 + k], hi, lo);
    g_w1[(size_t)n*2048 + k]        = hi;
    g_w1[(size_t)n*2048 + 1024 + k] = lo;
}

__global__ void conv_w2(const float* __restrict__ wo_lin, const float* __restrict__ wo_loc)
{
    size_t i = (size_t)blockIdx.x * 256 + threadIdx.x;
    int n = (int)(i >> 9), k = (int)(i & 511);
    __nv_bfloat16 hi, lo;
    split_bf16(wo_lin[(size_t)n*512 + k], hi, lo);
    g_w2[(size_t)n*2048 + k]       = hi;
    g_w2[(size_t)n*2048 + 512 + k] = lo;
    split_bf16(wo_loc[(size_t)n*512 + k], hi, lo);
    g_w2[(size_t)n*2048 + 1024 + k] = hi;
    g_w2[(size_t)n*2048 + 1536 + k] = lo;
}

__global__ void conv_bias(const float* __restrict__ b0, const float* __restrict__ b1,
                          const float* __restrict__ b2, const float* __restrict__ b3,
                          const float* __restrict__ b4, const float* __restrict__ b5,
                          const float* __restrict__ bo_lin, const float* __restrict__ bo_loc)
{
    int c = blockIdx.x * 256 + threadIdx.x;
    int proj = c >> 9, lc = c & 511;
    const float* src;
    switch (proj) {
        case 0: src = b0; break; case 1: src = b1; break; case 2: src = b2; break;
        case 3: src = b3; break; case 4: src = b4; break; default: src = b5; break;
    }
    g_bias1[c] = src[lc];
    if (c < 1024) g_bias2[c] = 0.5f * (bo_lin[c] + bo_loc[c]);
}

// =======================================================================
//   attention kernels — register-tiled (4x4 S-tiles, 4x2 O-tiles)
// =======================================================================
__global__ __launch_bounds__(256)
void attn_local_kernel()
{
    __shared__ float qs[64][33];
    __shared__ float ks[64][33];
    __shared__ float vs[64][33];
    __shared__ float S [64][65];

    int z = blockIdx.x;
    int l = z & 63, h = (z >> 6) & 15, b = z >> 10;
    int tid = threadIdx.x;
    const float* Q = g_proj + (size_t)3*RR*DD;
    const float* K = g_proj + (size_t)4*RR*DD;
    const float* V = g_proj + (size_t)5*RR*DD;

    for (int idx = tid; idx < 64*32; idx += 256) {
        int c = idx >> 5, dh = idx & 31;
        size_t off = ((size_t)((l*64 + c)*BB + b))*DD + h*32 + dh;
        qs[c][dh] = Q[off]; ks[c][dh] = K[off]; vs[c][dh] = V[off];
    }
    __syncthreads();

    // ---- S = relu(q k^T) * tril : 4x4 tile per thread ----
    {
        int tr = tid >> 4, tc = tid & 15;      // c-group, j-group
        int c0 = tr*4, j0 = tc*4;
        float s[4][4] = {{0.f}};
        if (tc <= tr) {                         // tile touches causal region
            #pragma unroll 8
            for (int d = 0; d < 32; d++) {
                float rq[4], rk[4];
                #pragma unroll
                for (int i = 0; i < 4; i++) rq[i] = qs[c0+i][d];
                #pragma unroll
                for (int j = 0; j < 4; j++) rk[j] = ks[j0+j][d];
                #pragma unroll
                for (int i = 0; i < 4; i++)
                    #pragma unroll
                    for (int j = 0; j < 4; j++)
                        s[i][j] += rq[i]*rk[j];
            }
        }
        #pragma unroll
        for (int i = 0; i < 4; i++)
            #pragma unroll
            for (int j = 0; j < 4; j++) {
                float v = (j0+j <= c0+i) ? fmaxf(s[i][j], 0.f) : 0.f;
                S[c0+i][j0+j] = v;
            }
    }
    __syncthreads();

    // ---- O = S @ v : 4x2 tile per thread ----
    {
        int cg = tid >> 4, dg = tid & 15;
        int c0 = cg*4, dh0 = dg*2;
        float o[4][2] = {{0.f}};
        #pragma unroll 8
        for (int j = 0; j < 64; j++) {
            float v0 = vs[j][dh0], v1 = vs[j][dh0+1];
            #pragma unroll
            for (int i = 0; i < 4; i++) {
                float sv = S[c0+i][j];
                o[i][0] += sv*v0; o[i][1] += sv*v1;
            }
        }
        #pragma unroll
        for (int i = 0; i < 4; i++) {
            size_t off = ((size_t)((l*64 + c0+i)*BB + b))*DD + h*32 + dh0;
            *reinterpret_cast<float2*>(g_oloc + off) = make_float2(o[i][0], o[i][1]);
        }
    }
}

__global__ __launch_bounds__(256)
void attn_kv_kernel()
{
    __shared__ float ks[64][33];
    __shared__ float vs[64][33];

    int z = blockIdx.x;
    int l = z & 63, h = (z >> 6) & 15, b = z >> 10;
    int tid = threadIdx.x;
    const float* K = g_proj + (size_t)1*RR*DD;
    const float* V = g_proj + (size_t)2*RR*DD;

    for (int idx = tid; idx < 64*32; idx += 256) {
        int c = idx >> 5, dh = idx & 31;
        size_t off = ((size_t)((l*64 + c)*BB + b))*DD + h*32 + dh;
        ks[c][dh] = K[off]; vs[c][dh] = V[off];
    }
    __syncthreads();

    // kv[d][e] = sum_c k[c][d] v[c][e] : 2x2 tile per thread
    int d0 = (tid >> 4)*2, e0 = (tid & 15)*2;
    float s[2][2] = {{0.f}};
    #pragma unroll 8
    for (int c = 0; c < 64; c++) {
        float k0 = ks[c][d0], k1 = ks[c][d0+1];
        float v0 = vs[c][e0], v1 = vs[c][e0+1];
        s[0][0] += k0*v0; s[0][1] += k0*v1;
        s[1][0] += k1*v0; s[1][1] += k1*v1;
    }
    float* dst = g_kv + (size_t)z*1024;
    *reinterpret_cast<float2*>(dst + (d0  )*32 + e0) = make_float2(s[0][0], s[0][1]);
    *reinterpret_cast<float2*>(dst + (d0+1)*32 + e0) = make_float2(s[1][0], s[1][1]);
}

__global__ __launch_bounds__(256)
void kv_cumsum_kernel()
{
    int bh = blockIdx.x;
    const float* src = g_kv     + (size_t)bh*LL*1024;
    float*       dst = g_kvprev + (size_t)bh*LL*1024;
    for (int j = threadIdx.x; j < 1024; j += 256) {
        float acc = 0.f;
        #pragma unroll 4
        for (int l = 0; l < LL; l++) {
            dst[l*1024 + j] = acc;
            acc += src[l*1024 + j];
        }
    }
}

__global__ __launch_bounds__(256)
void attn_lin_kernel()
{
    __shared__ float qs [64][33];
    __shared__ float ks [64][33];
    __shared__ float vs [64][33];
    __shared__ float kvp[32][33];
    __shared__ float S  [64][65];

    int z = blockIdx.x;
    int l = z & 63, h = (z >> 6) & 15, b = z >> 10;
    int tid = threadIdx.x;
    const float* Q = g_proj;
    const float* K = g_proj + (size_t)1*RR*DD;
    const float* V = g_proj + (size_t)2*RR*DD;

    for (int idx = tid; idx < 64*32; idx += 256) {
        int c = idx >> 5, dh = idx & 31;
        size_t off = ((size_t)((l*64 + c)*BB + b))*DD + h*32 + dh;
        qs[c][dh] = Q[off]; ks[c][dh] = K[off]; vs[c][dh] = V[off];
    }
    for (int idx = tid; idx < 32*32; idx += 256)
        kvp[idx >> 5][idx & 31] = g_kvprev[(size_t)z*1024 + idx];
    __syncthreads();

    // ---- S = (q k^T) * tril : 4x4 tile per thread ----
    {
        int tr = tid >> 4, tc = tid & 15;
        int c0 = tr*4, j0 = tc*4;
        float s[4][4] = {{0.f}};
        if (tc <= tr) {
            #pragma unroll 8
            for (int d = 0; d < 32; d++) {
                float rq[4], rk[4];
                #pragma unroll
                for (int i = 0; i < 4; i++) rq[i] = qs[c0+i][d];
                #pragma unroll
                for (int j = 0; j < 4; j++) rk[j] = ks[j0+j][d];
                #pragma unroll
                for (int i = 0; i < 4; i++)
                    #pragma unroll
                    for (int j = 0; j < 4; j++)
                        s[i][j] += rq[i]*rk[j];
            }
        }
        #pragma unroll
        for (int i = 0; i < 4; i++)
            #pragma unroll
            for (int j = 0; j < 4; j++)
                S[c0+i][j0+j] = (j0+j <= c0+i) ? s[i][j] : 0.f;
    }
    __syncthreads();

    // ---- O = S @ v + q @ kv_prev : 4x2 tile per thread ----
    {
        int cg = tid >> 4, dg = tid & 15;
        int c0 = cg*4, dh0 = dg*2;
        float o[4][2] = {{0.f}};
        #pragma unroll 8
        for (int j = 0; j < 64; j++) {
            float v0 = vs[j][dh0], v1 = vs[j][dh0+1];
            #pragma unroll
            for (int i = 0; i < 4; i++) {
                float sv = S[c0+i][j];
                o[i][0] += sv*v0; o[i][1] += sv*v1;
            }
        }
        #pragma unroll 8
        for (int d = 0; d < 32; d++) {
            float p0 = kvp[d][dh0], p1 = kvp[d][dh0+1];
            #pragma unroll
            for (int i = 0; i < 4; i++) {
                float qv = qs[c0+i][d];
                o[i][0] += qv*p0; o[i][1] += qv*p1;
            }
        }
        #pragma unroll
        for (int i = 0; i < 4; i++) {
            size_t off = ((size_t)((l*64 + c0+i)*BB + b))*DD + h*32 + dh0;
            *reinterpret_cast<float2*>(g_olin + off) = make_float2(o[i][0], o[i][1]);
        }
    }
}

// ---------------- norms -> bf16 hi/lo splits into g_a2 ----------------
__device__ __forceinline__ float block_sum256(float v, float* sbuf) {
    int tid = threadIdx.x;
    #pragma unroll
    for (int o = 16; o > 0; o >>= 1) v += __shfl_xor_sync(0xffffffffu, v, o);
    __syncthreads();
    if ((tid & 31) == 0) sbuf[tid >> 5] = v;
    __syncthreads();
    float t = sbuf[0];
    #pragma unroll
    for (int w = 1; w < 8; w++) t += sbuf[w];
    return t;
}

__global__ __launch_bounds__(256)
void norm_kernel(const float* __restrict__ ln_g, const float* __restrict__ ln_b,
                 const float* __restrict__ gsc,  const float* __restrict__ ggt)
{
    __shared__ float sbuf[8];
    int r = blockIdx.x, tid = threadIdx.x;
    __nv_bfloat16* a2 = g_a2 + (size_t)r*2048;

    const float* xl = g_olin + (size_t)r*DD;
    float a0 = xl[tid], a1 = xl[tid + 256];
    float mu = block_sum256(a0 + a1, sbuf) * (1.0f/512.0f);
    float d0 = a0 - mu, d1 = a1 - mu;
    float var = block_sum256(d0*d0 + d1*d1, sbuf) * (1.0f/512.0f);
    float rs = rsqrtf(var + 1e-5f);
    float y0 = d0*rs*ln_g[tid      ] + ln_b[tid      ];
    float y1 = d1*rs*ln_g[tid + 256] + ln_b[tid + 256];
    __nv_bfloat16 hi, lo;
    split_bf16(y0, hi, lo); a2[tid      ] = hi; a2[512 + tid      ] = lo;
    split_bf16(y1, hi, lo); a2[tid + 256] = hi; a2[512 + tid + 256] = lo;

    const float* xo = g_oloc + (size_t)r*DD;
    float b0 = xo[tid], b1 = xo[tid + 256];
    float ms = block_sum256(b0*b0 + b1*b1, sbuf) * (1.0f/512.0f);
    float inv = rsqrtf(ms + 1e-8f);
    float s0 = 1.0f/(1.0f + expf(-ggt[tid      ]*b0));
    float s1 = 1.0f/(1.0f + expf(-ggt[tid + 256]*b1));
    float z0 = b0*inv*gsc[tid      ]*s0;
    float z1 = b1*inv*gsc[tid + 256]*s1;
    split_bf16(z0, hi, lo); a2[1024 + tid      ] = hi; a2[1536 + tid      ] = lo;
    split_bf16(z1, hi, lo); a2[1024 + tid + 256] = hi; a2[1536 + tid + 256] = lo;
}

// =======================================================================
//   launch
// =======================================================================
extern "C" void kernel_launch(void* const* d_in, const int* in_sizes, int n_in,
                              void* d_out, int out_size)
{
    const float* query   = (const float*)d_in[0];
    const float* wq_lin  = (const float*)d_in[1];
    const float* bq_lin  = (const float*)d_in[2];
    const float* wk_lin  = (const float*)d_in[3];
    const float* bk_lin  = (const float*)d_in[4];
    const float* wv_lin  = (const float*)d_in[5];
    const float* bv_lin  = (const float*)d_in[6];
    const float* wo_lin  = (const float*)d_in[7];
    const float* bo_lin  = (const float*)d_in[8];
    const float* wq_loc  = (const float*)d_in[9];
    const float* bq_loc  = (const float*)d_in[10];
    const float* wk_loc  = (const float*)d_in[11];
    const float* bk_loc  = (const float*)d_in[12];
    const float* wv_loc  = (const float*)d_in[13];
    const float* bv_loc  = (const float*)d_in[14];
    const float* wo_loc  = (const float*)d_in[15];
    const float* bo_loc  = (const float*)d_in[16];
    const float* ln_g    = (const float*)d_in[17];
    const float* ln_b    = (const float*)d_in[18];
    const float* grn_s   = (const float*)d_in[19];
    const float* grn_g   = (const float*)d_in[20];
    float* out = (float*)d_out;

    cudaFuncSetAttribute(gemm_tc, cudaFuncAttributeMaxDynamicSharedMemorySize, SMEM_GEMM);

    conv_bias<<<3072/256, 256>>>(bq_lin, bk_lin, bv_lin, bq_loc, bk_loc, bv_loc, bo_lin, bo_loc);
    conv_a1  <<<(RR*1024)/256, 256>>>(query);
    conv_w1  <<<(3072*1024)/256, 256>>>(wq_lin, wk_lin, wv_lin, wq_loc, wk_loc, wv_loc);

    // fused input projections (6-in-1)   [launch idx 3]
    gemm_tc<<<dim3(3072/BN, RR/BM), 512, SMEM_GEMM>>>(0, nullptr);

    conv_w2  <<<(1024*512)/256, 256>>>(wo_lin, wo_loc);

    // attention (register-tiled)
    attn_local_kernel<<<BB*HH*LL, 256>>>();
    attn_kv_kernel   <<<BB*HH*LL, 256>>>();
    kv_cumsum_kernel <<<BB*HH,    256>>>();
    attn_lin_kernel  <<<BB*HH*LL, 256>>>();

    // norms (emit bf16 hi/lo operands for the output GEMM)
    norm_kernel<<<RR, 256>>>(ln_g, ln_b, grn_s, grn_g);

    // fused output projections (2-in-1)
    gemm_tc<<<dim3(1024/BN, RR/BM), 512, SMEM_GEMM>>>(1, out);
}

// round 8
// speedup vs baseline: 2.7419x; 1.0517x over previous
#include <cuda_runtime.h>
#include <cuda_bf16.h>
#include <stdint.h>
#include <math.h>

// ---------------- problem constants ----------------
#define NN 4096
#define BB 4
#define EE 1024
#define HH 16
#define DD 512
#define DH 32
#define LL 64
#define RR (NN*BB)   // 16384 rows

// ---------------- gemm geometry ----------------
#define BM 128
#define BN 256
#define BK 64                       // bf16 elems per k-step (128 bytes per row)
#define KSTEPS 48                   // both gemms: K' = 3072
#define STAGE_BYTES ((BM+BN)*128)   // 49152
#define NSTAGES 4
#define SMEM_GEMM (NSTAGES*STAGE_BYTES)  // 196608 (<= 227KB cap)

// ---------------- device scratch ----------------
__device__ __nv_bfloat16 g_a1[(size_t)RR*2048];      // [query_hi | query_lo]
__device__ __nv_bfloat16 g_w1[(size_t)3072*2048];    // 6 proj weights; cols [hi|lo]
__device__ __nv_bfloat16 g_a2[(size_t)RR*2048];      // [ln_hi | ln_lo | grn_hi | grn_lo]
__device__ __nv_bfloat16 g_w2[(size_t)1024*2048];    // [wol_hi | wol_lo | woc_hi | woc_lo]
__device__ float g_bias1[3072];
__device__ float g_bias2[1024];
__device__ float g_proj[(size_t)6*RR*DD];            // q_lin,k_lin,v_lin,q_loc,k_loc,v_loc
__device__ float g_olin[(size_t)RR*DD];
__device__ float g_oloc[(size_t)RR*DD];
__device__ float g_kv    [(size_t)BB*HH*LL*DH*DH];
__device__ float g_kvprev[(size_t)BB*HH*LL*DH*DH];

// ---------------- asm helpers (base sm_80-era; no 'a' features) ----------
__device__ __forceinline__ uint32_t smem_u32(const void* p) {
    uint32_t a;
    asm("{ .reg .u64 t; cvta.to.shared.u64 t, %1; cvt.u32.u64 %0, t; }" : "=r"(a) : "l"(p));
    return a;
}
__device__ __forceinline__ void cpasync16(uint32_t s, const void* g) {
    asm volatile("cp.async.cg.shared.global [%0], [%1], 16;" :: "r"(s), "l"(g));
}
#define CP_COMMIT() asm volatile("cp.async.commit_group;" ::: "memory")
#define CP_WAIT0()  asm volatile("cp.async.wait_group 0;"  ::: "memory")

__device__ __forceinline__ void ldsm4(uint32_t* r, uint32_t addr) {
    asm volatile("ldmatrix.sync.aligned.m8n8.x4.shared.b16 {%0,%1,%2,%3}, [%4];"
        : "=r"(r[0]), "=r"(r[1]), "=r"(r[2]), "=r"(r[3]) : "r"(addr));
}
__device__ __forceinline__ void mma_bf16(float* c, const uint32_t* a,
                                         uint32_t b0, uint32_t b1) {
    asm volatile(
        "mma.sync.aligned.m16n8k16.row.col.f32.bf16.bf16.f32 "
        "{%0,%1,%2,%3}, {%4,%5,%6,%7}, {%8,%9}, {%0,%1,%2,%3};"
        : "+f"(c[0]), "+f"(c[1]), "+f"(c[2]), "+f"(c[3])
        : "r"(a[0]), "r"(a[1]), "r"(a[2]), "r"(a[3]), "r"(b0), "r"(b1));
}

__device__ __forceinline__ float gelu_tanh(float x) {
    float x3 = x*x*x;
    return 0.5f*x*(1.0f + tanhf(0.7978845608028654f*(x + 0.044715f*x3)));
}
__device__ __forceinline__ void split_bf16(float x, __nv_bfloat16& hi, __nv_bfloat16& lo) {
    hi = __float2bfloat16(x);
    lo = __float2bfloat16(x - __bfloat162float(hi));
}

// SW128 swizzle base for a [rows][64 bf16] tile (128B rows)
__device__ __forceinline__ uint32_t swz128(int row) {
    return (uint32_t)(row*128) ^ (((uint32_t)row & 7u) << 4);
}

// (aoff,boff) in bf16 elements along the 2048-wide concatenated K for k-step ks
__device__ __forceinline__ void seg_off(int gemmid, int ks, int& aoff, int& boff) {
    if (gemmid == 0) {
        int seg = ks >> 4, ko = (ks & 15)*64;
        aoff = ko + (seg == 2 ? 1024 : 0);
        boff = ko + (seg == 1 ? 1024 : 0);
    } else {
        int seg = ks >> 3, ko = (ks & 7)*64;
        int sa, sb;
        switch (seg) {
            case 0:  sa = 0;    sb = 0;    break;
            case 1:  sa = 0;    sb = 512;  break;
            case 2:  sa = 512;  sb = 0;    break;
            case 3:  sa = 1024; sb = 1024; break;
            case 4:  sa = 1024; sb = 1536; break;
            default: sa = 1536; sb = 1024; break;
        }
        aoff = sa + ko; boff = sb + ko;
    }
}

// =======================================================================
//   bf16 mma.sync GEMM: 512 thr, warp 32x64, BK=64, 4 stages,
//   ONE sync + ONE wait per TWO k-steps.
// =======================================================================
__global__ __launch_bounds__(512, 1)
void gemm_tc(int gemmid, float* __restrict__ outp)
{
    extern __shared__ char smem[];
    const uint32_t sb = smem_u32(smem);
    const int tid = threadIdx.x;
    const int mbase = blockIdx.y * BM;
    const int nbase = blockIdx.x * BN;
    const __nv_bfloat16* __restrict__ Ap = gemmid ? g_a2 : g_a1;
    const __nv_bfloat16* __restrict__ Bp = gemmid ? g_w2 : g_w1;

    float acc[2][8][4];
    #pragma unroll
    for (int i = 0; i < 2; i++)
        #pragma unroll
        for (int j = 0; j < 8; j++)
            #pragma unroll
            for (int q = 0; q < 4; q++) acc[i][j][q] = 0.f;

    const int ldA_row0 = tid >> 3,          ldA_row1 = (tid + 512) >> 3;
    const int ldB_row0 = tid >> 3,          ldB_row1 = (tid + 512) >> 3;
    const int ldB_row2 = (tid + 1024) >> 3, ldB_row3 = (tid + 1536) >> 3;
    const int ld_ch = tid & 7;
    const uint32_t chx = (uint32_t)ld_ch << 4;
    const uint32_t sA0 = swz128(ldA_row0) ^ chx;
    const uint32_t sA1 = swz128(ldA_row1) ^ chx;
    const uint32_t sB0 = (uint32_t)(BM*128) + (swz128(ldB_row0) ^ chx);
    const uint32_t sB1 = (uint32_t)(BM*128) + (swz128(ldB_row1) ^ chx);
    const uint32_t sB2 = (uint32_t)(BM*128) + (swz128(ldB_row2) ^ chx);
    const uint32_t sB3 = (uint32_t)(BM*128) + (swz128(ldB_row3) ^ chx);

    auto load_stage = [&](uint32_t sst, int aoff, int boff) {
        cpasync16(sst + sA0, Ap + (size_t)(mbase + ldA_row0)*2048 + aoff + ld_ch*8);
        cpasync16(sst + sA1, Ap + (size_t)(mbase + ldA_row1)*2048 + aoff + ld_ch*8);
        cpasync16(sst + sB0, Bp + (size_t)(nbase + ldB_row0)*2048 + boff + ld_ch*8);
        cpasync16(sst + sB1, Bp + (size_t)(nbase + ldB_row1)*2048 + boff + ld_ch*8);
        cpasync16(sst + sB2, Bp + (size_t)(nbase + ldB_row2)*2048 + boff + ld_ch*8);
        cpasync16(sst + sB3, Bp + (size_t)(nbase + ldB_row3)*2048 + boff + ld_ch*8);
    };

    const int lane = tid & 31, wid = tid >> 5;
    const int m0 = (wid & 3) * 32;
    const int n0 = (wid >> 2) * 64;

    uint32_t aBase[2], bBase[4];
    #pragma unroll
    for (int mt = 0; mt < 2; mt++)
        aBase[mt] = swz128(m0 + mt*16 + (lane & 15));
    #pragma unroll
    for (int p = 0; p < 4; p++)
        bBase[p] = (uint32_t)(BM*128) + swz128(n0 + p*16 + (lane & 15));
    const uint32_t kqSel = (uint32_t)(lane >> 4) << 4;

    auto compute_stage = [&](uint32_t sS) {
        #pragma unroll
        for (int kt = 0; kt < 4; kt++) {
            uint32_t kx = ((uint32_t)(kt*2) << 4) ^ kqSel;
            uint32_t aF[2][4];
            ldsm4(aF[0], sS + (aBase[0] ^ kx));
            ldsm4(aF[1], sS + (aBase[1] ^ kx));
            #pragma unroll
            for (int p = 0; p < 4; p++) {
                uint32_t bF[4];
                ldsm4(bF, sS + (bBase[p] ^ kx));
                #pragma unroll
                for (int mt = 0; mt < 2; mt++) {
                    mma_bf16(acc[mt][2*p],   aF[mt], bF[0], bF[2]);
                    mma_bf16(acc[mt][2*p+1], aF[mt], bF[1], bF[3]);
                }
            }
        }
    };

    {   // prologue: stages 0,1
        int ao, bo;
        seg_off(gemmid, 0, ao, bo); load_stage(sb, ao, bo); CP_COMMIT();
        seg_off(gemmid, 1, ao, bo); load_stage(sb + STAGE_BYTES, ao, bo); CP_COMMIT();
    }

    // pair loop: one wait + one sync per 2 k-steps
    for (int ks = 0; ks < KSTEPS; ks += 2) {
        CP_WAIT0();            // stages ks, ks+1 resident
        __syncthreads();       // also orders: everyone done with ks-2, ks-1
        if (ks + 3 < KSTEPS) {
            int ao, bo;
            seg_off(gemmid, ks + 2, ao, bo);
            load_stage(sb + (uint32_t)(((ks + 2) & 3) * STAGE_BYTES), ao, bo);
            CP_COMMIT();
            seg_off(gemmid, ks + 3, ao, bo);
            load_stage(sb + (uint32_t)(((ks + 3) & 3) * STAGE_BYTES), ao, bo);
            CP_COMMIT();
        }
        compute_stage(sb + (uint32_t)((ks & 3) * STAGE_BYTES));
        compute_stage(sb + (uint32_t)(((ks + 1) & 3) * STAGE_BYTES));
    }

    // ---- epilogue ----
    const int r_lo  = mbase + m0 + (lane >> 2);
    const int cbase = nbase + n0 + (lane & 3)*2;
    #pragma unroll
    for (int mt = 0; mt < 2; mt++) {
        #pragma unroll
        for (int nt = 0; nt < 8; nt++) {
            int col = cbase + nt*8;
            int row0 = r_lo + mt*16;
            float v0 = acc[mt][nt][0], v1 = acc[mt][nt][1];
            float v2 = acc[mt][nt][2], v3 = acc[mt][nt][3];
            if (gemmid == 0) {
                float b0 = g_bias1[col], b1 = g_bias1[col+1];
                v0 += b0; v1 += b1; v2 += b0; v3 += b1;
                int proj = col >> 9, lc = col & 511;
                if (proj < 2) {
                    v0 = gelu_tanh(v0); v1 = gelu_tanh(v1);
                    v2 = gelu_tanh(v2); v3 = gelu_tanh(v3);
                }
                float* base = g_proj + (size_t)proj * ((size_t)RR*DD);
                *reinterpret_cast<float2*>(base + (size_t)row0*DD + lc)
                    = make_float2(v0, v1);
                *reinterpret_cast<float2*>(base + (size_t)(row0+8)*DD + lc)
                    = make_float2(v2, v3);
            } else {
                float b0 = g_bias2[col], b1 = g_bias2[col+1];
                *reinterpret_cast<float2*>(outp + (size_t)row0*1024 + col)
                    = make_float2(0.5f*v0 + b0, 0.5f*v1 + b1);
                *reinterpret_cast<float2*>(outp + (size_t)(row0+8)*1024 + col)
                    = make_float2(0.5f*v2 + b0, 0.5f*v3 + b1);
            }
        }
    }
}

// =======================================================================
//   conversion kernels (fp32 -> bf16 hi/lo splits)
// =======================================================================
__global__ void conv_a1(const float* __restrict__ query)
{
    size_t i = (size_t)blockIdx.x * 256 + threadIdx.x;
    int r = (int)(i >> 10), c = (int)(i & 1023);
    __nv_bfloat16 hi, lo;
    split_bf16(query[i], hi, lo);
    g_a1[(size_t)r*2048 + c]        = hi;
    g_a1[(size_t)r*2048 + 1024 + c] = lo;
}

__global__ void conv_w1(const float* __restrict__ w0, const float* __restrict__ w1,
                        const float* __restrict__ w2, const float* __restrict__ w3,
                        const float* __restrict__ w4, const float* __restrict__ w5)
{
    size_t i = (size_t)blockIdx.x * 256 + threadIdx.x;
    int n = (int)(i >> 10), k = (int)(i & 1023);
    int proj = n >> 9, rloc = n & 511;
    const float* src;
    switch (proj) {
        case 0: src = w0; break; case 1: src = w1; break; case 2: src = w2; break;
        case 3: src = w3; break; case 4: src = w4; break; default: src = w5; break;
    }
    __nv_bfloat16 hi, lo;
    split_bf16(src[(size_t)rloc*1024 + k], hi, lo);
    g_w1[(size_t)n*2048 + k]        = hi;
    g_w1[(size_t)n*2048 + 1024 + k] = lo;
}

__global__ void conv_w2(const float* __restrict__ wo_lin, const float* __restrict__ wo_loc)
{
    size_t i = (size_t)blockIdx.x * 256 + threadIdx.x;
    int n = (int)(i >> 9), k = (int)(i & 511);
    __nv_bfloat16 hi, lo;
    split_bf16(wo_lin[(size_t)n*512 + k], hi, lo);
    g_w2[(size_t)n*2048 + k]       = hi;
    g_w2[(size_t)n*2048 + 512 + k] = lo;
    split_bf16(wo_loc[(size_t)n*512 + k], hi, lo);
    g_w2[(size_t)n*2048 + 1024 + k] = hi;
    g_w2[(size_t)n*2048 + 1536 + k] = lo;
}

__global__ void conv_bias(const float* __restrict__ b0, const float* __restrict__ b1,
                          const float* __restrict__ b2, const float* __restrict__ b3,
                          const float* __restrict__ b4, const float* __restrict__ b5,
                          const float* __restrict__ bo_lin, const float* __restrict__ bo_loc)
{
    int c = blockIdx.x * 256 + threadIdx.x;
    int proj = c >> 9, lc = c & 511;
    const float* src;
    switch (proj) {
        case 0: src = b0; break; case 1: src = b1; break; case 2: src = b2; break;
        case 3: src = b3; break; case 4: src = b4; break; default: src = b5; break;
    }
    g_bias1[c] = src[lc];
    if (c < 1024) g_bias2[c] = 0.5f * (bo_lin[c] + bo_loc[c]);
}

// =======================================================================
//   attention kernels — register-tiled (4x4 S-tiles, 4x2 O-tiles)
// =======================================================================
__global__ __launch_bounds__(256)
void attn_local_kernel()
{
    __shared__ float qs[64][33];
    __shared__ float ks[64][33];
    __shared__ float vs[64][33];
    __shared__ float S [64][65];

    int z = blockIdx.x;
    int l = z & 63, h = (z >> 6) & 15, b = z >> 10;
    int tid = threadIdx.x;
    const float* Q = g_proj + (size_t)3*RR*DD;
    const float* K = g_proj + (size_t)4*RR*DD;
    const float* V = g_proj + (size_t)5*RR*DD;

    for (int idx = tid; idx < 64*32; idx += 256) {
        int c = idx >> 5, dh = idx & 31;
        size_t off = ((size_t)((l*64 + c)*BB + b))*DD + h*32 + dh;
        qs[c][dh] = Q[off]; ks[c][dh] = K[off]; vs[c][dh] = V[off];
    }
    __syncthreads();

    {
        int tr = tid >> 4, tc = tid & 15;
        int c0 = tr*4, j0 = tc*4;
        float s[4][4] = {{0.f}};
        if (tc <= tr) {
            #pragma unroll 8
            for (int d = 0; d < 32; d++) {
                float rq[4], rk[4];
                #pragma unroll
                for (int i = 0; i < 4; i++) rq[i] = qs[c0+i][d];
                #pragma unroll
                for (int j = 0; j < 4; j++) rk[j] = ks[j0+j][d];
                #pragma unroll
                for (int i = 0; i < 4; i++)
                    #pragma unroll
                    for (int j = 0; j < 4; j++)
                        s[i][j] += rq[i]*rk[j];
            }
        }
        #pragma unroll
        for (int i = 0; i < 4; i++)
            #pragma unroll
            for (int j = 0; j < 4; j++) {
                float v = (j0+j <= c0+i) ? fmaxf(s[i][j], 0.f) : 0.f;
                S[c0+i][j0+j] = v;
            }
    }
    __syncthreads();

    {
        int cg = tid >> 4, dg = tid & 15;
        int c0 = cg*4, dh0 = dg*2;
        float o[4][2] = {{0.f}};
        #pragma unroll 8
        for (int j = 0; j < 64; j++) {
            float v0 = vs[j][dh0], v1 = vs[j][dh0+1];
            #pragma unroll
            for (int i = 0; i < 4; i++) {
                float sv = S[c0+i][j];
                o[i][0] += sv*v0; o[i][1] += sv*v1;
            }
        }
        #pragma unroll
        for (int i = 0; i < 4; i++) {
            size_t off = ((size_t)((l*64 + c0+i)*BB + b))*DD + h*32 + dh0;
            *reinterpret_cast<float2*>(g_oloc + off) = make_float2(o[i][0], o[i][1]);
        }
    }
}

__global__ __launch_bounds__(256)
void attn_kv_kernel()
{
    __shared__ float ks[64][33];
    __shared__ float vs[64][33];

    int z = blockIdx.x;
    int l = z & 63, h = (z >> 6) & 15, b = z >> 10;
    int tid = threadIdx.x;
    const float* K = g_proj + (size_t)1*RR*DD;
    const float* V = g_proj + (size_t)2*RR*DD;

    for (int idx = tid; idx < 64*32; idx += 256) {
        int c = idx >> 5, dh = idx & 31;
        size_t off = ((size_t)((l*64 + c)*BB + b))*DD + h*32 + dh;
        ks[c][dh] = K[off]; vs[c][dh] = V[off];
    }
    __syncthreads();

    int d0 = (tid >> 4)*2, e0 = (tid & 15)*2;
    float s[2][2] = {{0.f}};
    #pragma unroll 8
    for (int c = 0; c < 64; c++) {
        float k0 = ks[c][d0], k1 = ks[c][d0+1];
        float v0 = vs[c][e0], v1 = vs[c][e0+1];
        s[0][0] += k0*v0; s[0][1] += k0*v1;
        s[1][0] += k1*v0; s[1][1] += k1*v1;
    }
    float* dst = g_kv + (size_t)z*1024;
    *reinterpret_cast<float2*>(dst + (d0  )*32 + e0) = make_float2(s[0][0], s[0][1]);
    *reinterpret_cast<float2*>(dst + (d0+1)*32 + e0) = make_float2(s[1][0], s[1][1]);
}

__global__ __launch_bounds__(256)
void kv_cumsum_kernel()
{
    int bh = blockIdx.x;
    const float* src = g_kv     + (size_t)bh*LL*1024;
    float*       dst = g_kvprev + (size_t)bh*LL*1024;
    for (int j = threadIdx.x; j < 1024; j += 256) {
        float acc = 0.f;
        #pragma unroll 4
        for (int l = 0; l < LL; l++) {
            dst[l*1024 + j] = acc;
            acc += src[l*1024 + j];
        }
    }
}

__global__ __launch_bounds__(256)
void attn_lin_kernel()
{
    __shared__ float qs [64][33];
    __shared__ float ks [64][33];
    __shared__ float vs [64][33];
    __shared__ float kvp[32][33];
    __shared__ float S  [64][65];

    int z = blockIdx.x;
    int l = z & 63, h = (z >> 6) & 15, b = z >> 10;
    int tid = threadIdx.x;
    const float* Q = g_proj;
    const float* K = g_proj + (size_t)1*RR*DD;
    const float* V = g_proj + (size_t)2*RR*DD;

    for (int idx = tid; idx < 64*32; idx += 256) {
        int c = idx >> 5, dh = idx & 31;
        size_t off = ((size_t)((l*64 + c)*BB + b))*DD + h*32 + dh;
        qs[c][dh] = Q[off]; ks[c][dh] = K[off]; vs[c][dh] = V[off];
    }
    for (int idx = tid; idx < 32*32; idx += 256)
        kvp[idx >> 5][idx & 31] = g_kvprev[(size_t)z*1024 + idx];
    __syncthreads();

    {
        int tr = tid >> 4, tc = tid & 15;
        int c0 = tr*4, j0 = tc*4;
        float s[4][4] = {{0.f}};
        if (tc <= tr) {
            #pragma unroll 8
            for (int d = 0; d < 32; d++) {
                float rq[4], rk[4];
                #pragma unroll
                for (int i = 0; i < 4; i++) rq[i] = qs[c0+i][d];
                #pragma unroll
                for (int j = 0; j < 4; j++) rk[j] = ks[j0+j][d];
                #pragma unroll
                for (int i = 0; i < 4; i++)
                    #pragma unroll
                    for (int j = 0; j < 4; j++)
                        s[i][j] += rq[i]*rk[j];
            }
        }
        #pragma unroll
        for (int i = 0; i < 4; i++)
            #pragma unroll
            for (int j = 0; j < 4; j++)
                S[c0+i][j0+j] = (j0+j <= c0+i) ? s[i][j] : 0.f;
    }
    __syncthreads();

    {
        int cg = tid >> 4, dg = tid & 15;
        int c0 = cg*4, dh0 = dg*2;
        float o[4][2] = {{0.f}};
        #pragma unroll 8
        for (int j = 0; j < 64; j++) {
            float v0 = vs[j][dh0], v1 = vs[j][dh0+1];
            #pragma unroll
            for (int i = 0; i < 4; i++) {
                float sv = S[c0+i][j];
                o[i][0] += sv*v0; o[i][1] += sv*v1;
            }
        }
        #pragma unroll 8
        for (int d = 0; d < 32; d++) {
            float p0 = kvp[d][dh0], p1 = kvp[d][dh0+1];
            #pragma unroll
            for (int i = 0; i < 4; i++) {
                float qv = qs[c0+i][d];
                o[i][0] += qv*p0; o[i][1] += qv*p1;
            }
        }
        #pragma unroll
        for (int i = 0; i < 4; i++) {
            size_t off = ((size_t)((l*64 + c0+i)*BB + b))*DD + h*32 + dh0;
            *reinterpret_cast<float2*>(g_olin + off) = make_float2(o[i][0], o[i][1]);
        }
    }
}

// ---------------- norms -> bf16 hi/lo splits into g_a2 ----------------
__device__ __forceinline__ float block_sum256(float v, float* sbuf) {
    int tid = threadIdx.x;
    #pragma unroll
    for (int o = 16; o > 0; o >>= 1) v += __shfl_xor_sync(0xffffffffu, v, o);
    __syncthreads();
    if ((tid & 31) == 0) sbuf[tid >> 5] = v;
    __syncthreads();
    float t = sbuf[0];
    #pragma unroll
    for (int w = 1; w < 8; w++) t += sbuf[w];
    return t;
}

__global__ __launch_bounds__(256)
void norm_kernel(const float* __restrict__ ln_g, const float* __restrict__ ln_b,
                 const float* __restrict__ gsc,  const float* __restrict__ ggt)
{
    __shared__ float sbuf[8];
    int r = blockIdx.x, tid = threadIdx.x;
    __nv_bfloat16* a2 = g_a2 + (size_t)r*2048;

    const float* xl = g_olin + (size_t)r*DD;
    float a0 = xl[tid], a1 = xl[tid + 256];
    float mu = block_sum256(a0 + a1, sbuf) * (1.0f/512.0f);
    float d0 = a0 - mu, d1 = a1 - mu;
    float var = block_sum256(d0*d0 + d1*d1, sbuf) * (1.0f/512.0f);
    float rs = rsqrtf(var + 1e-5f);
    float y0 = d0*rs*ln_g[tid      ] + ln_b[tid      ];
    float y1 = d1*rs*ln_g[tid + 256] + ln_b[tid + 256];
    __nv_bfloat16 hi, lo;
    split_bf16(y0, hi, lo); a2[tid      ] = hi; a2[512 + tid      ] = lo;
    split_bf16(y1, hi, lo); a2[tid + 256] = hi; a2[512 + tid + 256] = lo;

    const float* xo = g_oloc + (size_t)r*DD;
    float b0 = xo[tid], b1 = xo[tid + 256];
    float ms = block_sum256(b0*b0 + b1*b1, sbuf) * (1.0f/512.0f);
    float inv = rsqrtf(ms + 1e-8f);
    float s0 = 1.0f/(1.0f + expf(-ggt[tid      ]*b0));
    float s1 = 1.0f/(1.0f + expf(-ggt[tid + 256]*b1));
    float z0 = b0*inv*gsc[tid      ]*s0;
    float z1 = b1*inv*gsc[tid + 256]*s1;
    split_bf16(z0, hi, lo); a2[1024 + tid      ] = hi; a2[1536 + tid      ] = lo;
    split_bf16(z1, hi, lo); a2[1024 + tid + 256] = hi; a2[1536 + tid + 256] = lo;
}

// =======================================================================
//   launch
// =======================================================================
extern "C" void kernel_launch(void* const* d_in, const int* in_sizes, int n_in,
                              void* d_out, int out_size)
{
    const float* query   = (const float*)d_in[0];
    const float* wq_lin  = (const float*)d_in[1];
    const float* bq_lin  = (const float*)d_in[2];
    const float* wk_lin  = (const float*)d_in[3];
    const float* bk_lin  = (const float*)d_in[4];
    const float* wv_lin  = (const float*)d_in[5];
    const float* bv_lin  = (const float*)d_in[6];
    const float* wo_lin  = (const float*)d_in[7];
    const float* bo_lin  = (const float*)d_in[8];
    const float* wq_loc  = (const float*)d_in[9];
    const float* bq_loc  = (const float*)d_in[10];
    const float* wk_loc  = (const float*)d_in[11];
    const float* bk_loc  = (const float*)d_in[12];
    const float* wv_loc  = (const float*)d_in[13];
    const float* bv_loc  = (const float*)d_in[14];
    const float* wo_loc  = (const float*)d_in[15];
    const float* bo_loc  = (const float*)d_in[16];
    const float* ln_g    = (const float*)d_in[17];
    const float* ln_b    = (const float*)d_in[18];
    const float* grn_s   = (const float*)d_in[19];
    const float* grn_g   = (const float*)d_in[20];
    float* out = (float*)d_out;

    cudaFuncSetAttribute(gemm_tc, cudaFuncAttributeMaxDynamicSharedMemorySize, SMEM_GEMM);

    conv_bias<<<3072/256, 256>>>(bq_lin, bk_lin, bv_lin, bq_loc, bk_loc, bv_loc, bo_lin, bo_loc);
    conv_a1  <<<(RR*1024)/256, 256>>>(query);
    conv_w1  <<<(3072*1024)/256, 256>>>(wq_lin, wk_lin, wv_lin, wq_loc, wk_loc, wv_loc);

    // fused input projections (6-in-1)   [launch idx 3]
    gemm_tc<<<dim3(3072/BN, RR/BM), 512, SMEM_GEMM>>>(0, nullptr);

    conv_w2  <<<(1024*512)/256, 256>>>(wo_lin, wo_loc);

    // attention (register-tiled)
    attn_local_kernel<<<BB*HH*LL, 256>>>();
    attn_kv_kernel   <<<BB*HH*LL, 256>>>();
    kv_cumsum_kernel <<<BB*HH,    256>>>();
    attn_lin_kernel  <<<BB*HH*LL, 256>>>();

    // norms (emit bf16 hi/lo operands for the output GEMM)
    norm_kernel<<<RR, 256>>>(ln_g, ln_b, grn_s, grn_g);

    // fused output projections (2-in-1)
    gemm_tc<<<dim3(1024/BN, RR/BM), 512, SMEM_GEMM>>>(1, out);
}

// round 9
// speedup vs baseline: 2.7762x; 1.0125x over previous
#include <cuda_runtime.h>
#include <cuda_bf16.h>
#include <stdint.h>
#include <math.h>

// ---------------- problem constants ----------------
#define NN 4096
#define BB 4
#define EE 1024
#define HH 16
#define DD 512
#define DH 32
#define LL 64
#define RR (NN*BB)   // 16384 rows

// ---------------- gemm geometry ----------------
#define BM 128
#define BN 256
#define BK 64                       // bf16 elems per k-step (128 bytes per row)
#define KSTEPS 48                   // both gemms: K' = 3072
#define STAGE_BYTES ((BM+BN)*128)   // 49152
#define NSTAGES 4
#define SMEM_GEMM (NSTAGES*STAGE_BYTES)  // 196608

// ---------------- device scratch ----------------
__device__ __nv_bfloat16 g_a1[(size_t)RR*2048];      // [query_hi | query_lo]
__device__ __nv_bfloat16 g_w1[(size_t)3072*2048];    // 6 proj weights; cols [hi|lo]
__device__ __nv_bfloat16 g_a2[(size_t)RR*2048];      // [ln_hi | ln_lo | grn_hi | grn_lo]
__device__ __nv_bfloat16 g_w2[(size_t)1024*2048];    // [wol_hi | wol_lo | woc_hi | woc_lo]
__device__ float g_bias1[3072];
__device__ float g_bias2[1024];
__device__ float g_proj[(size_t)6*RR*DD];            // q_lin,k_lin,v_lin,q_loc,k_loc,v_loc
__device__ float g_olin[(size_t)RR*DD];
__device__ float g_oloc[(size_t)RR*DD];
__device__ float g_kv    [(size_t)BB*HH*LL*DH*DH];
__device__ float g_kvprev[(size_t)BB*HH*LL*DH*DH];

// ---------------- asm helpers ----------
__device__ __forceinline__ uint32_t smem_u32(const void* p) {
    uint32_t a;
    asm("{ .reg .u64 t; cvta.to.shared.u64 t, %1; cvt.u32.u64 %0, t; }" : "=r"(a) : "l"(p));
    return a;
}
__device__ __forceinline__ void cpasync16(uint32_t s, const void* g) {
    asm volatile("cp.async.cg.shared.global [%0], [%1], 16;" :: "r"(s), "l"(g));
}
#define CP_COMMIT() asm volatile("cp.async.commit_group;" ::: "memory")
#define CP_WAIT0()  asm volatile("cp.async.wait_group 0;"  ::: "memory")

__device__ __forceinline__ void ldsm4(uint32_t* r, uint32_t addr) {
    asm volatile("ldmatrix.sync.aligned.m8n8.x4.shared.b16 {%0,%1,%2,%3}, [%4];"
        : "=r"(r[0]), "=r"(r[1]), "=r"(r[2]), "=r"(r[3]) : "r"(addr));
}
__device__ __forceinline__ void mma_bf16(float* c, const uint32_t* a,
                                         uint32_t b0, uint32_t b1) {
    asm volatile(
        "mma.sync.aligned.m16n8k16.row.col.f32.bf16.bf16.f32 "
        "{%0,%1,%2,%3}, {%4,%5,%6,%7}, {%8,%9}, {%0,%1,%2,%3};"
        : "+f"(c[0]), "+f"(c[1]), "+f"(c[2]), "+f"(c[3])
        : "r"(a[0]), "r"(a[1]), "r"(a[2]), "r"(a[3]), "r"(b0), "r"(b1));
}

__device__ __forceinline__ float gelu_tanh(float x) {
    float x3 = x*x*x;
    return 0.5f*x*(1.0f + tanhf(0.7978845608028654f*(x + 0.044715f*x3)));
}
__device__ __forceinline__ void split_bf16(float x, __nv_bfloat16& hi, __nv_bfloat16& lo) {
    hi = __float2bfloat16(x);
    lo = __float2bfloat16(x - __bfloat162float(hi));
}

// SW128 swizzle base for a [rows][64 bf16] tile (128B rows)
__device__ __forceinline__ uint32_t swz128(int row) {
    return (uint32_t)(row*128) ^ (((uint32_t)row & 7u) << 4);
}

// (aoff,boff) in bf16 elements along the 2048-wide concatenated K for k-step ks
__device__ __forceinline__ void seg_off(int gemmid, int ks, int& aoff, int& boff) {
    if (gemmid == 0) {
        int seg = ks >> 4, ko = (ks & 15)*64;
        aoff = ko + (seg == 2 ? 1024 : 0);
        boff = ko + (seg == 1 ? 1024 : 0);
    } else {
        int seg = ks >> 3, ko = (ks & 7)*64;
        int sa, sb;
        switch (seg) {
            case 0:  sa = 0;    sb = 0;    break;
            case 1:  sa = 0;    sb = 512;  break;
            case 2:  sa = 512;  sb = 0;    break;
            case 3:  sa = 1024; sb = 1024; break;
            case 4:  sa = 1024; sb = 1536; break;
            default: sa = 1536; sb = 1024; break;
        }
        aoff = sa + ko; boff = sb + ko;
    }
}

// =======================================================================
//   bf16 mma.sync GEMM: 512 thr, warp 32x64, BK=64, 4 stages,
//   pair loop + manually software-pipelined fragment loads.
// =======================================================================
__global__ __launch_bounds__(512, 1)
void gemm_tc(int gemmid, float* __restrict__ outp)
{
    extern __shared__ char smem[];
    const uint32_t sb = smem_u32(smem);
    const int tid = threadIdx.x;
    const int mbase = blockIdx.y * BM;
    const int nbase = blockIdx.x * BN;
    const __nv_bfloat16* __restrict__ Ap = gemmid ? g_a2 : g_a1;
    const __nv_bfloat16* __restrict__ Bp = gemmid ? g_w2 : g_w1;

    float acc[2][8][4];
    #pragma unroll
    for (int i = 0; i < 2; i++)
        #pragma unroll
        for (int j = 0; j < 8; j++)
            #pragma unroll
            for (int q = 0; q < 4; q++) acc[i][j][q] = 0.f;

    const int ldA_row0 = tid >> 3,          ldA_row1 = (tid + 512) >> 3;
    const int ldB_row0 = tid >> 3,          ldB_row1 = (tid + 512) >> 3;
    const int ldB_row2 = (tid + 1024) >> 3, ldB_row3 = (tid + 1536) >> 3;
    const int ld_ch = tid & 7;
    const uint32_t chx = (uint32_t)ld_ch << 4;
    const uint32_t sA0 = swz128(ldA_row0) ^ chx;
    const uint32_t sA1 = swz128(ldA_row1) ^ chx;
    const uint32_t sB0 = (uint32_t)(BM*128) + (swz128(ldB_row0) ^ chx);
    const uint32_t sB1 = (uint32_t)(BM*128) + (swz128(ldB_row1) ^ chx);
    const uint32_t sB2 = (uint32_t)(BM*128) + (swz128(ldB_row2) ^ chx);
    const uint32_t sB3 = (uint32_t)(BM*128) + (swz128(ldB_row3) ^ chx);

    auto load_stage = [&](uint32_t sst, int aoff, int boff) {
        cpasync16(sst + sA0, Ap + (size_t)(mbase + ldA_row0)*2048 + aoff + ld_ch*8);
        cpasync16(sst + sA1, Ap + (size_t)(mbase + ldA_row1)*2048 + aoff + ld_ch*8);
        cpasync16(sst + sB0, Bp + (size_t)(nbase + ldB_row0)*2048 + boff + ld_ch*8);
        cpasync16(sst + sB1, Bp + (size_t)(nbase + ldB_row1)*2048 + boff + ld_ch*8);
        cpasync16(sst + sB2, Bp + (size_t)(nbase + ldB_row2)*2048 + boff + ld_ch*8);
        cpasync16(sst + sB3, Bp + (size_t)(nbase + ldB_row3)*2048 + boff + ld_ch*8);
    };

    const int lane = tid & 31, wid = tid >> 5;
    const int m0 = (wid & 3) * 32;
    const int n0 = (wid >> 2) * 64;

    uint32_t aBase[2], bBase[4];
    #pragma unroll
    for (int mt = 0; mt < 2; mt++)
        aBase[mt] = swz128(m0 + mt*16 + (lane & 15));
    #pragma unroll
    for (int p = 0; p < 4; p++)
        bBase[p] = (uint32_t)(BM*128) + swz128(n0 + p*16 + (lane & 15));
    const uint32_t kqSel = (uint32_t)(lane >> 4) << 4;

    // pipelined compute over a pair of stages (8 k-slices)
    auto compute_pair = [&](uint32_t sS0, uint32_t sS1) {
        uint32_t aCur[2][4], aNxt[2][4], bCur[4], bNxt[4];
        const uint32_t sArr2[2] = {sS0, sS1};
        {   // prologue: slice 0 fragments
            ldsm4(aCur[0], sS0 + (aBase[0] ^ kqSel));
            ldsm4(aCur[1], sS0 + (aBase[1] ^ kqSel));
            ldsm4(bCur,    sS0 + (bBase[0] ^ kqSel));
        }
        #pragma unroll
        for (int sl = 0; sl < 8; sl++) {
            uint32_t sS = sArr2[sl >> 2];
            uint32_t kx = ((uint32_t)((sl & 3) * 2) << 4) ^ kqSel;
            #pragma unroll
            for (int p = 0; p < 4; p++) {
                if (p < 3) {
                    ldsm4(bNxt, sS + (bBase[p+1] ^ kx));
                } else if (sl < 7) {
                    uint32_t sS2 = sArr2[(sl+1) >> 2];
                    uint32_t kx2 = ((uint32_t)(((sl+1) & 3) * 2) << 4) ^ kqSel;
                    ldsm4(aNxt[0], sS2 + (aBase[0] ^ kx2));
                    ldsm4(aNxt[1], sS2 + (aBase[1] ^ kx2));
                    ldsm4(bNxt,    sS2 + (bBase[0] ^ kx2));
                }
                #pragma unroll
                for (int mt = 0; mt < 2; mt++) {
                    mma_bf16(acc[mt][2*p],   aCur[mt], bCur[0], bCur[2]);
                    mma_bf16(acc[mt][2*p+1], aCur[mt], bCur[1], bCur[3]);
                }
                #pragma unroll
                for (int q = 0; q < 4; q++) bCur[q] = bNxt[q];
            }
            #pragma unroll
            for (int mt = 0; mt < 2; mt++)
                #pragma unroll
                for (int q = 0; q < 4; q++) aCur[mt][q] = aNxt[mt][q];
        }
    };

    {   // prologue: stages 0,1
        int ao, bo;
        seg_off(gemmid, 0, ao, bo); load_stage(sb, ao, bo); CP_COMMIT();
        seg_off(gemmid, 1, ao, bo); load_stage(sb + STAGE_BYTES, ao, bo); CP_COMMIT();
    }

    for (int ks = 0; ks < KSTEPS; ks += 2) {
        CP_WAIT0();
        __syncthreads();
        if (ks + 3 < KSTEPS) {
            int ao, bo;
            seg_off(gemmid, ks + 2, ao, bo);
            load_stage(sb + (uint32_t)(((ks + 2) & 3) * STAGE_BYTES), ao, bo);
            CP_COMMIT();
            seg_off(gemmid, ks + 3, ao, bo);
            load_stage(sb + (uint32_t)(((ks + 3) & 3) * STAGE_BYTES), ao, bo);
            CP_COMMIT();
        }
        compute_pair(sb + (uint32_t)((ks & 3) * STAGE_BYTES),
                     sb + (uint32_t)(((ks + 1) & 3) * STAGE_BYTES));
    }

    // ---- epilogue ----
    const int r_lo  = mbase + m0 + (lane >> 2);
    const int cbase = nbase + n0 + (lane & 3)*2;
    #pragma unroll
    for (int mt = 0; mt < 2; mt++) {
        #pragma unroll
        for (int nt = 0; nt < 8; nt++) {
            int col = cbase + nt*8;
            int row0 = r_lo + mt*16;
            float v0 = acc[mt][nt][0], v1 = acc[mt][nt][1];
            float v2 = acc[mt][nt][2], v3 = acc[mt][nt][3];
            if (gemmid == 0) {
                float b0 = g_bias1[col], b1 = g_bias1[col+1];
                v0 += b0; v1 += b1; v2 += b0; v3 += b1;
                int proj = col >> 9, lc = col & 511;
                if (proj < 2) {
                    v0 = gelu_tanh(v0); v1 = gelu_tanh(v1);
                    v2 = gelu_tanh(v2); v3 = gelu_tanh(v3);
                }
                float* base = g_proj + (size_t)proj * ((size_t)RR*DD);
                *reinterpret_cast<float2*>(base + (size_t)row0*DD + lc)
                    = make_float2(v0, v1);
                *reinterpret_cast<float2*>(base + (size_t)(row0+8)*DD + lc)
                    = make_float2(v2, v3);
            } else {
                float b0 = g_bias2[col], b1 = g_bias2[col+1];
                *reinterpret_cast<float2*>(outp + (size_t)row0*1024 + col)
                    = make_float2(0.5f*v0 + b0, 0.5f*v1 + b1);
                *reinterpret_cast<float2*>(outp + (size_t)(row0+8)*1024 + col)
                    = make_float2(0.5f*v2 + b0, 0.5f*v3 + b1);
            }
        }
    }
}

// =======================================================================
//   conversion kernels (fp32 -> bf16 hi/lo splits)
// =======================================================================
__global__ void conv_a1(const float* __restrict__ query)
{
    size_t i = (size_t)blockIdx.x * 256 + threadIdx.x;
    int r = (int)(i >> 10), c = (int)(i & 1023);
    __nv_bfloat16 hi, lo;
    split_bf16(query[i], hi, lo);
    g_a1[(size_t)r*2048 + c]        = hi;
    g_a1[(size_t)r*2048 + 1024 + c] = lo;
}

__global__ void conv_w1(const float* __restrict__ w0, const float* __restrict__ w1,
                        const float* __restrict__ w2, const float* __restrict__ w3,
                        const float* __restrict__ w4, const float* __restrict__ w5)
{
    size_t i = (size_t)blockIdx.x * 256 + threadIdx.x;
    int n = (int)(i >> 10), k = (int)(i & 1023);
    int proj = n >> 9, rloc = n & 511;
    const float* src;
    switch (proj) {
        case 0: src = w0; break; case 1: src = w1; break; case 2: src = w2; break;
        case 3: src = w3; break; case 4: src = w4; break; default: src = w5; break;
    }
    __nv_bfloat16 hi, lo;
    split_bf16(src[(size_t)rloc*1024 + k], hi, lo);
    g_w1[(size_t)n*2048 + k]        = hi;
    g_w1[(size_t)n*2048 + 1024 + k] = lo;
}

__global__ void conv_w2(const float* __restrict__ wo_lin, const float* __restrict__ wo_loc)
{
    size_t i = (size_t)blockIdx.x * 256 + threadIdx.x;
    int n = (int)(i >> 9), k = (int)(i & 511);
    __nv_bfloat16 hi, lo;
    split_bf16(wo_lin[(size_t)n*512 + k], hi, lo);
    g_w2[(size_t)n*2048 + k]       = hi;
    g_w2[(size_t)n*2048 + 512 + k] = lo;
    split_bf16(wo_loc[(size_t)n*512 + k], hi, lo);
    g_w2[(size_t)n*2048 + 1024 + k] = hi;
    g_w2[(size_t)n*2048 + 1536 + k] = lo;
}

__global__ void conv_bias(const float* __restrict__ b0, const float* __restrict__ b1,
                          const float* __restrict__ b2, const float* __restrict__ b3,
                          const float* __restrict__ b4, const float* __restrict__ b5,
                          const float* __restrict__ bo_lin, const float* __restrict__ bo_loc)
{
    int c = blockIdx.x * 256 + threadIdx.x;
    int proj = c >> 9, lc = c & 511;
    const float* src;
    switch (proj) {
        case 0: src = b0; break; case 1: src = b1; break; case 2: src = b2; break;
        case 3: src = b3; break; case 4: src = b4; break; default: src = b5; break;
    }
    g_bias1[c] = src[lc];
    if (c < 1024) g_bias2[c] = 0.5f * (bo_lin[c] + bo_loc[c]);
}

// =======================================================================
//   attention kernels — register-tiled
// =======================================================================
__global__ __launch_bounds__(256)
void attn_local_kernel()
{
    __shared__ float qs[64][33];
    __shared__ float ks[64][33];
    __shared__ float vs[64][33];
    __shared__ float S [64][65];

    int z = blockIdx.x;
    int l = z & 63, h = (z >> 6) & 15, b = z >> 10;
    int tid = threadIdx.x;
    const float* Q = g_proj + (size_t)3*RR*DD;
    const float* K = g_proj + (size_t)4*RR*DD;
    const float* V = g_proj + (size_t)5*RR*DD;

    for (int idx = tid; idx < 64*32; idx += 256) {
        int c = idx >> 5, dh = idx & 31;
        size_t off = ((size_t)((l*64 + c)*BB + b))*DD + h*32 + dh;
        qs[c][dh] = Q[off]; ks[c][dh] = K[off]; vs[c][dh] = V[off];
    }
    __syncthreads();

    {
        int tr = tid >> 4, tc = tid & 15;
        int c0 = tr*4, j0 = tc*4;
        float s[4][4] = {{0.f}};
        if (tc <= tr) {
            #pragma unroll 8
            for (int d = 0; d < 32; d++) {
                float rq[4], rk[4];
                #pragma unroll
                for (int i = 0; i < 4; i++) rq[i] = qs[c0+i][d];
                #pragma unroll
                for (int j = 0; j < 4; j++) rk[j] = ks[j0+j][d];
                #pragma unroll
                for (int i = 0; i < 4; i++)
                    #pragma unroll
                    for (int j = 0; j < 4; j++)
                        s[i][j] += rq[i]*rk[j];
            }
        }
        #pragma unroll
        for (int i = 0; i < 4; i++)
            #pragma unroll
            for (int j = 0; j < 4; j++) {
                float v = (j0+j <= c0+i) ? fmaxf(s[i][j], 0.f) : 0.f;
                S[c0+i][j0+j] = v;
            }
    }
    __syncthreads();

    {
        int cg = tid >> 4, dg = tid & 15;
        int c0 = cg*4, dh0 = dg*2;
        float o[4][2] = {{0.f}};
        #pragma unroll 8
        for (int j = 0; j < 64; j++) {
            float v0 = vs[j][dh0], v1 = vs[j][dh0+1];
            #pragma unroll
            for (int i = 0; i < 4; i++) {
                float sv = S[c0+i][j];
                o[i][0] += sv*v0; o[i][1] += sv*v1;
            }
        }
        #pragma unroll
        for (int i = 0; i < 4; i++) {
            size_t off = ((size_t)((l*64 + c0+i)*BB + b))*DD + h*32 + dh0;
            *reinterpret_cast<float2*>(g_oloc + off) = make_float2(o[i][0], o[i][1]);
        }
    }
}

__global__ __launch_bounds__(256)
void attn_kv_kernel()
{
    __shared__ float ks[64][33];
    __shared__ float vs[64][33];

    int z = blockIdx.x;
    int l = z & 63, h = (z >> 6) & 15, b = z >> 10;
    int tid = threadIdx.x;
    const float* K = g_proj + (size_t)1*RR*DD;
    const float* V = g_proj + (size_t)2*RR*DD;

    for (int idx = tid; idx < 64*32; idx += 256) {
        int c = idx >> 5, dh = idx & 31;
        size_t off = ((size_t)((l*64 + c)*BB + b))*DD + h*32 + dh;
        ks[c][dh] = K[off]; vs[c][dh] = V[off];
    }
    __syncthreads();

    int d0 = (tid >> 4)*2, e0 = (tid & 15)*2;
    float s[2][2] = {{0.f}};
    #pragma unroll 8
    for (int c = 0; c < 64; c++) {
        float k0 = ks[c][d0], k1 = ks[c][d0+1];
        float v0 = vs[c][e0], v1 = vs[c][e0+1];
        s[0][0] += k0*v0; s[0][1] += k0*v1;
        s[1][0] += k1*v0; s[1][1] += k1*v1;
    }
    float* dst = g_kv + (size_t)z*1024;
    *reinterpret_cast<float2*>(dst + (d0  )*32 + e0) = make_float2(s[0][0], s[0][1]);
    *reinterpret_cast<float2*>(dst + (d0+1)*32 + e0) = make_float2(s[1][0], s[1][1]);
}

__global__ __launch_bounds__(256)
void kv_cumsum_kernel()
{
    int bh = blockIdx.x;
    const float* src = g_kv     + (size_t)bh*LL*1024;
    float*       dst = g_kvprev + (size_t)bh*LL*1024;
    for (int j = threadIdx.x; j < 1024; j += 256) {
        float acc = 0.f;
        #pragma unroll 4
        for (int l = 0; l < LL; l++) {
            dst[l*1024 + j] = acc;
            acc += src[l*1024 + j];
        }
    }
}

__global__ __launch_bounds__(256)
void attn_lin_kernel()
{
    __shared__ float qs [64][33];
    __shared__ float ks [64][33];
    __shared__ float vs [64][33];
    __shared__ float kvp[32][33];
    __shared__ float S  [64][65];

    int z = blockIdx.x;
    int l = z & 63, h = (z >> 6) & 15, b = z >> 10;
    int tid = threadIdx.x;
    const float* Q = g_proj;
    const float* K = g_proj + (size_t)1*RR*DD;
    const float* V = g_proj + (size_t)2*RR*DD;

    for (int idx = tid; idx < 64*32; idx += 256) {
        int c = idx >> 5, dh = idx & 31;
        size_t off = ((size_t)((l*64 + c)*BB + b))*DD + h*32 + dh;
        qs[c][dh] = Q[off]; ks[c][dh] = K[off]; vs[c][dh] = V[off];
    }
    for (int idx = tid; idx < 32*32; idx += 256)
        kvp[idx >> 5][idx & 31] = g_kvprev[(size_t)z*1024 + idx];
    __syncthreads();

    {
        int tr = tid >> 4, tc = tid & 15;
        int c0 = tr*4, j0 = tc*4;
        float s[4][4] = {{0.f}};
        if (tc <= tr) {
            #pragma unroll 8
            for (int d = 0; d < 32; d++) {
                float rq[4], rk[4];
                #pragma unroll
                for (int i = 0; i < 4; i++) rq[i] = qs[c0+i][d];
                #pragma unroll
                for (int j = 0; j < 4; j++) rk[j] = ks[j0+j][d];
                #pragma unroll
                for (int i = 0; i < 4; i++)
                    #pragma unroll
                    for (int j = 0; j < 4; j++)
                        s[i][j] += rq[i]*rk[j];
            }
        }
        #pragma unroll
        for (int i = 0; i < 4; i++)
            #pragma unroll
            for (int j = 0; j < 4; j++)
                S[c0+i][j0+j] = (j0+j <= c0+i) ? s[i][j] : 0.f;
    }
    __syncthreads();

    {
        int cg = tid >> 4, dg = tid & 15;
        int c0 = cg*4, dh0 = dg*2;
        float o[4][2] = {{0.f}};
        #pragma unroll 8
        for (int j = 0; j < 64; j++) {
            float v0 = vs[j][dh0], v1 = vs[j][dh0+1];
            #pragma unroll
            for (int i = 0; i < 4; i++) {
                float sv = S[c0+i][j];
                o[i][0] += sv*v0; o[i][1] += sv*v1;
            }
        }
        #pragma unroll 8
        for (int d = 0; d < 32; d++) {
            float p0 = kvp[d][dh0], p1 = kvp[d][dh0+1];
            #pragma unroll
            for (int i = 0; i < 4; i++) {
                float qv = qs[c0+i][d];
                o[i][0] += qv*p0; o[i][1] += qv*p1;
            }
        }
        #pragma unroll
        for (int i = 0; i < 4; i++) {
            size_t off = ((size_t)((l*64 + c0+i)*BB + b))*DD + h*32 + dh0;
            *reinterpret_cast<float2*>(g_olin + off) = make_float2(o[i][0], o[i][1]);
        }
    }
}

// ---------------- norms -> bf16 hi/lo splits into g_a2 ----------------
__device__ __forceinline__ float block_sum256(float v, float* sbuf) {
    int tid = threadIdx.x;
    #pragma unroll
    for (int o = 16; o > 0; o >>= 1) v += __shfl_xor_sync(0xffffffffu, v, o);
    __syncthreads();
    if ((tid & 31) == 0) sbuf[tid >> 5] = v;
    __syncthreads();
    float t = sbuf[0];
    #pragma unroll
    for (int w = 1; w < 8; w++) t += sbuf[w];
    return t;
}

__global__ __launch_bounds__(256)
void norm_kernel(const float* __restrict__ ln_g, const float* __restrict__ ln_b,
                 const float* __restrict__ gsc,  const float* __restrict__ ggt)
{
    __shared__ float sbuf[8];
    int r = blockIdx.x, tid = threadIdx.x;
    __nv_bfloat16* a2 = g_a2 + (size_t)r*2048;

    const float* xl = g_olin + (size_t)r*DD;
    float a0 = xl[tid], a1 = xl[tid + 256];
    float mu = block_sum256(a0 + a1, sbuf) * (1.0f/512.0f);
    float d0 = a0 - mu, d1 = a1 - mu;
    float var = block_sum256(d0*d0 + d1*d1, sbuf) * (1.0f/512.0f);
    float rs = rsqrtf(var + 1e-5f);
    float y0 = d0*rs*ln_g[tid      ] + ln_b[tid      ];
    float y1 = d1*rs*ln_g[tid + 256] + ln_b[tid + 256];
    __nv_bfloat16 hi, lo;
    split_bf16(y0, hi, lo); a2[tid      ] = hi; a2[512 + tid      ] = lo;
    split_bf16(y1, hi, lo); a2[tid + 256] = hi; a2[512 + tid + 256] = lo;

    const float* xo = g_oloc + (size_t)r*DD;
    float b0 = xo[tid], b1 = xo[tid + 256];
    float ms = block_sum256(b0*b0 + b1*b1, sbuf) * (1.0f/512.0f);
    float inv = rsqrtf(ms + 1e-8f);
    float s0 = 1.0f/(1.0f + expf(-ggt[tid      ]*b0));
    float s1 = 1.0f/(1.0f + expf(-ggt[tid + 256]*b1));
    float z0 = b0*inv*gsc[tid      ]*s0;
    float z1 = b1*inv*gsc[tid + 256]*s1;
    split_bf16(z0, hi, lo); a2[1024 + tid      ] = hi; a2[1536 + tid      ] = lo;
    split_bf16(z1, hi, lo); a2[1024 + tid + 256] = hi; a2[1536 + tid + 256] = lo;
}

// =======================================================================
//   launch
// =======================================================================
extern "C" void kernel_launch(void* const* d_in, const int* in_sizes, int n_in,
                              void* d_out, int out_size)
{
    const float* query   = (const float*)d_in[0];
    const float* wq_lin  = (const float*)d_in[1];
    const float* bq_lin  = (const float*)d_in[2];
    const float* wk_lin  = (const float*)d_in[3];
    const float* bk_lin  = (const float*)d_in[4];
    const float* wv_lin  = (const float*)d_in[5];
    const float* bv_lin  = (const float*)d_in[6];
    const float* wo_lin  = (const float*)d_in[7];
    const float* bo_lin  = (const float*)d_in[8];
    const float* wq_loc  = (const float*)d_in[9];
    const float* bq_loc  = (const float*)d_in[10];
    const float* wk_loc  = (const float*)d_in[11];
    const float* bk_loc  = (const float*)d_in[12];
    const float* wv_loc  = (const float*)d_in[13];
    const float* bv_loc  = (const float*)d_in[14];
    const float* wo_loc  = (const float*)d_in[15];
    const float* bo_loc  = (const float*)d_in[16];
    const float* ln_g    = (const float*)d_in[17];
    const float* ln_b    = (const float*)d_in[18];
    const float* grn_s   = (const float*)d_in[19];
    const float* grn_g   = (const float*)d_in[20];
    float* out = (float*)d_out;

    cudaFuncSetAttribute(gemm_tc, cudaFuncAttributeMaxDynamicSharedMemorySize, SMEM_GEMM);

    conv_bias<<<3072/256, 256>>>(bq_lin, bk_lin, bv_lin, bq_loc, bk_loc, bv_loc, bo_lin, bo_loc);
    conv_a1  <<<(RR*1024)/256, 256>>>(query);
    conv_w1  <<<(3072*1024)/256, 256>>>(wq_lin, wk_lin, wv_lin, wq_loc, wk_loc, wv_loc);

    // fused input projections (6-in-1)   [launch idx 3]
    gemm_tc<<<dim3(3072/BN, RR/BM), 512, SMEM_GEMM>>>(0, nullptr);

    conv_w2  <<<(1024*512)/256, 256>>>(wo_lin, wo_loc);

    // attention (register-tiled)
    attn_local_kernel<<<BB*HH*LL, 256>>>();
    attn_kv_kernel   <<<BB*HH*LL, 256>>>();
    kv_cumsum_kernel <<<BB*HH,    256>>>();
    attn_lin_kernel  <<<BB*HH*LL, 256>>>();

    // norms (emit bf16 hi/lo operands for the output GEMM)
    norm_kernel<<<RR, 256>>>(ln_g, ln_b, grn_s, grn_g);

    // fused output projections (2-in-1)
    gemm_tc<<<dim3(1024/BN, RR/BM), 512, SMEM_GEMM>>>(1, out);
}

// round 10
// speedup vs baseline: 3.5820x; 1.2903x over previous
#include <cuda_runtime.h>
#include <cuda_fp16.h>
#include <stdint.h>
#include <math.h>

// ---------------- problem constants ----------------
#define NN 4096
#define BB 4
#define EE 1024
#define HH 16
#define DD 512
#define DH 32
#define LL 64
#define RR (NN*BB)   // 16384 rows

// ---------------- gemm geometry ----------------
#define BM 128
#define BN 256
#define BK 64                       // fp16 elems per k-step (128 bytes per row)
#define KSTEPS 32                   // both gemms: K' = 2048 (fp16 2-term split)
#define STAGE_BYTES ((BM+BN)*128)   // 49152
#define NSTAGES 4
#define SMEM_GEMM (NSTAGES*STAGE_BYTES)  // 196608

// ---------------- device scratch ----------------
__device__ __half g_a1[(size_t)RR*2048];      // [query_hi | query_lo]
__device__ __half g_w1[(size_t)3072*1024];    // 6 proj weights, hi only
__device__ __half g_a2[(size_t)RR*2048];      // [ln_hi | ln_lo | grn_hi | grn_lo]
__device__ __half g_w2[(size_t)1024*1024];    // [wol_hi | woc_hi]
__device__ float g_bias1[3072];
__device__ float g_bias2[1024];
__device__ float g_proj[(size_t)6*RR*DD];     // q_lin,k_lin,v_lin,q_loc,k_loc,v_loc
__device__ float g_olin[(size_t)RR*DD];
__device__ float g_oloc[(size_t)RR*DD];
__device__ float g_kv    [(size_t)BB*HH*LL*DH*DH];
__device__ float g_kvprev[(size_t)BB*HH*LL*DH*DH];

// ---------------- asm helpers ----------
__device__ __forceinline__ uint32_t smem_u32(const void* p) {
    uint32_t a;
    asm("{ .reg .u64 t; cvta.to.shared.u64 t, %1; cvt.u32.u64 %0, t; }" : "=r"(a) : "l"(p));
    return a;
}
__device__ __forceinline__ void cpasync16(uint32_t s, const void* g) {
    asm volatile("cp.async.cg.shared.global [%0], [%1], 16;" :: "r"(s), "l"(g));
}
#define CP_COMMIT() asm volatile("cp.async.commit_group;" ::: "memory")
#define CP_WAIT0()  asm volatile("cp.async.wait_group 0;"  ::: "memory")

__device__ __forceinline__ void ldsm4(uint32_t* r, uint32_t addr) {
    asm volatile("ldmatrix.sync.aligned.m8n8.x4.shared.b16 {%0,%1,%2,%3}, [%4];"
        : "=r"(r[0]), "=r"(r[1]), "=r"(r[2]), "=r"(r[3]) : "r"(addr));
}
__device__ __forceinline__ void mma_f16(float* c, const uint32_t* a,
                                        uint32_t b0, uint32_t b1) {
    asm volatile(
        "mma.sync.aligned.m16n8k16.row.col.f32.f16.f16.f32 "
        "{%0,%1,%2,%3}, {%4,%5,%6,%7}, {%8,%9}, {%0,%1,%2,%3};"
        : "+f"(c[0]), "+f"(c[1]), "+f"(c[2]), "+f"(c[3])
        : "r"(a[0]), "r"(a[1]), "r"(a[2]), "r"(a[3]), "r"(b0), "r"(b1));
}

__device__ __forceinline__ float gelu_tanh(float x) {
    float x3 = x*x*x;
    return 0.5f*x*(1.0f + tanhf(0.7978845608028654f*(x + 0.044715f*x3)));
}
__device__ __forceinline__ void split_f16(float x, __half& hi, __half& lo) {
    hi = __float2half(x);
    lo = __float2half(x - __half2float(hi));
}

// SW128 swizzle base for a [rows][64 fp16] tile (128B rows)
__device__ __forceinline__ uint32_t swz128(int row) {
    return (uint32_t)(row*128) ^ (((uint32_t)row & 7u) << 4);
}

// (aoff,boff) in fp16 elements along the concatenated K for k-step ks
__device__ __forceinline__ void seg_off(int gemmid, int ks, int& aoff, int& boff) {
    if (gemmid == 0) {
        // 2 segments of 1024: (q_hi, w_hi), (q_lo, w_hi)
        int seg = ks >> 4, ko = (ks & 15)*64;
        aoff = ko + (seg ? 1024 : 0);
        boff = ko;
    } else {
        // 4 segments of 512: (ln_hi,wol)(ln_lo,wol)(grn_hi,woc)(grn_lo,woc)
        int seg = ks >> 3, ko = (ks & 7)*64;
        aoff = seg*512 + ko;
        boff = (seg >= 2 ? 512 : 0) + ko;
    }
}

// =======================================================================
//   fp16 mma.sync GEMM: 512 thr, warp 32x64, BK=64, 4 stages, pair loop
//   gemmid 0: N=3072, A stride 2048, B stride 1024 -> g_proj (+bias/gelu)
//   gemmid 1: N=1024, A stride 2048, B stride 1024 -> out = 0.5*acc + bias2
// =======================================================================
__global__ __launch_bounds__(512, 1)
void gemm_tc(int gemmid, float* __restrict__ outp)
{
    extern __shared__ char smem[];
    const uint32_t sb = smem_u32(smem);
    const int tid = threadIdx.x;
    const int mbase = blockIdx.y * BM;
    const int nbase = blockIdx.x * BN;
    const __half* __restrict__ Ap = gemmid ? g_a2 : g_a1;
    const __half* __restrict__ Bp = gemmid ? g_w2 : g_w1;

    float acc[2][8][4];
    #pragma unroll
    for (int i = 0; i < 2; i++)
        #pragma unroll
        for (int j = 0; j < 8; j++)
            #pragma unroll
            for (int q = 0; q < 4; q++) acc[i][j][q] = 0.f;

    const int ldA_row0 = tid >> 3,          ldA_row1 = (tid + 512) >> 3;
    const int ldB_row0 = tid >> 3,          ldB_row1 = (tid + 512) >> 3;
    const int ldB_row2 = (tid + 1024) >> 3, ldB_row3 = (tid + 1536) >> 3;
    const int ld_ch = tid & 7;
    const uint32_t chx = (uint32_t)ld_ch << 4;
    const uint32_t sA0 = swz128(ldA_row0) ^ chx;
    const uint32_t sA1 = swz128(ldA_row1) ^ chx;
    const uint32_t sB0 = (uint32_t)(BM*128) + (swz128(ldB_row0) ^ chx);
    const uint32_t sB1 = (uint32_t)(BM*128) + (swz128(ldB_row1) ^ chx);
    const uint32_t sB2 = (uint32_t)(BM*128) + (swz128(ldB_row2) ^ chx);
    const uint32_t sB3 = (uint32_t)(BM*128) + (swz128(ldB_row3) ^ chx);

    auto load_stage = [&](uint32_t sst, int aoff, int boff) {
        cpasync16(sst + sA0, Ap + (size_t)(mbase + ldA_row0)*2048 + aoff + ld_ch*8);
        cpasync16(sst + sA1, Ap + (size_t)(mbase + ldA_row1)*2048 + aoff + ld_ch*8);
        cpasync16(sst + sB0, Bp + (size_t)(nbase + ldB_row0)*1024 + boff + ld_ch*8);
        cpasync16(sst + sB1, Bp + (size_t)(nbase + ldB_row1)*1024 + boff + ld_ch*8);
        cpasync16(sst + sB2, Bp + (size_t)(nbase + ldB_row2)*1024 + boff + ld_ch*8);
        cpasync16(sst + sB3, Bp + (size_t)(nbase + ldB_row3)*1024 + boff + ld_ch*8);
    };

    const int lane = tid & 31, wid = tid >> 5;
    const int m0 = (wid & 3) * 32;
    const int n0 = (wid >> 2) * 64;

    uint32_t aBase[2], bBase[4];
    #pragma unroll
    for (int mt = 0; mt < 2; mt++)
        aBase[mt] = swz128(m0 + mt*16 + (lane & 15));
    #pragma unroll
    for (int p = 0; p < 4; p++)
        bBase[p] = (uint32_t)(BM*128) + swz128(n0 + p*16 + (lane & 15));
    const uint32_t kqSel = (uint32_t)(lane >> 4) << 4;

    // pipelined compute over a pair of stages (8 k-slices)
    auto compute_pair = [&](uint32_t sS0, uint32_t sS1) {
        uint32_t aCur[2][4], aNxt[2][4], bCur[4], bNxt[4];
        const uint32_t sArr2[2] = {sS0, sS1};
        {
            ldsm4(aCur[0], sS0 + (aBase[0] ^ kqSel));
            ldsm4(aCur[1], sS0 + (aBase[1] ^ kqSel));
            ldsm4(bCur,    sS0 + (bBase[0] ^ kqSel));
        }
        #pragma unroll
        for (int sl = 0; sl < 8; sl++) {
            uint32_t sS = sArr2[sl >> 2];
            uint32_t kx = ((uint32_t)((sl & 3) * 2) << 4) ^ kqSel;
            #pragma unroll
            for (int p = 0; p < 4; p++) {
                if (p < 3) {
                    ldsm4(bNxt, sS + (bBase[p+1] ^ kx));
                } else if (sl < 7) {
                    uint32_t sS2 = sArr2[(sl+1) >> 2];
                    uint32_t kx2 = ((uint32_t)(((sl+1) & 3) * 2) << 4) ^ kqSel;
                    ldsm4(aNxt[0], sS2 + (aBase[0] ^ kx2));
                    ldsm4(aNxt[1], sS2 + (aBase[1] ^ kx2));
                    ldsm4(bNxt,    sS2 + (bBase[0] ^ kx2));
                }
                #pragma unroll
                for (int mt = 0; mt < 2; mt++) {
                    mma_f16(acc[mt][2*p],   aCur[mt], bCur[0], bCur[2]);
                    mma_f16(acc[mt][2*p+1], aCur[mt], bCur[1], bCur[3]);
                }
                #pragma unroll
                for (int q = 0; q < 4; q++) bCur[q] = bNxt[q];
            }
            #pragma unroll
            for (int mt = 0; mt < 2; mt++)
                #pragma unroll
                for (int q = 0; q < 4; q++) aCur[mt][q] = aNxt[mt][q];
        }
    };

    {   // prologue: stages 0,1
        int ao, bo;
        seg_off(gemmid, 0, ao, bo); load_stage(sb, ao, bo); CP_COMMIT();
        seg_off(gemmid, 1, ao, bo); load_stage(sb + STAGE_BYTES, ao, bo); CP_COMMIT();
    }

    for (int ks = 0; ks < KSTEPS; ks += 2) {
        CP_WAIT0();
        __syncthreads();
        if (ks + 3 < KSTEPS) {
            int ao, bo;
            seg_off(gemmid, ks + 2, ao, bo);
            load_stage(sb + (uint32_t)(((ks + 2) & 3) * STAGE_BYTES), ao, bo);
            CP_COMMIT();
            seg_off(gemmid, ks + 3, ao, bo);
            load_stage(sb + (uint32_t)(((ks + 3) & 3) * STAGE_BYTES), ao, bo);
            CP_COMMIT();
        }
        compute_pair(sb + (uint32_t)((ks & 3) * STAGE_BYTES),
                     sb + (uint32_t)(((ks + 1) & 3) * STAGE_BYTES));
    }

    // ---- epilogue ----
    const int r_lo  = mbase + m0 + (lane >> 2);
    const int cbase = nbase + n0 + (lane & 3)*2;
    #pragma unroll
    for (int mt = 0; mt < 2; mt++) {
        #pragma unroll
        for (int nt = 0; nt < 8; nt++) {
            int col = cbase + nt*8;
            int row0 = r_lo + mt*16;
            float v0 = acc[mt][nt][0], v1 = acc[mt][nt][1];
            float v2 = acc[mt][nt][2], v3 = acc[mt][nt][3];
            if (gemmid == 0) {
                float b0 = g_bias1[col], b1 = g_bias1[col+1];
                v0 += b0; v1 += b1; v2 += b0; v3 += b1;
                int proj = col >> 9, lc = col & 511;
                if (proj < 2) {
                    v0 = gelu_tanh(v0); v1 = gelu_tanh(v1);
                    v2 = gelu_tanh(v2); v3 = gelu_tanh(v3);
                }
                float* base = g_proj + (size_t)proj * ((size_t)RR*DD);
                *reinterpret_cast<float2*>(base + (size_t)row0*DD + lc)
                    = make_float2(v0, v1);
                *reinterpret_cast<float2*>(base + (size_t)(row0+8)*DD + lc)
                    = make_float2(v2, v3);
            } else {
                float b0 = g_bias2[col], b1 = g_bias2[col+1];
                *reinterpret_cast<float2*>(outp + (size_t)row0*1024 + col)
                    = make_float2(0.5f*v0 + b0, 0.5f*v1 + b1);
                *reinterpret_cast<float2*>(outp + (size_t)(row0+8)*1024 + col)
                    = make_float2(0.5f*v2 + b0, 0.5f*v3 + b1);
            }
        }
    }
}

// =======================================================================
//   conversion kernels (fp32 -> fp16 hi/lo splits)
// =======================================================================
__global__ void conv_a1(const float* __restrict__ query)
{
    size_t i = (size_t)blockIdx.x * 256 + threadIdx.x;
    int r = (int)(i >> 10), c = (int)(i & 1023);
    __half hi, lo;
    split_f16(query[i], hi, lo);
    g_a1[(size_t)r*2048 + c]        = hi;
    g_a1[(size_t)r*2048 + 1024 + c] = lo;
}

__global__ void conv_w1(const float* __restrict__ w0, const float* __restrict__ w1,
                        const float* __restrict__ w2, const float* __restrict__ w3,
                        const float* __restrict__ w4, const float* __restrict__ w5)
{
    size_t i = (size_t)blockIdx.x * 256 + threadIdx.x;   // 3072*1024
    int n = (int)(i >> 10), k = (int)(i & 1023);
    int proj = n >> 9, rloc = n & 511;
    const float* src;
    switch (proj) {
        case 0: src = w0; break; case 1: src = w1; break; case 2: src = w2; break;
        case 3: src = w3; break; case 4: src = w4; break; default: src = w5; break;
    }
    g_w1[(size_t)n*1024 + k] = __float2half(src[(size_t)rloc*1024 + k]);
}

__global__ void conv_w2(const float* __restrict__ wo_lin, const float* __restrict__ wo_loc)
{
    size_t i = (size_t)blockIdx.x * 256 + threadIdx.x;   // 1024*512
    int n = (int)(i >> 9), k = (int)(i & 511);
    g_w2[(size_t)n*1024 + k]       = __float2half(wo_lin[(size_t)n*512 + k]);
    g_w2[(size_t)n*1024 + 512 + k] = __float2half(wo_loc[(size_t)n*512 + k]);
}

__global__ void conv_bias(const float* __restrict__ b0, const float* __restrict__ b1,
                          const float* __restrict__ b2, const float* __restrict__ b3,
                          const float* __restrict__ b4, const float* __restrict__ b5,
                          const float* __restrict__ bo_lin, const float* __restrict__ bo_loc)
{
    int c = blockIdx.x * 256 + threadIdx.x;
    int proj = c >> 9, lc = c & 511;
    const float* src;
    switch (proj) {
        case 0: src = b0; break; case 1: src = b1; break; case 2: src = b2; break;
        case 3: src = b3; break; case 4: src = b4; break; default: src = b5; break;
    }
    g_bias1[c] = src[lc];
    if (c < 1024) g_bias2[c] = 0.5f * (bo_lin[c] + bo_loc[c]);
}

// =======================================================================
//   attention kernels — register-tiled
// =======================================================================
__global__ __launch_bounds__(256)
void attn_local_kernel()
{
    __shared__ float qs[64][33];
    __shared__ float ks[64][33];
    __shared__ float vs[64][33];
    __shared__ float S [64][65];

    int z = blockIdx.x;
    int l = z & 63, h = (z >> 6) & 15, b = z >> 10;
    int tid = threadIdx.x;
    const float* Q = g_proj + (size_t)3*RR*DD;
    const float* K = g_proj + (size_t)4*RR*DD;
    const float* V = g_proj + (size_t)5*RR*DD;

    for (int idx = tid; idx < 64*32; idx += 256) {
        int c = idx >> 5, dh = idx & 31;
        size_t off = ((size_t)((l*64 + c)*BB + b))*DD + h*32 + dh;
        qs[c][dh] = Q[off]; ks[c][dh] = K[off]; vs[c][dh] = V[off];
    }
    __syncthreads();

    {
        int tr = tid >> 4, tc = tid & 15;
        int c0 = tr*4, j0 = tc*4;
        float s[4][4] = {{0.f}};
        if (tc <= tr) {
            #pragma unroll 8
            for (int d = 0; d < 32; d++) {
                float rq[4], rk[4];
                #pragma unroll
                for (int i = 0; i < 4; i++) rq[i] = qs[c0+i][d];
                #pragma unroll
                for (int j = 0; j < 4; j++) rk[j] = ks[j0+j][d];
                #pragma unroll
                for (int i = 0; i < 4; i++)
                    #pragma unroll
                    for (int j = 0; j < 4; j++)
                        s[i][j] += rq[i]*rk[j];
            }
        }
        #pragma unroll
        for (int i = 0; i < 4; i++)
            #pragma unroll
            for (int j = 0; j < 4; j++) {
                float v = (j0+j <= c0+i) ? fmaxf(s[i][j], 0.f) : 0.f;
                S[c0+i][j0+j] = v;
            }
    }
    __syncthreads();

    {
        int cg = tid >> 4, dg = tid & 15;
        int c0 = cg*4, dh0 = dg*2;
        float o[4][2] = {{0.f}};
        #pragma unroll 8
        for (int j = 0; j < 64; j++) {
            float v0 = vs[j][dh0], v1 = vs[j][dh0+1];
            #pragma unroll
            for (int i = 0; i < 4; i++) {
                float sv = S[c0+i][j];
                o[i][0] += sv*v0; o[i][1] += sv*v1;
            }
        }
        #pragma unroll
        for (int i = 0; i < 4; i++) {
            size_t off = ((size_t)((l*64 + c0+i)*BB + b))*DD + h*32 + dh0;
            *reinterpret_cast<float2*>(g_oloc + off) = make_float2(o[i][0], o[i][1]);
        }
    }
}

__global__ __launch_bounds__(256)
void attn_kv_kernel()
{
    __shared__ float ks[64][33];
    __shared__ float vs[64][33];

    int z = blockIdx.x;
    int l = z & 63, h = (z >> 6) & 15, b = z >> 10;
    int tid = threadIdx.x;
    const float* K = g_proj + (size_t)1*RR*DD;
    const float* V = g_proj + (size_t)2*RR*DD;

    for (int idx = tid; idx < 64*32; idx += 256) {
        int c = idx >> 5, dh = idx & 31;
        size_t off = ((size_t)((l*64 + c)*BB + b))*DD + h*32 + dh;
        ks[c][dh] = K[off]; vs[c][dh] = V[off];
    }
    __syncthreads();

    int d0 = (tid >> 4)*2, e0 = (tid & 15)*2;
    float s[2][2] = {{0.f}};
    #pragma unroll 8
    for (int c = 0; c < 64; c++) {
        float k0 = ks[c][d0], k1 = ks[c][d0+1];
        float v0 = vs[c][e0], v1 = vs[c][e0+1];
        s[0][0] += k0*v0; s[0][1] += k0*v1;
        s[1][0] += k1*v0; s[1][1] += k1*v1;
    }
    float* dst = g_kv + (size_t)z*1024;
    *reinterpret_cast<float2*>(dst + (d0  )*32 + e0) = make_float2(s[0][0], s[0][1]);
    *reinterpret_cast<float2*>(dst + (d0+1)*32 + e0) = make_float2(s[1][0], s[1][1]);
}

__global__ __launch_bounds__(256)
void kv_cumsum_kernel()
{
    int bh = blockIdx.x;
    const float* src = g_kv     + (size_t)bh*LL*1024;
    float*       dst = g_kvprev + (size_t)bh*LL*1024;
    for (int j = threadIdx.x; j < 1024; j += 256) {
        float acc = 0.f;
        #pragma unroll 4
        for (int l = 0; l < LL; l++) {
            dst[l*1024 + j] = acc;
            acc += src[l*1024 + j];
        }
    }
}

__global__ __launch_bounds__(256)
void attn_lin_kernel()
{
    __shared__ float qs [64][33];
    __shared__ float ks [64][33];
    __shared__ float vs [64][33];
    __shared__ float kvp[32][33];
    __shared__ float S  [64][65];

    int z = blockIdx.x;
    int l = z & 63, h = (z >> 6) & 15, b = z >> 10;
    int tid = threadIdx.x;
    const float* Q = g_proj;
    const float* K = g_proj + (size_t)1*RR*DD;
    const float* V = g_proj + (size_t)2*RR*DD;

    for (int idx = tid; idx < 64*32; idx += 256) {
        int c = idx >> 5, dh = idx & 31;
        size_t off = ((size_t)((l*64 + c)*BB + b))*DD + h*32 + dh;
        qs[c][dh] = Q[off]; ks[c][dh] = K[off]; vs[c][dh] = V[off];
    }
    for (int idx = tid; idx < 32*32; idx += 256)
        kvp[idx >> 5][idx & 31] = g_kvprev[(size_t)z*1024 + idx];
    __syncthreads();

    {
        int tr = tid >> 4, tc = tid & 15;
        int c0 = tr*4, j0 = tc*4;
        float s[4][4] = {{0.f}};
        if (tc <= tr) {
            #pragma unroll 8
            for (int d = 0; d < 32; d++) {
                float rq[4], rk[4];
                #pragma unroll
                for (int i = 0; i < 4; i++) rq[i] = qs[c0+i][d];
                #pragma unroll
                for (int j = 0; j < 4; j++) rk[j] = ks[j0+j][d];
                #pragma unroll
                for (int i = 0; i < 4; i++)
                    #pragma unroll
                    for (int j = 0; j < 4; j++)
                        s[i][j] += rq[i]*rk[j];
            }
        }
        #pragma unroll
        for (int i = 0; i < 4; i++)
            #pragma unroll
            for (int j = 0; j < 4; j++)
                S[c0+i][j0+j] = (j0+j <= c0+i) ? s[i][j] : 0.f;
    }
    __syncthreads();

    {
        int cg = tid >> 4, dg = tid & 15;
        int c0 = cg*4, dh0 = dg*2;
        float o[4][2] = {{0.f}};
        #pragma unroll 8
        for (int j = 0; j < 64; j++) {
            float v0 = vs[j][dh0], v1 = vs[j][dh0+1];
            #pragma unroll
            for (int i = 0; i < 4; i++) {
                float sv = S[c0+i][j];
                o[i][0] += sv*v0; o[i][1] += sv*v1;
            }
        }
        #pragma unroll 8
        for (int d = 0; d < 32; d++) {
            float p0 = kvp[d][dh0], p1 = kvp[d][dh0+1];
            #pragma unroll
            for (int i = 0; i < 4; i++) {
                float qv = qs[c0+i][d];
                o[i][0] += qv*p0; o[i][1] += qv*p1;
            }
        }
        #pragma unroll
        for (int i = 0; i < 4; i++) {
            size_t off = ((size_t)((l*64 + c0+i)*BB + b))*DD + h*32 + dh0;
            *reinterpret_cast<float2*>(g_olin + off) = make_float2(o[i][0], o[i][1]);
        }
    }
}

// ---------------- norms -> fp16 hi/lo splits into g_a2 ----------------
__device__ __forceinline__ float block_sum256(float v, float* sbuf) {
    int tid = threadIdx.x;
    #pragma unroll
    for (int o = 16; o > 0; o >>= 1) v += __shfl_xor_sync(0xffffffffu, v, o);
    __syncthreads();
    if ((tid & 31) == 0) sbuf[tid >> 5] = v;
    __syncthreads();
    float t = sbuf[0];
    #pragma unroll
    for (int w = 1; w < 8; w++) t += sbuf[w];
    return t;
}

__global__ __launch_bounds__(256)
void norm_kernel(const float* __restrict__ ln_g, const float* __restrict__ ln_b,
                 const float* __restrict__ gsc,  const float* __restrict__ ggt)
{
    __shared__ float sbuf[8];
    int r = blockIdx.x, tid = threadIdx.x;
    __half* a2 = g_a2 + (size_t)r*2048;

    const float* xl = g_olin + (size_t)r*DD;
    float a0 = xl[tid], a1 = xl[tid + 256];
    float mu = block_sum256(a0 + a1, sbuf) * (1.0f/512.0f);
    float d0 = a0 - mu, d1 = a1 - mu;
    float var = block_sum256(d0*d0 + d1*d1, sbuf) * (1.0f/512.0f);
    float rs = rsqrtf(var + 1e-5f);
    float y0 = d0*rs*ln_g[tid      ] + ln_b[tid      ];
    float y1 = d1*rs*ln_g[tid + 256] + ln_b[tid + 256];
    __half hi, lo;
    split_f16(y0, hi, lo); a2[tid      ] = hi; a2[512 + tid      ] = lo;
    split_f16(y1, hi, lo); a2[tid + 256] = hi; a2[512 + tid + 256] = lo;

    const float* xo = g_oloc + (size_t)r*DD;
    float b0 = xo[tid], b1 = xo[tid + 256];
    float ms = block_sum256(b0*b0 + b1*b1, sbuf) * (1.0f/512.0f);
    float inv = rsqrtf(ms + 1e-8f);
    float s0 = 1.0f/(1.0f + expf(-ggt[tid      ]*b0));
    float s1 = 1.0f/(1.0f + expf(-ggt[tid + 256]*b1));
    float z0 = b0*inv*gsc[tid      ]*s0;
    float z1 = b1*inv*gsc[tid + 256]*s1;
    split_f16(z0, hi, lo); a2[1024 + tid      ] = hi; a2[1536 + tid      ] = lo;
    split_f16(z1, hi, lo); a2[1024 + tid + 256] = hi; a2[1536 + tid + 256] = lo;
}

// =======================================================================
//   launch
// =======================================================================
extern "C" void kernel_launch(void* const* d_in, const int* in_sizes, int n_in,
                              void* d_out, int out_size)
{
    const float* query   = (const float*)d_in[0];
    const float* wq_lin  = (const float*)d_in[1];
    const float* bq_lin  = (const float*)d_in[2];
    const float* wk_lin  = (const float*)d_in[3];
    const float* bk_lin  = (const float*)d_in[4];
    const float* wv_lin  = (const float*)d_in[5];
    const float* bv_lin  = (const float*)d_in[6];
    const float* wo_lin  = (const float*)d_in[7];
    const float* bo_lin  = (const float*)d_in[8];
    const float* wq_loc  = (const float*)d_in[9];
    const float* bq_loc  = (const float*)d_in[10];
    const float* wk_loc  = (const float*)d_in[11];
    const float* bk_loc  = (const float*)d_in[12];
    const float* wv_loc  = (const float*)d_in[13];
    const float* bv_loc  = (const float*)d_in[14];
    const float* wo_loc  = (const float*)d_in[15];
    const float* bo_loc  = (const float*)d_in[16];
    const float* ln_g    = (const float*)d_in[17];
    const float* ln_b    = (const float*)d_in[18];
    const float* grn_s   = (const float*)d_in[19];
    const float* grn_g   = (const float*)d_in[20];
    float* out = (float*)d_out;

    cudaFuncSetAttribute(gemm_tc, cudaFuncAttributeMaxDynamicSharedMemorySize, SMEM_GEMM);

    conv_bias<<<3072/256, 256>>>(bq_lin, bk_lin, bv_lin, bq_loc, bk_loc, bv_loc, bo_lin, bo_loc);
    conv_a1  <<<(RR*1024)/256, 256>>>(query);
    conv_w1  <<<(3072*1024)/256, 256>>>(wq_lin, wk_lin, wv_lin, wq_loc, wk_loc, wv_loc);

    // fused input projections (6-in-1), fp16 2-term   [launch idx 3]
    gemm_tc<<<dim3(3072/BN, RR/BM), 512, SMEM_GEMM>>>(0, nullptr);

    conv_w2  <<<(1024*512)/256, 256>>>(wo_lin, wo_loc);

    // attention (register-tiled)
    attn_local_kernel<<<BB*HH*LL, 256>>>();
    attn_kv_kernel   <<<BB*HH*LL, 256>>>();
    kv_cumsum_kernel <<<BB*HH,    256>>>();
    attn_lin_kernel  <<<BB*HH*LL, 256>>>();

    // norms (emit fp16 hi/lo operands for the output GEMM)
    norm_kernel<<<RR, 256>>>(ln_g, ln_b, grn_s, grn_g);

    // fused output projections (2-in-1)
    gemm_tc<<<dim3(1024/BN, RR/BM), 512, SMEM_GEMM>>>(1, out);
}

// round 11
// speedup vs baseline: 3.8747x; 1.0817x over previous
#include <cuda_runtime.h>
#include <cuda_fp16.h>
#include <stdint.h>
#include <math.h>

// ---------------- problem constants ----------------
#define NN 4096
#define BB 4
#define EE 1024
#define HH 16
#define DD 512
#define DH 32
#define LL 64
#define RR (NN*BB)   // 16384 rows

// ---------------- gemm geometry ----------------
#define BM 128
#define BN 256
#define BK 64                       // fp16 elems per k-step (128 bytes per row)
#define KSTEPS 32                   // both gemms: K' = 2048 (fp16 2-term split)
#define STAGE_BYTES ((BM+BN)*128)   // 49152
#define NSTAGES 4
#define SMEM_GEMM (NSTAGES*STAGE_BYTES)  // 196608

// ---------------- device scratch ----------------
__device__ __half g_a1[(size_t)RR*2048];      // [query_hi | query_lo]
__device__ __half g_w1[(size_t)3072*1024];    // 6 proj weights, hi only
__device__ __half g_a2[(size_t)RR*2048];      // [ln_hi | ln_lo | grn_hi | grn_lo]
__device__ __half g_w2[(size_t)1024*1024];    // [wol_hi | woc_hi]
__device__ float g_bias1[3072];
__device__ float g_bias2[1024];
__device__ float g_proj[(size_t)6*RR*DD];     // q_lin,k_lin,v_lin,q_loc,k_loc,v_loc
__device__ float g_olin[(size_t)RR*DD];
__device__ float g_oloc[(size_t)RR*DD];
__device__ float g_kv    [(size_t)BB*HH*LL*DH*DH];
__device__ float g_kvprev[(size_t)BB*HH*LL*DH*DH];

// ---------------- asm helpers ----------
__device__ __forceinline__ uint32_t smem_u32(const void* p) {
    uint32_t a;
    asm("{ .reg .u64 t; cvta.to.shared.u64 t, %1; cvt.u32.u64 %0, t; }" : "=r"(a) : "l"(p));
    return a;
}
__device__ __forceinline__ void cpasync16(uint32_t s, const void* g) {
    asm volatile("cp.async.cg.shared.global [%0], [%1], 16;" :: "r"(s), "l"(g));
}
#define CP_COMMIT() asm volatile("cp.async.commit_group;" ::: "memory")
#define CP_WAIT0()  asm volatile("cp.async.wait_group 0;"  ::: "memory")

__device__ __forceinline__ void ldsm4(uint32_t* r, uint32_t addr) {
    asm volatile("ldmatrix.sync.aligned.m8n8.x4.shared.b16 {%0,%1,%2,%3}, [%4];"
        : "=r"(r[0]), "=r"(r[1]), "=r"(r[2]), "=r"(r[3]) : "r"(addr));
}
__device__ __forceinline__ void mma_f16(float* c, const uint32_t* a,
                                        uint32_t b0, uint32_t b1) {
    asm volatile(
        "mma.sync.aligned.m16n8k16.row.col.f32.f16.f16.f32 "
        "{%0,%1,%2,%3}, {%4,%5,%6,%7}, {%8,%9}, {%0,%1,%2,%3};"
        : "+f"(c[0]), "+f"(c[1]), "+f"(c[2]), "+f"(c[3])
        : "r"(a[0]), "r"(a[1]), "r"(a[2]), "r"(a[3]), "r"(b0), "r"(b1));
}

__device__ __forceinline__ float gelu_tanh(float x) {
    float x3 = x*x*x;
    return 0.5f*x*(1.0f + tanhf(0.7978845608028654f*(x + 0.044715f*x3)));
}
__device__ __forceinline__ void split_f16(float x, __half& hi, __half& lo) {
    hi = __float2half(x);
    lo = __float2half(x - __half2float(hi));
}

// SW128 swizzle base for a [rows][64 fp16] tile (128B rows)
__device__ __forceinline__ uint32_t swz128(int row) {
    return (uint32_t)(row*128) ^ (((uint32_t)row & 7u) << 4);
}

// (aoff,boff) in fp16 elements along the concatenated K for k-step ks
__device__ __forceinline__ void seg_off(int gemmid, int ks, int& aoff, int& boff) {
    if (gemmid == 0) {
        int seg = ks >> 4, ko = (ks & 15)*64;
        aoff = ko + (seg ? 1024 : 0);
        boff = ko;
    } else {
        int seg = ks >> 3, ko = (ks & 7)*64;
        aoff = seg*512 + ko;
        boff = (seg >= 2 ? 512 : 0) + ko;
    }
}

// =======================================================================
//   fp16 mma.sync GEMM (unchanged from R10)
// =======================================================================
__global__ __launch_bounds__(512, 1)
void gemm_tc(int gemmid, float* __restrict__ outp)
{
    extern __shared__ char smem[];
    const uint32_t sb = smem_u32(smem);
    const int tid = threadIdx.x;
    const int mbase = blockIdx.y * BM;
    const int nbase = blockIdx.x * BN;
    const __half* __restrict__ Ap = gemmid ? g_a2 : g_a1;
    const __half* __restrict__ Bp = gemmid ? g_w2 : g_w1;

    float acc[2][8][4];
    #pragma unroll
    for (int i = 0; i < 2; i++)
        #pragma unroll
        for (int j = 0; j < 8; j++)
            #pragma unroll
            for (int q = 0; q < 4; q++) acc[i][j][q] = 0.f;

    const int ldA_row0 = tid >> 3,          ldA_row1 = (tid + 512) >> 3;
    const int ldB_row0 = tid >> 3,          ldB_row1 = (tid + 512) >> 3;
    const int ldB_row2 = (tid + 1024) >> 3, ldB_row3 = (tid + 1536) >> 3;
    const int ld_ch = tid & 7;
    const uint32_t chx = (uint32_t)ld_ch << 4;
    const uint32_t sA0 = swz128(ldA_row0) ^ chx;
    const uint32_t sA1 = swz128(ldA_row1) ^ chx;
    const uint32_t sB0 = (uint32_t)(BM*128) + (swz128(ldB_row0) ^ chx);
    const uint32_t sB1 = (uint32_t)(BM*128) + (swz128(ldB_row1) ^ chx);
    const uint32_t sB2 = (uint32_t)(BM*128) + (swz128(ldB_row2) ^ chx);
    const uint32_t sB3 = (uint32_t)(BM*128) + (swz128(ldB_row3) ^ chx);

    auto load_stage = [&](uint32_t sst, int aoff, int boff) {
        cpasync16(sst + sA0, Ap + (size_t)(mbase + ldA_row0)*2048 + aoff + ld_ch*8);
        cpasync16(sst + sA1, Ap + (size_t)(mbase + ldA_row1)*2048 + aoff + ld_ch*8);
        cpasync16(sst + sB0, Bp + (size_t)(nbase + ldB_row0)*1024 + boff + ld_ch*8);
        cpasync16(sst + sB1, Bp + (size_t)(nbase + ldB_row1)*1024 + boff + ld_ch*8);
        cpasync16(sst + sB2, Bp + (size_t)(nbase + ldB_row2)*1024 + boff + ld_ch*8);
        cpasync16(sst + sB3, Bp + (size_t)(nbase + ldB_row3)*1024 + boff + ld_ch*8);
    };

    const int lane = tid & 31, wid = tid >> 5;
    const int m0 = (wid & 3) * 32;
    const int n0 = (wid >> 2) * 64;

    uint32_t aBase[2], bBase[4];
    #pragma unroll
    for (int mt = 0; mt < 2; mt++)
        aBase[mt] = swz128(m0 + mt*16 + (lane & 15));
    #pragma unroll
    for (int p = 0; p < 4; p++)
        bBase[p] = (uint32_t)(BM*128) + swz128(n0 + p*16 + (lane & 15));
    const uint32_t kqSel = (uint32_t)(lane >> 4) << 4;

    auto compute_pair = [&](uint32_t sS0, uint32_t sS1) {
        uint32_t aCur[2][4], aNxt[2][4], bCur[4], bNxt[4];
        const uint32_t sArr2[2] = {sS0, sS1};
        {
            ldsm4(aCur[0], sS0 + (aBase[0] ^ kqSel));
            ldsm4(aCur[1], sS0 + (aBase[1] ^ kqSel));
            ldsm4(bCur,    sS0 + (bBase[0] ^ kqSel));
        }
        #pragma unroll
        for (int sl = 0; sl < 8; sl++) {
            uint32_t sS = sArr2[sl >> 2];
            uint32_t kx = ((uint32_t)((sl & 3) * 2) << 4) ^ kqSel;
            #pragma unroll
            for (int p = 0; p < 4; p++) {
                if (p < 3) {
                    ldsm4(bNxt, sS + (bBase[p+1] ^ kx));
                } else if (sl < 7) {
                    uint32_t sS2 = sArr2[(sl+1) >> 2];
                    uint32_t kx2 = ((uint32_t)(((sl+1) & 3) * 2) << 4) ^ kqSel;
                    ldsm4(aNxt[0], sS2 + (aBase[0] ^ kx2));
                    ldsm4(aNxt[1], sS2 + (aBase[1] ^ kx2));
                    ldsm4(bNxt,    sS2 + (bBase[0] ^ kx2));
                }
                #pragma unroll
                for (int mt = 0; mt < 2; mt++) {
                    mma_f16(acc[mt][2*p],   aCur[mt], bCur[0], bCur[2]);
                    mma_f16(acc[mt][2*p+1], aCur[mt], bCur[1], bCur[3]);
                }
                #pragma unroll
                for (int q = 0; q < 4; q++) bCur[q] = bNxt[q];
            }
            #pragma unroll
            for (int mt = 0; mt < 2; mt++)
                #pragma unroll
                for (int q = 0; q < 4; q++) aCur[mt][q] = aNxt[mt][q];
        }
    };

    {
        int ao, bo;
        seg_off(gemmid, 0, ao, bo); load_stage(sb, ao, bo); CP_COMMIT();
        seg_off(gemmid, 1, ao, bo); load_stage(sb + STAGE_BYTES, ao, bo); CP_COMMIT();
    }

    for (int ks = 0; ks < KSTEPS; ks += 2) {
        CP_WAIT0();
        __syncthreads();
        if (ks + 3 < KSTEPS) {
            int ao, bo;
            seg_off(gemmid, ks + 2, ao, bo);
            load_stage(sb + (uint32_t)(((ks + 2) & 3) * STAGE_BYTES), ao, bo);
            CP_COMMIT();
            seg_off(gemmid, ks + 3, ao, bo);
            load_stage(sb + (uint32_t)(((ks + 3) & 3) * STAGE_BYTES), ao, bo);
            CP_COMMIT();
        }
        compute_pair(sb + (uint32_t)((ks & 3) * STAGE_BYTES),
                     sb + (uint32_t)(((ks + 1) & 3) * STAGE_BYTES));
    }

    const int r_lo  = mbase + m0 + (lane >> 2);
    const int cbase = nbase + n0 + (lane & 3)*2;
    #pragma unroll
    for (int mt = 0; mt < 2; mt++) {
        #pragma unroll
        for (int nt = 0; nt < 8; nt++) {
            int col = cbase + nt*8;
            int row0 = r_lo + mt*16;
            float v0 = acc[mt][nt][0], v1 = acc[mt][nt][1];
            float v2 = acc[mt][nt][2], v3 = acc[mt][nt][3];
            if (gemmid == 0) {
                float b0 = g_bias1[col], b1 = g_bias1[col+1];
                v0 += b0; v1 += b1; v2 += b0; v3 += b1;
                int proj = col >> 9, lc = col & 511;
                if (proj < 2) {
                    v0 = gelu_tanh(v0); v1 = gelu_tanh(v1);
                    v2 = gelu_tanh(v2); v3 = gelu_tanh(v3);
                }
                float* base = g_proj + (size_t)proj * ((size_t)RR*DD);
                *reinterpret_cast<float2*>(base + (size_t)row0*DD + lc)
                    = make_float2(v0, v1);
                *reinterpret_cast<float2*>(base + (size_t)(row0+8)*DD + lc)
                    = make_float2(v2, v3);
            } else {
                float b0 = g_bias2[col], b1 = g_bias2[col+1];
                *reinterpret_cast<float2*>(outp + (size_t)row0*1024 + col)
                    = make_float2(0.5f*v0 + b0, 0.5f*v1 + b1);
                *reinterpret_cast<float2*>(outp + (size_t)(row0+8)*1024 + col)
                    = make_float2(0.5f*v2 + b0, 0.5f*v3 + b1);
            }
        }
    }
}

// =======================================================================
//   conversion kernels
// =======================================================================
// vectorized: 4 elems per thread
__global__ void conv_a1(const float* __restrict__ query)
{
    size_t i4 = ((size_t)blockIdx.x * 256 + threadIdx.x) * 4;   // 16384*1024 elems
    int r = (int)(i4 >> 10), c = (int)(i4 & 1023);
    float4 v = *reinterpret_cast<const float4*>(query + i4);
    __half hi[4], lo[4];
    split_f16(v.x, hi[0], lo[0]); split_f16(v.y, hi[1], lo[1]);
    split_f16(v.z, hi[2], lo[2]); split_f16(v.w, hi[3], lo[3]);
    __half* dst = g_a1 + (size_t)r*2048 + c;
    *reinterpret_cast<uint2*>(dst)        = *reinterpret_cast<uint2*>(hi);
    *reinterpret_cast<uint2*>(dst + 1024) = *reinterpret_cast<uint2*>(lo);
}

// conv_w1 + all bias prep fused (one launch)
__global__ void conv_w1b(const float* __restrict__ w0, const float* __restrict__ w1,
                         const float* __restrict__ w2, const float* __restrict__ w3,
                         const float* __restrict__ w4, const float* __restrict__ w5,
                         const float* __restrict__ b0, const float* __restrict__ b1,
                         const float* __restrict__ b2, const float* __restrict__ b3,
                         const float* __restrict__ b4, const float* __restrict__ b5,
                         const float* __restrict__ bo_lin, const float* __restrict__ bo_loc)
{
    size_t i = (size_t)blockIdx.x * 256 + threadIdx.x;   // 3072*1024
    int n = (int)(i >> 10), k = (int)(i & 1023);
    int proj = n >> 9, rloc = n & 511;
    const float* src;
    const float* bsrc;
    switch (proj) {
        case 0: src = w0; bsrc = b0; break; case 1: src = w1; bsrc = b1; break;
        case 2: src = w2; bsrc = b2; break; case 3: src = w3; bsrc = b3; break;
        case 4: src = w4; bsrc = b4; break; default: src = w5; bsrc = b5; break;
    }
    g_w1[(size_t)n*1024 + k] = __float2half(src[(size_t)rloc*1024 + k]);
    if (i < 3072) {
        int proj2 = (int)i >> 9, lc = (int)i & 511;
        const float* bs;
        switch (proj2) {
            case 0: bs = b0; break; case 1: bs = b1; break; case 2: bs = b2; break;
            case 3: bs = b3; break; case 4: bs = b4; break; default: bs = b5; break;
        }
        g_bias1[i] = bs[lc];
        if (i < 1024) g_bias2[i] = 0.5f * (bo_lin[i] + bo_loc[i]);
    }
    (void)bsrc;
}

__global__ void conv_w2(const float* __restrict__ wo_lin, const float* __restrict__ wo_loc)
{
    size_t i = (size_t)blockIdx.x * 256 + threadIdx.x;   // 1024*512
    int n = (int)(i >> 9), k = (int)(i & 511);
    g_w2[(size_t)n*1024 + k]       = __float2half(wo_lin[(size_t)n*512 + k]);
    g_w2[(size_t)n*1024 + 512 + k] = __float2half(wo_loc[(size_t)n*512 + k]);
}

// =======================================================================
//   attention kernels — register-tiled
// =======================================================================
__global__ __launch_bounds__(256)
void attn_local_kernel()
{
    __shared__ float qs[64][33];
    __shared__ float ks[64][33];
    __shared__ float vs[64][33];
    __shared__ float S [64][65];

    int z = blockIdx.x;
    int l = z & 63, h = (z >> 6) & 15, b = z >> 10;
    int tid = threadIdx.x;
    const float* Q = g_proj + (size_t)3*RR*DD;
    const float* K = g_proj + (size_t)4*RR*DD;
    const float* V = g_proj + (size_t)5*RR*DD;

    for (int idx = tid; idx < 64*32; idx += 256) {
        int c = idx >> 5, dh = idx & 31;
        size_t off = ((size_t)((l*64 + c)*BB + b))*DD + h*32 + dh;
        qs[c][dh] = Q[off]; ks[c][dh] = K[off]; vs[c][dh] = V[off];
    }
    __syncthreads();

    {
        int tr = tid >> 4, tc = tid & 15;
        int c0 = tr*4, j0 = tc*4;
        float s[4][4] = {{0.f}};
        if (tc <= tr) {
            #pragma unroll 8
            for (int d = 0; d < 32; d++) {
                float rq[4], rk[4];
                #pragma unroll
                for (int i = 0; i < 4; i++) rq[i] = qs[c0+i][d];
                #pragma unroll
                for (int j = 0; j < 4; j++) rk[j] = ks[j0+j][d];
                #pragma unroll
                for (int i = 0; i < 4; i++)
                    #pragma unroll
                    for (int j = 0; j < 4; j++)
                        s[i][j] += rq[i]*rk[j];
            }
        }
        #pragma unroll
        for (int i = 0; i < 4; i++)
            #pragma unroll
            for (int j = 0; j < 4; j++) {
                float v = (j0+j <= c0+i) ? fmaxf(s[i][j], 0.f) : 0.f;
                S[c0+i][j0+j] = v;
            }
    }
    __syncthreads();

    {
        int cg = tid >> 4, dg = tid & 15;
        int c0 = cg*4, dh0 = dg*2;
        float o[4][2] = {{0.f}};
        #pragma unroll 8
        for (int j = 0; j < 64; j++) {
            float v0 = vs[j][dh0], v1 = vs[j][dh0+1];
            #pragma unroll
            for (int i = 0; i < 4; i++) {
                float sv = S[c0+i][j];
                o[i][0] += sv*v0; o[i][1] += sv*v1;
            }
        }
        #pragma unroll
        for (int i = 0; i < 4; i++) {
            size_t off = ((size_t)((l*64 + c0+i)*BB + b))*DD + h*32 + dh0;
            *reinterpret_cast<float2*>(g_oloc + off) = make_float2(o[i][0], o[i][1]);
        }
    }
}

__global__ __launch_bounds__(256)
void attn_kv_kernel()
{
    __shared__ float ks[64][33];
    __shared__ float vs[64][33];

    int z = blockIdx.x;
    int l = z & 63, h = (z >> 6) & 15, b = z >> 10;
    int tid = threadIdx.x;
    const float* K = g_proj + (size_t)1*RR*DD;
    const float* V = g_proj + (size_t)2*RR*DD;

    for (int idx = tid; idx < 64*32; idx += 256) {
        int c = idx >> 5, dh = idx & 31;
        size_t off = ((size_t)((l*64 + c)*BB + b))*DD + h*32 + dh;
        ks[c][dh] = K[off]; vs[c][dh] = V[off];
    }
    __syncthreads();

    int d0 = (tid >> 4)*2, e0 = (tid & 15)*2;
    float s[2][2] = {{0.f}};
    #pragma unroll 8
    for (int c = 0; c < 64; c++) {
        float k0 = ks[c][d0], k1 = ks[c][d0+1];
        float v0 = vs[c][e0], v1 = vs[c][e0+1];
        s[0][0] += k0*v0; s[0][1] += k0*v1;
        s[1][0] += k1*v0; s[1][1] += k1*v1;
    }
    float* dst = g_kv + (size_t)z*1024;
    *reinterpret_cast<float2*>(dst + (d0  )*32 + e0) = make_float2(s[0][0], s[0][1]);
    *reinterpret_cast<float2*>(dst + (d0+1)*32 + e0) = make_float2(s[1][0], s[1][1]);
}

// widened: 256 blocks, each owns 256 j-columns of one (b,h)
__global__ __launch_bounds__(256)
void kv_cumsum_kernel()
{
    int bh = blockIdx.x >> 2;
    int j  = (blockIdx.x & 3) * 256 + threadIdx.x;
    const float* src = g_kv     + (size_t)bh*LL*1024 + j;
    float*       dst = g_kvprev + (size_t)bh*LL*1024 + j;
    float acc = 0.f;
    #pragma unroll 8
    for (int l = 0; l < LL; l++) {
        dst[l*1024] = acc;
        acc += src[l*1024];
    }
}

__global__ __launch_bounds__(256)
void attn_lin_kernel()
{
    __shared__ float qs [64][33];
    __shared__ float ks [64][33];
    __shared__ float vs [64][33];
    __shared__ float kvp[32][33];
    __shared__ float S  [64][65];

    int z = blockIdx.x;
    int l = z & 63, h = (z >> 6) & 15, b = z >> 10;
    int tid = threadIdx.x;
    const float* Q = g_proj;
    const float* K = g_proj + (size_t)1*RR*DD;
    const float* V = g_proj + (size_t)2*RR*DD;

    for (int idx = tid; idx < 64*32; idx += 256) {
        int c = idx >> 5, dh = idx & 31;
        size_t off = ((size_t)((l*64 + c)*BB + b))*DD + h*32 + dh;
        qs[c][dh] = Q[off]; ks[c][dh] = K[off]; vs[c][dh] = V[off];
    }
    for (int idx = tid; idx < 32*32; idx += 256)
        kvp[idx >> 5][idx & 31] = g_kvprev[(size_t)z*1024 + idx];
    __syncthreads();

    {
        int tr = tid >> 4, tc = tid & 15;
        int c0 = tr*4, j0 = tc*4;
        float s[4][4] = {{0.f}};
        if (tc <= tr) {
            #pragma unroll 8
            for (int d = 0; d < 32; d++) {
                float rq[4], rk[4];
                #pragma unroll
                for (int i = 0; i < 4; i++) rq[i] = qs[c0+i][d];
                #pragma unroll
                for (int j = 0; j < 4; j++) rk[j] = ks[j0+j][d];
                #pragma unroll
                for (int i = 0; i < 4; i++)
                    #pragma unroll
                    for (int j = 0; j < 4; j++)
                        s[i][j] += rq[i]*rk[j];
            }
        }
        #pragma unroll
        for (int i = 0; i < 4; i++)
            #pragma unroll
            for (int j = 0; j < 4; j++)
                S[c0+i][j0+j] = (j0+j <= c0+i) ? s[i][j] : 0.f;
    }
    __syncthreads();

    {
        int cg = tid >> 4, dg = tid & 15;
        int c0 = cg*4, dh0 = dg*2;
        float o[4][2] = {{0.f}};
        #pragma unroll 8
        for (int j = 0; j < 64; j++) {
            float v0 = vs[j][dh0], v1 = vs[j][dh0+1];
            #pragma unroll
            for (int i = 0; i < 4; i++) {
                float sv = S[c0+i][j];
                o[i][0] += sv*v0; o[i][1] += sv*v1;
            }
        }
        #pragma unroll 8
        for (int d = 0; d < 32; d++) {
            float p0 = kvp[d][dh0], p1 = kvp[d][dh0+1];
            #pragma unroll
            for (int i = 0; i < 4; i++) {
                float qv = qs[c0+i][d];
                o[i][0] += qv*p0; o[i][1] += qv*p1;
            }
        }
        #pragma unroll
        for (int i = 0; i < 4; i++) {
            size_t off = ((size_t)((l*64 + c0+i)*BB + b))*DD + h*32 + dh0;
            *reinterpret_cast<float2*>(g_olin + off) = make_float2(o[i][0], o[i][1]);
        }
    }
}

// ---------------- norms — warp-per-row (no block barriers) ----------------
__global__ __launch_bounds__(256)
void norm_kernel(const float* __restrict__ ln_g, const float* __restrict__ ln_b,
                 const float* __restrict__ gsc,  const float* __restrict__ ggt)
{
    int warp = (blockIdx.x << 3) | (threadIdx.x >> 5);   // row, 8 warps/block
    int lane = threadIdx.x & 31;
    __half* a2 = g_a2 + (size_t)warp*2048;

    // ---- LayerNorm ----
    const float* xl = g_olin + (size_t)warp*DD;
    float xa[16];
    float sum = 0.f;
    #pragma unroll
    for (int k = 0; k < 16; k++) { xa[k] = xl[lane + 32*k]; sum += xa[k]; }
    #pragma unroll
    for (int o = 16; o > 0; o >>= 1) sum += __shfl_xor_sync(0xffffffffu, sum, o);
    float mu = sum * (1.0f/512.0f);
    float vsum = 0.f;
    #pragma unroll
    for (int k = 0; k < 16; k++) { float d = xa[k] - mu; vsum += d*d; }
    #pragma unroll
    for (int o = 16; o > 0; o >>= 1) vsum += __shfl_xor_sync(0xffffffffu, vsum, o);
    float rs = rsqrtf(vsum * (1.0f/512.0f) + 1e-5f);
    #pragma unroll
    for (int k = 0; k < 16; k++) {
        int c = lane + 32*k;
        float y = (xa[k] - mu)*rs*ln_g[c] + ln_b[c];
        __half hi, lo; split_f16(y, hi, lo);
        a2[c] = hi; a2[512 + c] = lo;
    }

    // ---- gated RMSNorm ----
    const float* xo = g_oloc + (size_t)warp*DD;
    float ms = 0.f;
    #pragma unroll
    for (int k = 0; k < 16; k++) { xa[k] = xo[lane + 32*k]; ms += xa[k]*xa[k]; }
    #pragma unroll
    for (int o = 16; o > 0; o >>= 1) ms += __shfl_xor_sync(0xffffffffu, ms, o);
    float inv = rsqrtf(ms * (1.0f/512.0f) + 1e-8f);
    #pragma unroll
    for (int k = 0; k < 16; k++) {
        int c = lane + 32*k;
        float sg = 1.0f/(1.0f + expf(-ggt[c]*xa[k]));
        float zv = xa[k]*inv*gsc[c]*sg;
        __half hi, lo; split_f16(zv, hi, lo);
        a2[1024 + c] = hi; a2[1536 + c] = lo;
    }
}

// =======================================================================
//   launch  (attn_local at idx 3 -> profiled this round)
// =======================================================================
extern "C" void kernel_launch(void* const* d_in, const int* in_sizes, int n_in,
                              void* d_out, int out_size)
{
    const float* query   = (const float*)d_in[0];
    const float* wq_lin  = (const float*)d_in[1];
    const float* bq_lin  = (const float*)d_in[2];
    const float* wk_lin  = (const float*)d_in[3];
    const float* bk_lin  = (const float*)d_in[4];
    const float* wv_lin  = (const float*)d_in[5];
    const float* bv_lin  = (const float*)d_in[6];
    const float* wo_lin  = (const float*)d_in[7];
    const float* bo_lin  = (const float*)d_in[8];
    const float* wq_loc  = (const float*)d_in[9];
    const float* bq_loc  = (const float*)d_in[10];
    const float* wk_loc  = (const float*)d_in[11];
    const float* bk_loc  = (const float*)d_in[12];
    const float* wv_loc  = (const float*)d_in[13];
    const float* bv_loc  = (const float*)d_in[14];
    const float* wo_loc  = (const float*)d_in[15];
    const float* bo_loc  = (const float*)d_in[16];
    const float* ln_g    = (const float*)d_in[17];
    const float* ln_b    = (const float*)d_in[18];
    const float* grn_s   = (const float*)d_in[19];
    const float* grn_g   = (const float*)d_in[20];
    float* out = (float*)d_out;

    cudaFuncSetAttribute(gemm_tc, cudaFuncAttributeMaxDynamicSharedMemorySize, SMEM_GEMM);

    conv_a1 <<<(RR*1024/4)/256, 256>>>(query);
    conv_w1b<<<(3072*1024)/256, 256>>>(wq_lin, wk_lin, wv_lin, wq_loc, wk_loc, wv_loc,
                                       bq_lin, bk_lin, bv_lin, bq_loc, bk_loc, bv_loc,
                                       bo_lin, bo_loc);

    // fused input projections (6-in-1)
    gemm_tc<<<dim3(3072/BN, RR/BM), 512, SMEM_GEMM>>>(0, nullptr);

    // attention  [attn_local at launch idx 3 -> profiled]
    attn_local_kernel<<<BB*HH*LL, 256>>>();
    attn_kv_kernel   <<<BB*HH*LL, 256>>>();
    kv_cumsum_kernel <<<BB*HH*4,  256>>>();
    attn_lin_kernel  <<<BB*HH*LL, 256>>>();

    conv_w2<<<(1024*512)/256, 256>>>(wo_lin, wo_loc);

    // norms (warp-per-row)
    norm_kernel<<<RR/8, 256>>>(ln_g, ln_b, grn_s, grn_g);

    // fused output projections (2-in-1)
    gemm_tc<<<dim3(1024/BN, RR/BM), 512, SMEM_GEMM>>>(1, out);
}